// round 5
// baseline (speedup 1.0000x reference)
#include <cuda_runtime.h>
#include <cuda_bf16.h>
#include <math.h>

#define L_SEQ 2049
#define BATCH 8
#define NH 16
#define HD 64
#define NS 128
#define DIN 1024
#define CONVD 1280
#define DPROJ 2320
#define NROWS 2056
#define GENEF 384
#define DMODEL 512
#define TCOR 2045   // corrected timesteps t=4..2048

// ------------------------- scratch (static device globals) -------------------
__device__ float d_feat[NROWS * GENEF];
__device__ float d_X[NROWS * DMODEL];
__device__ float d_Z[2][NROWS * DPROJ];
__device__ float d_xBCs[2][(size_t)L_SEQ * CONVD];   // batch-shared conv out
__device__ float d_xBC0[BATCH * 4 * CONVD];          // fwd per-batch conv out, t=0..3
__device__ float d_dtr[2][NROWS * NH];
__device__ float d_dAr[2][NROWS * NH];
__device__ float d_ysp[2][(size_t)L_SEQ * NH * 8 * 64];  // scan partials [t][h][q][p]
__device__ float d_ysum[2][(size_t)L_SEQ * NH * 64];     // reduced shared-scan y
__device__ float d_ypre[BATCH * 3 * NH * 128];       // fwd per-batch y (t=1..3), halves
__device__ float d_hb3[BATCH * NH * HD * NS];        // fwd per-batch state after t=3
__device__ float d_decayf[NH * TCOR];                // cumprod dA fwd, t=4..2048
__device__ float d_V[(size_t)BATCH * TCOR * DIN];    // correction C_t . h_b3
__device__ float d_P[2][(size_t)2048 * DIN];         // silu(z) per gene row
__device__ float d_wcomb[2][DIN];

__device__ __forceinline__ int seq_row(int b, int t) {
    return (t == 0) ? (2048 + b) : (t - 1);
}
__device__ __forceinline__ const float* xbc_fwd_ptr(int b, int t) {
    return (t >= 4) ? (d_xBCs[0] + (size_t)t * CONVD)
                    : (d_xBC0 + (size_t)(b * 4 + t) * CONVD);
}
__device__ __forceinline__ float fast_silu(float x) {
    return __fdividef(x, 1.f + __expf(-x));
}

// f32x2 packed math (sm_100+)
#define MUL2(d, a, b) asm("mul.rn.f32x2 %0,%1,%2;" : "=l"(d) : "l"(a), "l"(b))
#define FMA2(d, a, b, c) asm("fma.rn.f32x2 %0,%1,%2,%3;" : "=l"(d) : "l"(a), "l"(b), "l"(c))
#define ADD2(d, a, b) asm("add.rn.f32x2 %0,%1,%2;" : "=l"(d) : "l"(a), "l"(b))
__device__ __forceinline__ unsigned long long pack2(float x) {
    unsigned long long r;
    asm("mov.b64 %0,{%1,%1};" : "=l"(r) : "r"(__float_as_uint(x)));
    return r;
}
__device__ __forceinline__ float sum2(unsigned long long v) {
    unsigned int lo, hi;
    asm("mov.b64 {%0,%1},%2;" : "=r"(lo), "=r"(hi) : "l"(v));
    return __uint_as_float(lo) + __uint_as_float(hi);
}
__device__ __forceinline__ float lo2(unsigned long long v) {
    unsigned int lo;
    asm("mov.b64 {%0,_},%1;" : "=r"(lo) : "l"(v));
    return __uint_as_float(lo);
}
__device__ __forceinline__ float hi2(unsigned long long v) {
    unsigned int hi;
    asm("mov.b64 {_,%0},%1;" : "=r"(hi) : "l"(v));
    return __uint_as_float(hi);
}

// ------------------------- 1. feature rows -----------------------------------
__global__ void feat_kernel(const int* __restrict__ pidx,
                            const int* __restrict__ chridx,
                            const float* __restrict__ locus_fourier,
                            const float* __restrict__ pathway,
                            const float* __restrict__ pert_emb,
                            const float* __restrict__ gene_id,
                            const float* __restrict__ chr_emb,
                            const float* __restrict__ locus_w,
                            const float* __restrict__ locus_b,
                            const float* __restrict__ cond_w,
                            const float* __restrict__ cond_b) {
    int g = blockIdx.x;
    int tid = threadIdx.x;  // 128
    if (g < 2048) {
        d_feat[g * GENEF + tid] = gene_id[g * 128 + tid];
        d_feat[g * GENEF + 128 + tid] = pathway[g * 128 + tid];
        if (tid < 64) {
            int ci = chridx[g];
            d_feat[g * GENEF + 256 + tid] = chr_emb[ci * 64 + tid];
        } else {
            int j = tid - 64;
            float acc = locus_b[j];
            const float* lf = locus_fourier + g * 64;
            const float* lw = locus_w + j * 64;
            for (int k = 0; k < 64; k++) acc = fmaf(lf[k], lw[k], acc);
            float ge = 0.5f * acc * (1.f + erff(acc * 0.70710678118654752f));
            d_feat[g * GENEF + 320 + j] = ge;
        }
    } else {
        int b = g - 2048;
        const float* pe = pert_emb + (size_t)pidx[b] * 128;
        for (int j = tid; j < GENEF; j += 128) {
            float acc = cond_b[j];
            const float* cw = cond_w + (size_t)j * 128;
            for (int k = 0; k < 128; k++) acc = fmaf(pe[k], cw[k], acc);
            d_feat[g * GENEF + j] = acc;
        }
    }
}

// ------------------------- 2. SGEMM 128x128 tile, 8x8/thread, f32x2 ----------
__global__ __launch_bounds__(256) void sgemm128(int src_sel,
                                                const float* __restrict__ W,
                                                const float* __restrict__ bias,
                                                int dst_sel, int M, int N, int K) {
    const float* A = (src_sel == 0) ? d_feat : d_X;
    float* C = (dst_sel == 0) ? d_X : d_Z[dst_sel - 1];

    __shared__ __align__(16) float2 As2[2][8][128];
    __shared__ __align__(16) float Ws[2][8][132];

    int tid = threadIdx.x;
    int row0 = blockIdx.y * 128, col0 = blockIdx.x * 128;
    int lr = tid >> 1;
    int lk = (tid & 1) * 4;
    bool aval = (row0 + lr) < M;
    bool wval = (col0 + lr) < N;
    const float* Aptr = A + (size_t)(row0 + lr) * K + lk;
    const float* Wptr = W + (size_t)(col0 + lr) * K + lk;

    float4 av = aval ? *(const float4*)Aptr : make_float4(0, 0, 0, 0);
    float4 wv = wval ? *(const float4*)Wptr : make_float4(0, 0, 0, 0);
    As2[0][lk + 0][lr] = make_float2(av.x, av.x);
    As2[0][lk + 1][lr] = make_float2(av.y, av.y);
    As2[0][lk + 2][lr] = make_float2(av.z, av.z);
    As2[0][lk + 3][lr] = make_float2(av.w, av.w);
    Ws[0][lk + 0][lr] = wv.x; Ws[0][lk + 1][lr] = wv.y;
    Ws[0][lk + 2][lr] = wv.z; Ws[0][lk + 3][lr] = wv.w;
    __syncthreads();

    unsigned long long acc2[8][4];
#pragma unroll
    for (int i = 0; i < 8; i++)
#pragma unroll
        for (int j = 0; j < 4; j++) acc2[i][j] = 0ull;

    int ty = tid >> 4, tx = tid & 15;

    for (int k0 = 0; k0 < K; k0 += 8) {
        int buf = (k0 >> 3) & 1;
        bool more = (k0 + 8) < K;
        if (more) {
            av = aval ? *(const float4*)(Aptr + k0 + 8) : make_float4(0, 0, 0, 0);
            wv = wval ? *(const float4*)(Wptr + k0 + 8) : make_float4(0, 0, 0, 0);
        }
#pragma unroll
        for (int kk = 0; kk < 8; kk++) {
            const ulonglong2* Ap = (const ulonglong2*)&As2[buf][kk][ty * 8];
            const ulonglong2* Bp0 = (const ulonglong2*)&Ws[buf][kk][tx * 4];
            const ulonglong2* Bp1 = (const ulonglong2*)&Ws[buf][kk][64 + tx * 4];
            ulonglong2 b0 = Bp0[0];
            ulonglong2 b1 = Bp1[0];
            ulonglong2 a01 = Ap[0], a23 = Ap[1], a45 = Ap[2], a67 = Ap[3];
            unsigned long long ra[8] = {a01.x, a01.y, a23.x, a23.y,
                                        a45.x, a45.y, a67.x, a67.y};
#pragma unroll
            for (int i = 0; i < 8; i++) {
                FMA2(acc2[i][0], ra[i], b0.x, acc2[i][0]);
                FMA2(acc2[i][1], ra[i], b0.y, acc2[i][1]);
                FMA2(acc2[i][2], ra[i], b1.x, acc2[i][2]);
                FMA2(acc2[i][3], ra[i], b1.y, acc2[i][3]);
            }
        }
        if (more) {
            int nb = buf ^ 1;
            As2[nb][lk + 0][lr] = make_float2(av.x, av.x);
            As2[nb][lk + 1][lr] = make_float2(av.y, av.y);
            As2[nb][lk + 2][lr] = make_float2(av.z, av.z);
            As2[nb][lk + 3][lr] = make_float2(av.w, av.w);
            Ws[nb][lk + 0][lr] = wv.x; Ws[nb][lk + 1][lr] = wv.y;
            Ws[nb][lk + 2][lr] = wv.z; Ws[nb][lk + 3][lr] = wv.w;
        }
        __syncthreads();
    }
#pragma unroll
    for (int i = 0; i < 8; i++) {
        int r = row0 + ty * 8 + i;
        if (r >= M) continue;
        float vals[8] = {lo2(acc2[i][0]), hi2(acc2[i][0]), lo2(acc2[i][1]), hi2(acc2[i][1]),
                         lo2(acc2[i][2]), hi2(acc2[i][2]), lo2(acc2[i][3]), hi2(acc2[i][3])};
#pragma unroll
        for (int j = 0; j < 8; j++) {
            int c = col0 + ((j < 4) ? (tx * 4 + j) : (64 + tx * 4 + (j - 4)));
            if (c < N) C[(size_t)r * N + c] = vals[j] + (bias ? bias[c] : 0.f);
        }
    }
}

// ------------------------- 2b. V-GEMM: correction = C_t . h_b3 ---------------
__global__ __launch_bounds__(256) void vgemm(void) {
    int h = blockIdx.z;
    __shared__ __align__(16) float2 As2[2][8][128];
    __shared__ __align__(16) float Ws[2][8][132];

    int tid = threadIdx.x;
    int row0 = blockIdx.y * 128, col0 = blockIdx.x * 128;
    int lr = tid >> 1;
    int lk = (tid & 1) * 4;
    bool aval = (row0 + lr) < TCOR;
    int cW = col0 + lr;
    const float* Aptr = d_xBCs[0] + (size_t)(row0 + lr + 4) * CONVD + (DIN + NS) + lk;
    const float* Wptr = d_hb3 + ((size_t)(cW >> 6) * 1024 + h * 64 + (cW & 63)) * 128 + lk;

    float4 av = aval ? *(const float4*)Aptr : make_float4(0, 0, 0, 0);
    float4 wv = *(const float4*)Wptr;
    As2[0][lk + 0][lr] = make_float2(av.x, av.x);
    As2[0][lk + 1][lr] = make_float2(av.y, av.y);
    As2[0][lk + 2][lr] = make_float2(av.z, av.z);
    As2[0][lk + 3][lr] = make_float2(av.w, av.w);
    Ws[0][lk + 0][lr] = wv.x; Ws[0][lk + 1][lr] = wv.y;
    Ws[0][lk + 2][lr] = wv.z; Ws[0][lk + 3][lr] = wv.w;
    __syncthreads();

    unsigned long long acc2[8][4];
#pragma unroll
    for (int i = 0; i < 8; i++)
#pragma unroll
        for (int j = 0; j < 4; j++) acc2[i][j] = 0ull;

    int ty = tid >> 4, tx = tid & 15;

    for (int k0 = 0; k0 < 128; k0 += 8) {
        int buf = (k0 >> 3) & 1;
        bool more = (k0 + 8) < 128;
        if (more) {
            av = aval ? *(const float4*)(Aptr + k0 + 8) : make_float4(0, 0, 0, 0);
            wv = *(const float4*)(Wptr + k0 + 8);
        }
#pragma unroll
        for (int kk = 0; kk < 8; kk++) {
            const ulonglong2* Ap = (const ulonglong2*)&As2[buf][kk][ty * 8];
            const ulonglong2* Bp0 = (const ulonglong2*)&Ws[buf][kk][tx * 4];
            const ulonglong2* Bp1 = (const ulonglong2*)&Ws[buf][kk][64 + tx * 4];
            ulonglong2 b0 = Bp0[0];
            ulonglong2 b1 = Bp1[0];
            ulonglong2 a01 = Ap[0], a23 = Ap[1], a45 = Ap[2], a67 = Ap[3];
            unsigned long long ra[8] = {a01.x, a01.y, a23.x, a23.y,
                                        a45.x, a45.y, a67.x, a67.y};
#pragma unroll
            for (int i = 0; i < 8; i++) {
                FMA2(acc2[i][0], ra[i], b0.x, acc2[i][0]);
                FMA2(acc2[i][1], ra[i], b0.y, acc2[i][1]);
                FMA2(acc2[i][2], ra[i], b1.x, acc2[i][2]);
                FMA2(acc2[i][3], ra[i], b1.y, acc2[i][3]);
            }
        }
        if (more) {
            int nb = buf ^ 1;
            As2[nb][lk + 0][lr] = make_float2(av.x, av.x);
            As2[nb][lk + 1][lr] = make_float2(av.y, av.y);
            As2[nb][lk + 2][lr] = make_float2(av.z, av.z);
            As2[nb][lk + 3][lr] = make_float2(av.w, av.w);
            Ws[nb][lk + 0][lr] = wv.x; Ws[nb][lk + 1][lr] = wv.y;
            Ws[nb][lk + 2][lr] = wv.z; Ws[nb][lk + 3][lr] = wv.w;
        }
        __syncthreads();
    }
#pragma unroll
    for (int i = 0; i < 8; i++) {
        int r = row0 + ty * 8 + i;
        if (r >= TCOR) continue;
        float vals[8] = {lo2(acc2[i][0]), hi2(acc2[i][0]), lo2(acc2[i][1]), hi2(acc2[i][1]),
                         lo2(acc2[i][2]), hi2(acc2[i][2]), lo2(acc2[i][3]), hi2(acc2[i][3])};
#pragma unroll
        for (int j = 0; j < 8; j++) {
            int c = col0 + ((j < 4) ? (tx * 4 + j) : (64 + tx * 4 + (j - 4)));
            int b = c >> 6, p = c & 63;
            d_V[((size_t)b * TCOR + r) * DIN + h * 64 + p] = vals[j];
        }
    }
}

// ------------------------- 3. causal depthwise conv + silu -------------------
__global__ void conv_kernel(const float* __restrict__ cw_f, const float* __restrict__ cb_f,
                            const float* __restrict__ cw_b, const float* __restrict__ cb_b) {
    int bx = blockIdx.x;
    int dir = blockIdx.y;
    const float* cw = dir ? cw_b : cw_f;
    const float* cb = dir ? cb_b : cb_f;
    const float* Z = d_Z[dir];

    const float* rows[4];
    float* dst;
    if (bx < L_SEQ) {
        int t = bx;
        if ((dir == 0 && t < 4) || (dir == 1 && t < 1)) return;
        dst = d_xBCs[dir] + (size_t)t * CONVD;
#pragma unroll
        for (int k = 0; k < 4; k++) {
            int tau = dir ? (t + 3 - k) : (t - 3 + k);
            rows[k] = (tau <= L_SEQ - 1) ? (Z + (size_t)(tau - 1) * DPROJ + DIN) : nullptr;
        }
    } else {
        if (dir == 1) return;
        int idx = bx - L_SEQ;
        int b = idx >> 2;
        int t = idx & 3;
        dst = d_xBC0 + (size_t)(b * 4 + t) * CONVD;
#pragma unroll
        for (int k = 0; k < 4; k++) {
            int tau = t - 3 + k;
            rows[k] = (tau >= 0) ? (Z + (size_t)seq_row(b, tau) * DPROJ + DIN) : nullptr;
        }
    }
    for (int c = threadIdx.x; c < CONVD; c += blockDim.x) {
        float acc = cb[c];
#pragma unroll
        for (int k = 0; k < 4; k++)
            if (rows[k]) acc = fmaf(rows[k][c], cw[c * 4 + k], acc);
        dst[c] = fast_silu(acc);
    }
}

// ------------------------- 4. dt / dA per row --------------------------------
__global__ void dtda_kernel(const float* __restrict__ fdtb, const float* __restrict__ fAl,
                            const float* __restrict__ bdtb, const float* __restrict__ bAl) {
    int idx = blockIdx.x * blockDim.x + threadIdx.x;
    const int per = NROWS * NH;
    if (idx >= 2 * per) return;
    int dir = idx / per;
    int r = idx % per;
    int row = r >> 4;
    int h = r & 15;
    float raw = d_Z[dir][(size_t)row * DPROJ + (DIN + CONVD) + h] + (dir ? bdtb : fdtb)[h];
    float dtv = (raw > 20.f) ? raw : log1pf(expf(raw));
    float Al = (dir ? bAl : fAl)[h];
    d_dtr[dir][row * NH + h] = dtv;
    d_dAr[dir][row * NH + h] = expf(-expf(Al) * dtv);
}

// ------------------------- 4b. fwd decay cumprod -----------------------------
__global__ void decay_kernel() {
    int h = threadIdx.x;
    if (h >= NH) return;
    float acc = 1.f;
    for (int t = 4; t <= 2048; t++) {
        acc *= d_dAr[0][(t - 1) * NH + h];
        d_decayf[h * TCOR + (t - 4)] = acc;
    }
}

// ------------------------- 5. combined output vector -------------------------
__global__ void wcomb_kernel(const float* __restrict__ head_w,
                             const float* __restrict__ fow, const float* __restrict__ bow,
                             const float* __restrict__ fnw, const float* __restrict__ bnw) {
    int idx = blockIdx.x * blockDim.x + threadIdx.x;
    if (idx >= 2 * DIN) return;
    int dir = idx >> 10;
    int j = idx & 1023;
    const float* ow = dir ? bow : fow;
    float acc = 0.f;
    for (int i = 0; i < DMODEL; i++) acc = fmaf(ow[(size_t)i * DIN + j], head_w[i], acc);
    d_wcomb[dir][j] = acc * (dir ? bnw : fnw)[j];
}

// ------------------------- 5b. silu(z) per gene row --------------------------
__global__ void siluz_kernel() {
    int row = blockIdx.x;
    int dir = blockIdx.y;
    const float* z = d_Z[dir] + (size_t)row * DPROJ;
    float* P = d_P[dir] + (size_t)row * DIN;
    for (int j = threadIdx.x; j < DIN; j += 256) P[j] = fast_silu(z[j]);
}

// ------------------------- 6a. fwd per-batch prefix scan (t=0..3) ------------
__global__ __launch_bounds__(128) void prefix_kernel(const float* __restrict__ fD) {
    int blk = blockIdx.x;
    int b = blk >> 4;
    int h = blk & 15;
    int tid = threadIdx.x;
    int p = tid & 63;
    int nh = tid >> 6;
    float Dh = fD[h];

    __shared__ __align__(16) float sB[128], sC[128], sx[64];

    unsigned long long hs2[32];
#pragma unroll
    for (int i = 0; i < 32; i++) hs2[i] = 0ull;

    for (int t = 0; t < 4; t++) {
        const float* pp = xbc_fwd_ptr(b, t);
        sB[tid] = pp[DIN + tid];
        sC[tid] = pp[DIN + NS + tid];
        if (tid < 64) sx[tid] = pp[h * HD + tid];
        __syncthreads();
        int row = (t == 0) ? (2048 + b) : (t - 1);
        float dtv = d_dtr[0][row * NH + h];
        float dAv = d_dAr[0][row * NH + h];
        float xv = sx[p];
        unsigned long long coef2 = pack2(dtv * xv);
        unsigned long long dA2 = pack2(dAv);
        const ulonglong2* B4 = (const ulonglong2*)(sB + nh * 64);
        const ulonglong2* C4 = (const ulonglong2*)(sC + nh * 64);
        unsigned long long a0 = 0ull, a1 = 0ull;
#pragma unroll
        for (int i = 0; i < 16; i++) {
            ulonglong2 bv = B4[i], cv = C4[i];
            unsigned long long tm;
            MUL2(tm, coef2, bv.x);
            FMA2(hs2[2 * i + 0], dA2, hs2[2 * i + 0], tm);
            FMA2(a0, hs2[2 * i + 0], cv.x, a0);
            MUL2(tm, coef2, bv.y);
            FMA2(hs2[2 * i + 1], dA2, hs2[2 * i + 1], tm);
            FMA2(a1, hs2[2 * i + 1], cv.y, a1);
        }
        ADD2(a0, a0, a1);
        float part = sum2(a0);
        if (nh == 0) part = fmaf(Dh, xv, part);
        if (t >= 1)
            d_ypre[((size_t)(b * 3 + (t - 1)) * 16 + h) * 128 + tid] = part;
        __syncthreads();
    }
    float2* dst = (float2*)(d_hb3 + ((size_t)(b * 1024 + h * 64 + p)) * 128 + nh * 64);
#pragma unroll
    for (int i = 0; i < 32; i++) dst[i] = *(float2*)&hs2[i];
}

// ------------------------- 6b. shared scans ----------------------------------
// 256 blocks = (dir, h, n-eighth q); 128 threads: p = tid>>1, nh = tid&1.
// Thread owns 8 states (4 hs2). Pair-reduce via shfl_xor(1).
__global__ __launch_bounds__(128) void scan_shared(const float* __restrict__ fD,
                                                   const float* __restrict__ bD) {
    int blk = blockIdx.x;          // 0..255
    int dir = blk >> 7;
    int rest = blk & 127;
    int h = rest >> 3;
    int q = rest & 7;
    int tid = threadIdx.x;
    int p = tid >> 1;
    int nh = tid & 1;
    float Dh = (dir ? bD : fD)[h];
    const float* xbc = d_xBCs[dir];
    const float* dtr = d_dtr[dir];
    const float* dAr = d_dAr[dir];
    float* ysp = d_ysp[dir];

    int S = dir ? 2048 : TCOR;
    int t0 = dir ? 2048 : 4;

    __shared__ __align__(16) float sB[2][16], sC[2][16], sx[2][64];

    unsigned long long hs2[4] = {0ull, 0ull, 0ull, 0ull};

    const float* pp = xbc + (size_t)t0 * CONVD;
    float rv = 0.f;
    if (tid < 16) rv = pp[DIN + q * 16 + tid];
    else if (tid < 32) rv = pp[DIN + NS + q * 16 + (tid - 16)];
    else if (tid >= 64) rv = pp[h * HD + (tid - 64)];
    float rdt = dtr[(t0 - 1) * NH + h];
    float rdA = dAr[(t0 - 1) * NH + h];

    for (int s = 0; s < S; s++) {
        int buf = s & 1;
        int t = dir ? (2048 - s) : (4 + s);
        if (tid < 16) sB[buf][tid] = rv;
        else if (tid < 32) sC[buf][tid - 16] = rv;
        else if (tid >= 64) sx[buf][tid - 64] = rv;
        float dtv = rdt, dAv = rdA;
        __syncthreads();

        int sn = (s + 1 < S) ? (s + 1) : s;
        int tn = dir ? (2048 - sn) : (4 + sn);
        const float* pn = xbc + (size_t)tn * CONVD;
        if (tid < 16) rv = pn[DIN + q * 16 + tid];
        else if (tid < 32) rv = pn[DIN + NS + q * 16 + (tid - 16)];
        else if (tid >= 64) rv = pn[h * HD + (tid - 64)];
        rdt = dtr[(tn - 1) * NH + h];
        rdA = dAr[(tn - 1) * NH + h];

        float xv = sx[buf][p];
        unsigned long long coef2 = pack2(dtv * xv);
        unsigned long long dA2 = pack2(dAv);
        const ulonglong2* B4 = (const ulonglong2*)(sB[buf] + nh * 8);
        const ulonglong2* C4 = (const ulonglong2*)(sC[buf] + nh * 8);
        ulonglong2 bv0 = B4[0], bv1 = B4[1];
        ulonglong2 cv0 = C4[0], cv1 = C4[1];
        unsigned long long a0 = 0ull, a1 = 0ull, tm;
        MUL2(tm, coef2, bv0.x);
        FMA2(hs2[0], dA2, hs2[0], tm);
        FMA2(a0, hs2[0], cv0.x, a0);
        MUL2(tm, coef2, bv0.y);
        FMA2(hs2[1], dA2, hs2[1], tm);
        FMA2(a1, hs2[1], cv0.y, a1);
        MUL2(tm, coef2, bv1.x);
        FMA2(hs2[2], dA2, hs2[2], tm);
        FMA2(a0, hs2[2], cv1.x, a0);
        MUL2(tm, coef2, bv1.y);
        FMA2(hs2[3], dA2, hs2[3], tm);
        FMA2(a1, hs2[3], cv1.y, a1);
        ADD2(a0, a0, a1);
        float part = sum2(a0);
        float other = __shfl_xor_sync(0xffffffffu, part, 1);
        if (nh == 0) {
            float y = part + other;
            if (q == 0) y = fmaf(Dh, xv, y);
            ysp[((size_t)t * NH + h) * 512 + q * 64 + p] = y;
        }
    }
}

// ------------------------- 6c. reduce n-partials -----------------------------
__global__ __launch_bounds__(256) void reduce_ys() {
    int t = blockIdx.x;       // 0..2048
    int dir = blockIdx.y;
    const float* src = d_ysp[dir] + (size_t)t * NH * 512;
    float* dst = d_ysum[dir] + (size_t)t * NH * 64;
    for (int j = threadIdx.x; j < DIN; j += 256) {
        int h = j >> 6, p = j & 63;
        const float* sp = src + h * 512 + p;
        float acc = ((sp[0] + sp[64]) + (sp[128] + sp[192])) +
                    ((sp[256] + sp[320]) + (sp[384] + sp[448]));
        dst[j] = acc;
    }
}

// ------------------------- 7. gate + RMSnorm + fused head --------------------
__global__ __launch_bounds__(256) void final_kernel(const float* __restrict__ head_b,
                                                    float* __restrict__ out) {
    int blk = blockIdx.x;       // 0..8*2048-1
    int b = blk >> 11;
    int t = (blk & 2047) + 1;
    int tid = threadIdx.x;      // 256
    __shared__ float sh[8][4];

    const float* Pf = d_P[0] + (size_t)(t - 1) * DIN;
    const float* Pb = d_P[1] + (size_t)(t - 1) * DIN;
    const float* ysf = d_ysum[0] + (size_t)t * DIN;
    const float* ysb = d_ysum[1] + (size_t)t * DIN;
    const float* Vp = d_V + ((size_t)b * TCOR + (t - 4)) * DIN;  // valid only t>=4

    float ssqf = 0.f, sdotf = 0.f, ssqb = 0.f, sdotb = 0.f;
    for (int j = tid; j < DIN; j += 256) {
        float yb = ysb[j];
        float yf;
        if (t >= 4) {
            int h = j >> 6;
            yf = fmaf(d_decayf[h * TCOR + (t - 4)], Vp[j], ysf[j]);
        } else {
            int h = j >> 6, p = j & 63;
            const float* yp = d_ypre + ((size_t)(b * 3 + (t - 1)) * 16 + h) * 128;
            yf = yp[p] + yp[64 + p];
        }
        float gf = yf * Pf[j];
        ssqf = fmaf(gf, gf, ssqf);
        sdotf = fmaf(gf, d_wcomb[0][j], sdotf);
        float gb = yb * Pb[j];
        ssqb = fmaf(gb, gb, ssqb);
        sdotb = fmaf(gb, d_wcomb[1][j], sdotb);
    }
#pragma unroll
    for (int off = 16; off; off >>= 1) {
        ssqf += __shfl_xor_sync(0xffffffffu, ssqf, off);
        sdotf += __shfl_xor_sync(0xffffffffu, sdotf, off);
        ssqb += __shfl_xor_sync(0xffffffffu, ssqb, off);
        sdotb += __shfl_xor_sync(0xffffffffu, sdotb, off);
    }
    int w = tid >> 5, l = tid & 31;
    if (l == 0) { sh[w][0] = ssqf; sh[w][1] = sdotf; sh[w][2] = ssqb; sh[w][3] = sdotb; }
    __syncthreads();
    if (tid == 0) {
        float a0 = 0.f, a1 = 0.f, a2 = 0.f, a3 = 0.f;
        for (int i = 0; i < 8; i++) {
            a0 += sh[i][0]; a1 += sh[i][1]; a2 += sh[i][2]; a3 += sh[i][3];
        }
        float res = rsqrtf(a0 * (1.f / 1024.f) + 1e-5f) * a1 +
                    rsqrtf(a2 * (1.f / 1024.f) + 1e-5f) * a3;
        out[blk] = res + head_b[0];
    }
}

// ------------------------- launch --------------------------------------------
extern "C" void kernel_launch(void* const* d_in, const int* in_sizes, int n_in,
                              void* d_out, int out_size) {
    const int* pidx            = (const int*)d_in[0];
    const int* chridx          = (const int*)d_in[1];
    const float* locus_fourier = (const float*)d_in[2];
    const float* pathway       = (const float*)d_in[3];
    const float* pert_emb      = (const float*)d_in[4];
    const float* gene_id       = (const float*)d_in[5];
    const float* chr_emb       = (const float*)d_in[6];
    const float* locus_w       = (const float*)d_in[7];
    const float* locus_b       = (const float*)d_in[8];
    const float* cond_w        = (const float*)d_in[9];
    const float* cond_b        = (const float*)d_in[10];
    const float* in_w          = (const float*)d_in[11];
    const float* in_b          = (const float*)d_in[12];
    const float* head_w        = (const float*)d_in[13];
    const float* head_b        = (const float*)d_in[14];
    const float* f_in_w        = (const float*)d_in[15];
    const float* f_conv_w      = (const float*)d_in[16];
    const float* f_conv_b      = (const float*)d_in[17];
    const float* f_dt_bias     = (const float*)d_in[18];
    const float* f_A_log       = (const float*)d_in[19];
    const float* f_D           = (const float*)d_in[20];
    const float* f_norm_w      = (const float*)d_in[21];
    const float* f_out_w       = (const float*)d_in[22];
    const float* b_in_w        = (const float*)d_in[23];
    const float* b_conv_w      = (const float*)d_in[24];
    const float* b_conv_b      = (const float*)d_in[25];
    const float* b_dt_bias     = (const float*)d_in[26];
    const float* b_A_log       = (const float*)d_in[27];
    const float* b_D           = (const float*)d_in[28];
    const float* b_norm_w      = (const float*)d_in[29];
    const float* b_out_w       = (const float*)d_in[30];
    float* out = (float*)d_out;

    feat_kernel<<<NROWS, 128>>>(pidx, chridx, locus_fourier, pathway, pert_emb,
                                gene_id, chr_emb, locus_w, locus_b, cond_w, cond_b);

    sgemm128<<<dim3(4, 17), 256>>>(0, in_w, in_b, 0, NROWS, DMODEL, GENEF);
    sgemm128<<<dim3(19, 17), 256>>>(1, f_in_w, nullptr, 1, NROWS, DPROJ, DMODEL);
    sgemm128<<<dim3(19, 17), 256>>>(1, b_in_w, nullptr, 2, NROWS, DPROJ, DMODEL);

    conv_kernel<<<dim3(L_SEQ + 32, 2), 256>>>(f_conv_w, f_conv_b, b_conv_w, b_conv_b);

    dtda_kernel<<<(2 * NROWS * NH + 255) / 256, 256>>>(f_dt_bias, f_A_log, b_dt_bias, b_A_log);
    decay_kernel<<<1, 32>>>();

    wcomb_kernel<<<(2 * DIN + 255) / 256, 256>>>(head_w, f_out_w, b_out_w, f_norm_w, b_norm_w);
    siluz_kernel<<<dim3(2048, 2), 256>>>();

    // fwd per-batch prefix (t=0..3) -> h_b3, y(1..3)
    prefix_kernel<<<128, 128>>>(f_D);

    // correction GEMM: V[b][t][h*64+p] = C_t . h_b3
    vgemm<<<dim3(4, 16, 16), 256>>>();

    // shared scans: fwd t=4..2048, bwd t=2048..1 (256 blocks, 2/SM)
    scan_shared<<<256, 128>>>(f_D, b_D);

    // reduce n-eighth partials
    reduce_ys<<<dim3(L_SEQ, 2), 256>>>();

    final_kernel<<<BATCH * 2048, 256>>>(head_b, out);
}

// round 6
// speedup vs baseline: 1.7040x; 1.7040x over previous
#include <cuda_runtime.h>
#include <cuda_bf16.h>
#include <math.h>

#define L_SEQ 2049
#define BATCH 8
#define NH 16
#define HD 64
#define NS 128
#define DIN 1024
#define CONVD 1280
#define DPROJ 2320
#define NROWS 2056
#define GENEF 384
#define DMODEL 512
#define TCOR 2045   // corrected timesteps t=4..2048
#define TC 32       // scan chunk length

// ------------------------- scratch (static device globals) -------------------
__device__ float d_feat[NROWS * GENEF];
__device__ float d_X[NROWS * DMODEL];
__device__ float d_Z[2][NROWS * DPROJ];
__device__ float d_xBCs[2][(size_t)L_SEQ * CONVD];   // batch-shared conv out
__device__ float d_xBC0[BATCH * 4 * CONVD];          // fwd per-batch conv out, t=0..3
__device__ float d_dtr[2][NROWS * NH];
__device__ float d_dAr[2][NROWS * NH];
__device__ float d_ysp[2][(size_t)L_SEQ * NH * 8 * 64];  // scan partials [t][h][q][p]
__device__ float d_ysum[2][(size_t)L_SEQ * NH * 64];     // reduced shared-scan y
__device__ float d_ypre[BATCH * 3 * NH * 128];       // fwd per-batch y (t=1..3), halves
__device__ float d_hb3[BATCH * NH * HD * NS];        // fwd per-batch state after t=3
__device__ float d_decayf[NH * TCOR];                // cumprod dA fwd, t=4..2048
__device__ float d_V[(size_t)BATCH * TCOR * DIN];    // correction C_t . h_b3
__device__ float d_P[2][(size_t)2048 * DIN];         // silu(z) per gene row
__device__ float d_wcomb[2][DIN];

__device__ __forceinline__ int seq_row(int b, int t) {
    return (t == 0) ? (2048 + b) : (t - 1);
}
__device__ __forceinline__ const float* xbc_fwd_ptr(int b, int t) {
    return (t >= 4) ? (d_xBCs[0] + (size_t)t * CONVD)
                    : (d_xBC0 + (size_t)(b * 4 + t) * CONVD);
}
__device__ __forceinline__ float fast_silu(float x) {
    return __fdividef(x, 1.f + __expf(-x));
}

// f32x2 packed math (sm_100+)
#define MUL2(d, a, b) asm("mul.rn.f32x2 %0,%1,%2;" : "=l"(d) : "l"(a), "l"(b))
#define FMA2(d, a, b, c) asm("fma.rn.f32x2 %0,%1,%2,%3;" : "=l"(d) : "l"(a), "l"(b), "l"(c))
#define ADD2(d, a, b) asm("add.rn.f32x2 %0,%1,%2;" : "=l"(d) : "l"(a), "l"(b))
__device__ __forceinline__ unsigned long long pack2(float x) {
    unsigned long long r;
    asm("mov.b64 %0,{%1,%1};" : "=l"(r) : "r"(__float_as_uint(x)));
    return r;
}
__device__ __forceinline__ float sum2(unsigned long long v) {
    unsigned int lo, hi;
    asm("mov.b64 {%0,%1},%2;" : "=r"(lo), "=r"(hi) : "l"(v));
    return __uint_as_float(lo) + __uint_as_float(hi);
}
__device__ __forceinline__ float lo2(unsigned long long v) {
    unsigned int lo;
    asm("mov.b64 {%0,_},%1;" : "=r"(lo) : "l"(v));
    return __uint_as_float(lo);
}
__device__ __forceinline__ float hi2(unsigned long long v) {
    unsigned int hi;
    asm("mov.b64 {_,%0},%1;" : "=r"(hi) : "l"(v));
    return __uint_as_float(hi);
}

// ------------------------- 1. feature rows -----------------------------------
__global__ void feat_kernel(const int* __restrict__ pidx,
                            const int* __restrict__ chridx,
                            const float* __restrict__ locus_fourier,
                            const float* __restrict__ pathway,
                            const float* __restrict__ pert_emb,
                            const float* __restrict__ gene_id,
                            const float* __restrict__ chr_emb,
                            const float* __restrict__ locus_w,
                            const float* __restrict__ locus_b,
                            const float* __restrict__ cond_w,
                            const float* __restrict__ cond_b) {
    int g = blockIdx.x;
    int tid = threadIdx.x;  // 128
    if (g < 2048) {
        d_feat[g * GENEF + tid] = gene_id[g * 128 + tid];
        d_feat[g * GENEF + 128 + tid] = pathway[g * 128 + tid];
        if (tid < 64) {
            int ci = chridx[g];
            d_feat[g * GENEF + 256 + tid] = chr_emb[ci * 64 + tid];
        } else {
            int j = tid - 64;
            float acc = locus_b[j];
            const float* lf = locus_fourier + g * 64;
            const float* lw = locus_w + j * 64;
            for (int k = 0; k < 64; k++) acc = fmaf(lf[k], lw[k], acc);
            float ge = 0.5f * acc * (1.f + erff(acc * 0.70710678118654752f));
            d_feat[g * GENEF + 320 + j] = ge;
        }
    } else {
        int b = g - 2048;
        const float* pe = pert_emb + (size_t)pidx[b] * 128;
        for (int j = tid; j < GENEF; j += 128) {
            float acc = cond_b[j];
            const float* cw = cond_w + (size_t)j * 128;
            for (int k = 0; k < 128; k++) acc = fmaf(pe[k], cw[k], acc);
            d_feat[g * GENEF + j] = acc;
        }
    }
}

// ------------------------- 2. SGEMM 128x128 tile, 8x8/thread, f32x2 ----------
__global__ __launch_bounds__(256) void sgemm128(int src_sel,
                                                const float* __restrict__ W,
                                                const float* __restrict__ bias,
                                                int dst_sel, int M, int N, int K) {
    const float* A = (src_sel == 0) ? d_feat : d_X;
    float* C = (dst_sel == 0) ? d_X : d_Z[dst_sel - 1];

    __shared__ __align__(16) float2 As2[2][8][128];
    __shared__ __align__(16) float Ws[2][8][132];

    int tid = threadIdx.x;
    int row0 = blockIdx.y * 128, col0 = blockIdx.x * 128;
    int lr = tid >> 1;
    int lk = (tid & 1) * 4;
    bool aval = (row0 + lr) < M;
    bool wval = (col0 + lr) < N;
    const float* Aptr = A + (size_t)(row0 + lr) * K + lk;
    const float* Wptr = W + (size_t)(col0 + lr) * K + lk;

    float4 av = aval ? *(const float4*)Aptr : make_float4(0, 0, 0, 0);
    float4 wv = wval ? *(const float4*)Wptr : make_float4(0, 0, 0, 0);
    As2[0][lk + 0][lr] = make_float2(av.x, av.x);
    As2[0][lk + 1][lr] = make_float2(av.y, av.y);
    As2[0][lk + 2][lr] = make_float2(av.z, av.z);
    As2[0][lk + 3][lr] = make_float2(av.w, av.w);
    Ws[0][lk + 0][lr] = wv.x; Ws[0][lk + 1][lr] = wv.y;
    Ws[0][lk + 2][lr] = wv.z; Ws[0][lk + 3][lr] = wv.w;
    __syncthreads();

    unsigned long long acc2[8][4];
#pragma unroll
    for (int i = 0; i < 8; i++)
#pragma unroll
        for (int j = 0; j < 4; j++) acc2[i][j] = 0ull;

    int ty = tid >> 4, tx = tid & 15;

    for (int k0 = 0; k0 < K; k0 += 8) {
        int buf = (k0 >> 3) & 1;
        bool more = (k0 + 8) < K;
        if (more) {
            av = aval ? *(const float4*)(Aptr + k0 + 8) : make_float4(0, 0, 0, 0);
            wv = wval ? *(const float4*)(Wptr + k0 + 8) : make_float4(0, 0, 0, 0);
        }
#pragma unroll
        for (int kk = 0; kk < 8; kk++) {
            const ulonglong2* Ap = (const ulonglong2*)&As2[buf][kk][ty * 8];
            const ulonglong2* Bp0 = (const ulonglong2*)&Ws[buf][kk][tx * 4];
            const ulonglong2* Bp1 = (const ulonglong2*)&Ws[buf][kk][64 + tx * 4];
            ulonglong2 b0 = Bp0[0];
            ulonglong2 b1 = Bp1[0];
            ulonglong2 a01 = Ap[0], a23 = Ap[1], a45 = Ap[2], a67 = Ap[3];
            unsigned long long ra[8] = {a01.x, a01.y, a23.x, a23.y,
                                        a45.x, a45.y, a67.x, a67.y};
#pragma unroll
            for (int i = 0; i < 8; i++) {
                FMA2(acc2[i][0], ra[i], b0.x, acc2[i][0]);
                FMA2(acc2[i][1], ra[i], b0.y, acc2[i][1]);
                FMA2(acc2[i][2], ra[i], b1.x, acc2[i][2]);
                FMA2(acc2[i][3], ra[i], b1.y, acc2[i][3]);
            }
        }
        if (more) {
            int nb = buf ^ 1;
            As2[nb][lk + 0][lr] = make_float2(av.x, av.x);
            As2[nb][lk + 1][lr] = make_float2(av.y, av.y);
            As2[nb][lk + 2][lr] = make_float2(av.z, av.z);
            As2[nb][lk + 3][lr] = make_float2(av.w, av.w);
            Ws[nb][lk + 0][lr] = wv.x; Ws[nb][lk + 1][lr] = wv.y;
            Ws[nb][lk + 2][lr] = wv.z; Ws[nb][lk + 3][lr] = wv.w;
        }
        __syncthreads();
    }
#pragma unroll
    for (int i = 0; i < 8; i++) {
        int r = row0 + ty * 8 + i;
        if (r >= M) continue;
        float vals[8] = {lo2(acc2[i][0]), hi2(acc2[i][0]), lo2(acc2[i][1]), hi2(acc2[i][1]),
                         lo2(acc2[i][2]), hi2(acc2[i][2]), lo2(acc2[i][3]), hi2(acc2[i][3])};
#pragma unroll
        for (int j = 0; j < 8; j++) {
            int c = col0 + ((j < 4) ? (tx * 4 + j) : (64 + tx * 4 + (j - 4)));
            if (c < N) C[(size_t)r * N + c] = vals[j] + (bias ? bias[c] : 0.f);
        }
    }
}

// ------------------------- 2b. V-GEMM: correction = C_t . h_b3 ---------------
__global__ __launch_bounds__(256) void vgemm(void) {
    int h = blockIdx.z;
    __shared__ __align__(16) float2 As2[2][8][128];
    __shared__ __align__(16) float Ws[2][8][132];

    int tid = threadIdx.x;
    int row0 = blockIdx.y * 128, col0 = blockIdx.x * 128;
    int lr = tid >> 1;
    int lk = (tid & 1) * 4;
    bool aval = (row0 + lr) < TCOR;
    int cW = col0 + lr;
    const float* Aptr = d_xBCs[0] + (size_t)(row0 + lr + 4) * CONVD + (DIN + NS) + lk;
    const float* Wptr = d_hb3 + ((size_t)(cW >> 6) * 1024 + h * 64 + (cW & 63)) * 128 + lk;

    float4 av = aval ? *(const float4*)Aptr : make_float4(0, 0, 0, 0);
    float4 wv = *(const float4*)Wptr;
    As2[0][lk + 0][lr] = make_float2(av.x, av.x);
    As2[0][lk + 1][lr] = make_float2(av.y, av.y);
    As2[0][lk + 2][lr] = make_float2(av.z, av.z);
    As2[0][lk + 3][lr] = make_float2(av.w, av.w);
    Ws[0][lk + 0][lr] = wv.x; Ws[0][lk + 1][lr] = wv.y;
    Ws[0][lk + 2][lr] = wv.z; Ws[0][lk + 3][lr] = wv.w;
    __syncthreads();

    unsigned long long acc2[8][4];
#pragma unroll
    for (int i = 0; i < 8; i++)
#pragma unroll
        for (int j = 0; j < 4; j++) acc2[i][j] = 0ull;

    int ty = tid >> 4, tx = tid & 15;

    for (int k0 = 0; k0 < 128; k0 += 8) {
        int buf = (k0 >> 3) & 1;
        bool more = (k0 + 8) < 128;
        if (more) {
            av = aval ? *(const float4*)(Aptr + k0 + 8) : make_float4(0, 0, 0, 0);
            wv = *(const float4*)(Wptr + k0 + 8);
        }
#pragma unroll
        for (int kk = 0; kk < 8; kk++) {
            const ulonglong2* Ap = (const ulonglong2*)&As2[buf][kk][ty * 8];
            const ulonglong2* Bp0 = (const ulonglong2*)&Ws[buf][kk][tx * 4];
            const ulonglong2* Bp1 = (const ulonglong2*)&Ws[buf][kk][64 + tx * 4];
            ulonglong2 b0 = Bp0[0];
            ulonglong2 b1 = Bp1[0];
            ulonglong2 a01 = Ap[0], a23 = Ap[1], a45 = Ap[2], a67 = Ap[3];
            unsigned long long ra[8] = {a01.x, a01.y, a23.x, a23.y,
                                        a45.x, a45.y, a67.x, a67.y};
#pragma unroll
            for (int i = 0; i < 8; i++) {
                FMA2(acc2[i][0], ra[i], b0.x, acc2[i][0]);
                FMA2(acc2[i][1], ra[i], b0.y, acc2[i][1]);
                FMA2(acc2[i][2], ra[i], b1.x, acc2[i][2]);
                FMA2(acc2[i][3], ra[i], b1.y, acc2[i][3]);
            }
        }
        if (more) {
            int nb = buf ^ 1;
            As2[nb][lk + 0][lr] = make_float2(av.x, av.x);
            As2[nb][lk + 1][lr] = make_float2(av.y, av.y);
            As2[nb][lk + 2][lr] = make_float2(av.z, av.z);
            As2[nb][lk + 3][lr] = make_float2(av.w, av.w);
            Ws[nb][lk + 0][lr] = wv.x; Ws[nb][lk + 1][lr] = wv.y;
            Ws[nb][lk + 2][lr] = wv.z; Ws[nb][lk + 3][lr] = wv.w;
        }
        __syncthreads();
    }
#pragma unroll
    for (int i = 0; i < 8; i++) {
        int r = row0 + ty * 8 + i;
        if (r >= TCOR) continue;
        float vals[8] = {lo2(acc2[i][0]), hi2(acc2[i][0]), lo2(acc2[i][1]), hi2(acc2[i][1]),
                         lo2(acc2[i][2]), hi2(acc2[i][2]), lo2(acc2[i][3]), hi2(acc2[i][3])};
#pragma unroll
        for (int j = 0; j < 8; j++) {
            int c = col0 + ((j < 4) ? (tx * 4 + j) : (64 + tx * 4 + (j - 4)));
            int b = c >> 6, p = c & 63;
            d_V[((size_t)b * TCOR + r) * DIN + h * 64 + p] = vals[j];
        }
    }
}

// ------------------------- 3. causal depthwise conv + silu -------------------
__global__ void conv_kernel(const float* __restrict__ cw_f, const float* __restrict__ cb_f,
                            const float* __restrict__ cw_b, const float* __restrict__ cb_b) {
    int bx = blockIdx.x;
    int dir = blockIdx.y;
    const float* cw = dir ? cw_b : cw_f;
    const float* cb = dir ? cb_b : cb_f;
    const float* Z = d_Z[dir];

    const float* rows[4];
    float* dst;
    if (bx < L_SEQ) {
        int t = bx;
        if ((dir == 0 && t < 4) || (dir == 1 && t < 1)) return;
        dst = d_xBCs[dir] + (size_t)t * CONVD;
#pragma unroll
        for (int k = 0; k < 4; k++) {
            int tau = dir ? (t + 3 - k) : (t - 3 + k);
            rows[k] = (tau <= L_SEQ - 1) ? (Z + (size_t)(tau - 1) * DPROJ + DIN) : nullptr;
        }
    } else {
        if (dir == 1) return;
        int idx = bx - L_SEQ;
        int b = idx >> 2;
        int t = idx & 3;
        dst = d_xBC0 + (size_t)(b * 4 + t) * CONVD;
#pragma unroll
        for (int k = 0; k < 4; k++) {
            int tau = t - 3 + k;
            rows[k] = (tau >= 0) ? (Z + (size_t)seq_row(b, tau) * DPROJ + DIN) : nullptr;
        }
    }
    for (int c = threadIdx.x; c < CONVD; c += blockDim.x) {
        float acc = cb[c];
#pragma unroll
        for (int k = 0; k < 4; k++)
            if (rows[k]) acc = fmaf(rows[k][c], cw[c * 4 + k], acc);
        dst[c] = fast_silu(acc);
    }
}

// ------------------------- 4. dt / dA per row --------------------------------
__global__ void dtda_kernel(const float* __restrict__ fdtb, const float* __restrict__ fAl,
                            const float* __restrict__ bdtb, const float* __restrict__ bAl) {
    int idx = blockIdx.x * blockDim.x + threadIdx.x;
    const int per = NROWS * NH;
    if (idx >= 2 * per) return;
    int dir = idx / per;
    int r = idx % per;
    int row = r >> 4;
    int h = r & 15;
    float raw = d_Z[dir][(size_t)row * DPROJ + (DIN + CONVD) + h] + (dir ? bdtb : fdtb)[h];
    float dtv = (raw > 20.f) ? raw : log1pf(expf(raw));
    float Al = (dir ? bAl : fAl)[h];
    d_dtr[dir][row * NH + h] = dtv;
    d_dAr[dir][row * NH + h] = expf(-expf(Al) * dtv);
}

// ------------------------- 4b. fwd decay cumprod -----------------------------
__global__ void decay_kernel() {
    int h = threadIdx.x;
    if (h >= NH) return;
    float acc = 1.f;
    for (int t = 4; t <= 2048; t++) {
        acc *= d_dAr[0][(t - 1) * NH + h];
        d_decayf[h * TCOR + (t - 4)] = acc;
    }
}

// ------------------------- 5. combined output vector -------------------------
__global__ void wcomb_kernel(const float* __restrict__ head_w,
                             const float* __restrict__ fow, const float* __restrict__ bow,
                             const float* __restrict__ fnw, const float* __restrict__ bnw) {
    int idx = blockIdx.x * blockDim.x + threadIdx.x;
    if (idx >= 2 * DIN) return;
    int dir = idx >> 10;
    int j = idx & 1023;
    const float* ow = dir ? bow : fow;
    float acc = 0.f;
    for (int i = 0; i < DMODEL; i++) acc = fmaf(ow[(size_t)i * DIN + j], head_w[i], acc);
    d_wcomb[dir][j] = acc * (dir ? bnw : fnw)[j];
}

// ------------------------- 5b. silu(z) per gene row --------------------------
__global__ void siluz_kernel() {
    int row = blockIdx.x;
    int dir = blockIdx.y;
    const float* z = d_Z[dir] + (size_t)row * DPROJ;
    float* P = d_P[dir] + (size_t)row * DIN;
    for (int j = threadIdx.x; j < DIN; j += 256) P[j] = fast_silu(z[j]);
}

// ------------------------- 6a. fwd per-batch prefix scan (t=0..3) ------------
__global__ __launch_bounds__(128) void prefix_kernel(const float* __restrict__ fD) {
    int blk = blockIdx.x;
    int b = blk >> 4;
    int h = blk & 15;
    int tid = threadIdx.x;
    int p = tid & 63;
    int nh = tid >> 6;
    float Dh = fD[h];

    __shared__ __align__(16) float sB[128], sC[128], sx[64];

    unsigned long long hs2[32];
#pragma unroll
    for (int i = 0; i < 32; i++) hs2[i] = 0ull;

    for (int t = 0; t < 4; t++) {
        const float* pp = xbc_fwd_ptr(b, t);
        sB[tid] = pp[DIN + tid];
        sC[tid] = pp[DIN + NS + tid];
        if (tid < 64) sx[tid] = pp[h * HD + tid];
        __syncthreads();
        int row = (t == 0) ? (2048 + b) : (t - 1);
        float dtv = d_dtr[0][row * NH + h];
        float dAv = d_dAr[0][row * NH + h];
        float xv = sx[p];
        unsigned long long coef2 = pack2(dtv * xv);
        unsigned long long dA2 = pack2(dAv);
        const ulonglong2* B4 = (const ulonglong2*)(sB + nh * 64);
        const ulonglong2* C4 = (const ulonglong2*)(sC + nh * 64);
        unsigned long long a0 = 0ull, a1 = 0ull;
#pragma unroll
        for (int i = 0; i < 16; i++) {
            ulonglong2 bv = B4[i], cv = C4[i];
            unsigned long long tm;
            MUL2(tm, coef2, bv.x);
            FMA2(hs2[2 * i + 0], dA2, hs2[2 * i + 0], tm);
            FMA2(a0, hs2[2 * i + 0], cv.x, a0);
            MUL2(tm, coef2, bv.y);
            FMA2(hs2[2 * i + 1], dA2, hs2[2 * i + 1], tm);
            FMA2(a1, hs2[2 * i + 1], cv.y, a1);
        }
        ADD2(a0, a0, a1);
        float part = sum2(a0);
        if (nh == 0) part = fmaf(Dh, xv, part);
        if (t >= 1)
            d_ypre[((size_t)(b * 3 + (t - 1)) * 16 + h) * 128 + tid] = part;
        __syncthreads();
    }
    float2* dst = (float2*)(d_hb3 + ((size_t)(b * 1024 + h * 64 + p)) * 128 + nh * 64);
#pragma unroll
    for (int i = 0; i < 32; i++) dst[i] = *(float2*)&hs2[i];
}

// ------------------------- 6b. shared scans, chunked staging -----------------
// 128 blocks = (dir, h, n-quarter nq). 128 threads = 4 warps.
// warp w: p-lane = (w&1)*32 + lane (32 p per warp), n-sub = w>>1 (16 states).
// Per chunk of TC=32 steps: stage B/C quarter + x + dt/dA into shared with
// coalesced float4 loads, then 32 steps from shared only (no per-step barrier).
__global__ __launch_bounds__(128) void scan_shared(const float* __restrict__ fD,
                                                   const float* __restrict__ bD) {
    int blk = blockIdx.x;          // 0..127
    int dir = blk >> 6;
    int rest = blk & 63;
    int h = rest >> 2;
    int nq = rest & 3;
    int tid = threadIdx.x;
    int wid = tid >> 5;
    int lane = tid & 31;
    int p = (wid & 1) * 32 + lane;
    int sub = wid >> 1;            // n-sub within quarter
    int qg = nq * 2 + sub;         // global n-eighth index (0..7)
    float Dh = (dir ? bD : fD)[h];
    const float* xbc = d_xBCs[dir];
    const float* dtr = d_dtr[dir];
    const float* dAr = d_dAr[dir];
    float* ysp = d_ysp[dir];

    int S = dir ? 2048 : TCOR;     // steps
    // t(j) = dir ? 2048 - s : 4 + s

    __shared__ __align__(16) float sB[TC][32];
    __shared__ __align__(16) float sC[TC][32];
    __shared__ __align__(16) float sx[TC][64];
    __shared__ float sdt[TC], sdA[TC];

    unsigned long long hs2[8];
#pragma unroll
    for (int i = 0; i < 8; i++) hs2[i] = 0ull;

    for (int s0 = 0; s0 < S; s0 += TC) {
        int cnt = (S - s0 < TC) ? (S - s0) : TC;
        __syncthreads();   // previous chunk fully consumed
        // stage B, C (8 float4 per row each)
        for (int i = tid; i < cnt * 8; i += 128) {
            int j = i >> 3, cc = i & 7;
            int tt = dir ? (2048 - (s0 + j)) : (4 + s0 + j);
            const float* rowp = xbc + (size_t)tt * CONVD + DIN + nq * 32;
            *(float4*)&sB[j][cc * 4] = ((const float4*)rowp)[cc];
            *(float4*)&sC[j][cc * 4] = ((const float4*)(rowp + NS))[cc];
        }
        // stage x (16 float4 per row)
        for (int i = tid; i < cnt * 16; i += 128) {
            int j = i >> 4, cc = i & 15;
            int tt = dir ? (2048 - (s0 + j)) : (4 + s0 + j);
            *(float4*)&sx[j][cc * 4] =
                ((const float4*)(xbc + (size_t)tt * CONVD + h * HD))[cc];
        }
        // stage dt / dA
        if (tid < cnt) {
            int tt = dir ? (2048 - (s0 + tid)) : (4 + s0 + tid);
            sdt[tid] = dtr[(tt - 1) * NH + h];
            sdA[tid] = dAr[(tt - 1) * NH + h];
        }
        __syncthreads();

        for (int j = 0; j < cnt; j++) {
            int tt = dir ? (2048 - (s0 + j)) : (4 + s0 + j);
            float dtv = sdt[j], dAv = sdA[j];
            float xv = sx[j][p];
            unsigned long long coef2 = pack2(dtv * xv);
            unsigned long long dA2 = pack2(dAv);
            const ulonglong2* B4 = (const ulonglong2*)&sB[j][sub * 16];
            const ulonglong2* C4 = (const ulonglong2*)&sC[j][sub * 16];
            unsigned long long a0 = 0ull, a1 = 0ull, tm;
#pragma unroll
            for (int i = 0; i < 4; i++) {
                ulonglong2 bv = B4[i], cv = C4[i];
                MUL2(tm, coef2, bv.x);
                FMA2(hs2[2 * i + 0], dA2, hs2[2 * i + 0], tm);
                FMA2(a0, hs2[2 * i + 0], cv.x, a0);
                MUL2(tm, coef2, bv.y);
                FMA2(hs2[2 * i + 1], dA2, hs2[2 * i + 1], tm);
                FMA2(a1, hs2[2 * i + 1], cv.y, a1);
            }
            ADD2(a0, a0, a1);
            float y = sum2(a0);
            if (qg == 0) y = fmaf(Dh, xv, y);
            ysp[((size_t)tt * NH + h) * 512 + qg * 64 + p] = y;
        }
    }
}

// ------------------------- 6c. reduce n-partials -----------------------------
__global__ __launch_bounds__(256) void reduce_ys() {
    int t = blockIdx.x;       // 0..2048
    int dir = blockIdx.y;
    const float* src = d_ysp[dir] + (size_t)t * NH * 512;
    float* dst = d_ysum[dir] + (size_t)t * NH * 64;
    for (int j = threadIdx.x; j < DIN; j += 256) {
        int h = j >> 6, p = j & 63;
        const float* sp = src + h * 512 + p;
        float acc = ((sp[0] + sp[64]) + (sp[128] + sp[192])) +
                    ((sp[256] + sp[320]) + (sp[384] + sp[448]));
        dst[j] = acc;
    }
}

// ------------------------- 7. gate + RMSnorm + fused head --------------------
__global__ __launch_bounds__(256) void final_kernel(const float* __restrict__ head_b,
                                                    float* __restrict__ out) {
    int blk = blockIdx.x;       // 0..8*2048-1
    int b = blk >> 11;
    int t = (blk & 2047) + 1;
    int tid = threadIdx.x;      // 256
    __shared__ float sh[8][4];

    const float* Pf = d_P[0] + (size_t)(t - 1) * DIN;
    const float* Pb = d_P[1] + (size_t)(t - 1) * DIN;
    const float* ysf = d_ysum[0] + (size_t)t * DIN;
    const float* ysb = d_ysum[1] + (size_t)t * DIN;
    const float* Vp = d_V + ((size_t)b * TCOR + (t - 4)) * DIN;  // valid only t>=4

    float ssqf = 0.f, sdotf = 0.f, ssqb = 0.f, sdotb = 0.f;
    for (int j = tid; j < DIN; j += 256) {
        float yb = ysb[j];
        float yf;
        if (t >= 4) {
            int h = j >> 6;
            yf = fmaf(d_decayf[h * TCOR + (t - 4)], Vp[j], ysf[j]);
        } else {
            int h = j >> 6, p = j & 63;
            const float* yp = d_ypre + ((size_t)(b * 3 + (t - 1)) * 16 + h) * 128;
            yf = yp[p] + yp[64 + p];
        }
        float gf = yf * Pf[j];
        ssqf = fmaf(gf, gf, ssqf);
        sdotf = fmaf(gf, d_wcomb[0][j], sdotf);
        float gb = yb * Pb[j];
        ssqb = fmaf(gb, gb, ssqb);
        sdotb = fmaf(gb, d_wcomb[1][j], sdotb);
    }
#pragma unroll
    for (int off = 16; off; off >>= 1) {
        ssqf += __shfl_xor_sync(0xffffffffu, ssqf, off);
        sdotf += __shfl_xor_sync(0xffffffffu, sdotf, off);
        ssqb += __shfl_xor_sync(0xffffffffu, ssqb, off);
        sdotb += __shfl_xor_sync(0xffffffffu, sdotb, off);
    }
    int w = tid >> 5, l = tid & 31;
    if (l == 0) { sh[w][0] = ssqf; sh[w][1] = sdotf; sh[w][2] = ssqb; sh[w][3] = sdotb; }
    __syncthreads();
    if (tid == 0) {
        float a0 = 0.f, a1 = 0.f, a2 = 0.f, a3 = 0.f;
        for (int i = 0; i < 8; i++) {
            a0 += sh[i][0]; a1 += sh[i][1]; a2 += sh[i][2]; a3 += sh[i][3];
        }
        float res = rsqrtf(a0 * (1.f / 1024.f) + 1e-5f) * a1 +
                    rsqrtf(a2 * (1.f / 1024.f) + 1e-5f) * a3;
        out[blk] = res + head_b[0];
    }
}

// ------------------------- launch --------------------------------------------
extern "C" void kernel_launch(void* const* d_in, const int* in_sizes, int n_in,
                              void* d_out, int out_size) {
    const int* pidx            = (const int*)d_in[0];
    const int* chridx          = (const int*)d_in[1];
    const float* locus_fourier = (const float*)d_in[2];
    const float* pathway       = (const float*)d_in[3];
    const float* pert_emb      = (const float*)d_in[4];
    const float* gene_id       = (const float*)d_in[5];
    const float* chr_emb       = (const float*)d_in[6];
    const float* locus_w       = (const float*)d_in[7];
    const float* locus_b       = (const float*)d_in[8];
    const float* cond_w        = (const float*)d_in[9];
    const float* cond_b        = (const float*)d_in[10];
    const float* in_w          = (const float*)d_in[11];
    const float* in_b          = (const float*)d_in[12];
    const float* head_w        = (const float*)d_in[13];
    const float* head_b        = (const float*)d_in[14];
    const float* f_in_w        = (const float*)d_in[15];
    const float* f_conv_w      = (const float*)d_in[16];
    const float* f_conv_b      = (const float*)d_in[17];
    const float* f_dt_bias     = (const float*)d_in[18];
    const float* f_A_log       = (const float*)d_in[19];
    const float* f_D           = (const float*)d_in[20];
    const float* f_norm_w      = (const float*)d_in[21];
    const float* f_out_w       = (const float*)d_in[22];
    const float* b_in_w        = (const float*)d_in[23];
    const float* b_conv_w      = (const float*)d_in[24];
    const float* b_conv_b      = (const float*)d_in[25];
    const float* b_dt_bias     = (const float*)d_in[26];
    const float* b_A_log       = (const float*)d_in[27];
    const float* b_D           = (const float*)d_in[28];
    const float* b_norm_w      = (const float*)d_in[29];
    const float* b_out_w       = (const float*)d_in[30];
    float* out = (float*)d_out;

    feat_kernel<<<NROWS, 128>>>(pidx, chridx, locus_fourier, pathway, pert_emb,
                                gene_id, chr_emb, locus_w, locus_b, cond_w, cond_b);

    sgemm128<<<dim3(4, 17), 256>>>(0, in_w, in_b, 0, NROWS, DMODEL, GENEF);
    sgemm128<<<dim3(19, 17), 256>>>(1, f_in_w, nullptr, 1, NROWS, DPROJ, DMODEL);
    sgemm128<<<dim3(19, 17), 256>>>(1, b_in_w, nullptr, 2, NROWS, DPROJ, DMODEL);

    conv_kernel<<<dim3(L_SEQ + 32, 2), 256>>>(f_conv_w, f_conv_b, b_conv_w, b_conv_b);

    dtda_kernel<<<(2 * NROWS * NH + 255) / 256, 256>>>(f_dt_bias, f_A_log, b_dt_bias, b_A_log);
    decay_kernel<<<1, 32>>>();

    wcomb_kernel<<<(2 * DIN + 255) / 256, 256>>>(head_w, f_out_w, b_out_w, f_norm_w, b_norm_w);
    siluz_kernel<<<dim3(2048, 2), 256>>>();

    // fwd per-batch prefix (t=0..3) -> h_b3, y(1..3)
    prefix_kernel<<<128, 128>>>(f_D);

    // correction GEMM: V[b][t][h*64+p] = C_t . h_b3
    vgemm<<<dim3(4, 16, 16), 256>>>();

    // shared scans with chunked staging (128 blocks, 1/SM)
    scan_shared<<<128, 128>>>(f_D, b_D);

    // reduce n-eighth partials
    reduce_ys<<<dim3(L_SEQ, 2), 256>>>();

    final_kernel<<<BATCH * 2048, 256>>>(head_b, out);
}

// round 7
// speedup vs baseline: 1.8586x; 1.0907x over previous
#include <cuda_runtime.h>
#include <cuda_bf16.h>
#include <math.h>

#define L_SEQ 2049
#define BATCH 8
#define NH 16
#define HD 64
#define NS 128
#define DIN 1024
#define CONVD 1280
#define DPROJ 2320
#define NROWS 2056
#define GENEF 384
#define DMODEL 512
#define TCOR 2045   // corrected timesteps t=4..2048
#define TC 32       // scan chunk length

// ------------------------- scratch (static device globals) -------------------
__device__ float d_feat[NROWS * GENEF];
__device__ float d_X[NROWS * DMODEL];
__device__ float d_Z[2][NROWS * DPROJ];
__device__ float d_xBCs[2][(size_t)L_SEQ * CONVD];   // batch-shared conv out
__device__ float d_xBC0[BATCH * 4 * CONVD];          // fwd per-batch conv out, t=0..3
__device__ float d_dtr[2][NROWS * NH];
__device__ float d_dAr[2][NROWS * NH];
__device__ float d_ysp[2][(size_t)L_SEQ * NH * 16 * 64]; // scan partials [t][h][s16][p]
__device__ float d_ysum[2][(size_t)L_SEQ * NH * 64];     // reduced shared-scan y
__device__ float d_ypre[BATCH * 3 * NH * 128];       // fwd per-batch y (t=1..3), halves
__device__ float d_decayf[NH * TCOR];                // cumprod dA fwd, t=4..2048
__device__ float d_dotCB[L_SEQ * 32];                // C_t . B_tau  [t][b][tau]
__device__ float d_W4[BATCH * NH * 4];               // dt_tau * prod dA  [b][h][tau]
__device__ float d_P[2][(size_t)2048 * DIN];         // silu(z) per gene row
__device__ float d_wcomb[2][DIN];

__device__ __forceinline__ int seq_row(int b, int t) {
    return (t == 0) ? (2048 + b) : (t - 1);
}
__device__ __forceinline__ const float* xbc_fwd_ptr(int b, int t) {
    return (t >= 4) ? (d_xBCs[0] + (size_t)t * CONVD)
                    : (d_xBC0 + (size_t)(b * 4 + t) * CONVD);
}
__device__ __forceinline__ float fast_silu(float x) {
    return __fdividef(x, 1.f + __expf(-x));
}

// f32x2 packed math (sm_100+)
#define MUL2(d, a, b) asm("mul.rn.f32x2 %0,%1,%2;" : "=l"(d) : "l"(a), "l"(b))
#define FMA2(d, a, b, c) asm("fma.rn.f32x2 %0,%1,%2,%3;" : "=l"(d) : "l"(a), "l"(b), "l"(c))
#define ADD2(d, a, b) asm("add.rn.f32x2 %0,%1,%2;" : "=l"(d) : "l"(a), "l"(b))
__device__ __forceinline__ unsigned long long pack2(float x) {
    unsigned long long r;
    asm("mov.b64 %0,{%1,%1};" : "=l"(r) : "r"(__float_as_uint(x)));
    return r;
}
__device__ __forceinline__ float sum2(unsigned long long v) {
    unsigned int lo, hi;
    asm("mov.b64 {%0,%1},%2;" : "=r"(lo), "=r"(hi) : "l"(v));
    return __uint_as_float(lo) + __uint_as_float(hi);
}
__device__ __forceinline__ float lo2(unsigned long long v) {
    unsigned int lo;
    asm("mov.b64 {%0,_},%1;" : "=r"(lo) : "l"(v));
    return __uint_as_float(lo);
}
__device__ __forceinline__ float hi2(unsigned long long v) {
    unsigned int hi;
    asm("mov.b64 {_,%0},%1;" : "=r"(hi) : "l"(v));
    return __uint_as_float(hi);
}

// ------------------------- 1. feature rows -----------------------------------
__global__ void feat_kernel(const int* __restrict__ pidx,
                            const int* __restrict__ chridx,
                            const float* __restrict__ locus_fourier,
                            const float* __restrict__ pathway,
                            const float* __restrict__ pert_emb,
                            const float* __restrict__ gene_id,
                            const float* __restrict__ chr_emb,
                            const float* __restrict__ locus_w,
                            const float* __restrict__ locus_b,
                            const float* __restrict__ cond_w,
                            const float* __restrict__ cond_b) {
    int g = blockIdx.x;
    int tid = threadIdx.x;  // 128
    if (g < 2048) {
        d_feat[g * GENEF + tid] = gene_id[g * 128 + tid];
        d_feat[g * GENEF + 128 + tid] = pathway[g * 128 + tid];
        if (tid < 64) {
            int ci = chridx[g];
            d_feat[g * GENEF + 256 + tid] = chr_emb[ci * 64 + tid];
        } else {
            int j = tid - 64;
            float acc = locus_b[j];
            const float* lf = locus_fourier + g * 64;
            const float* lw = locus_w + j * 64;
            for (int k = 0; k < 64; k++) acc = fmaf(lf[k], lw[k], acc);
            float ge = 0.5f * acc * (1.f + erff(acc * 0.70710678118654752f));
            d_feat[g * GENEF + 320 + j] = ge;
        }
    } else {
        int b = g - 2048;
        const float* pe = pert_emb + (size_t)pidx[b] * 128;
        for (int j = tid; j < GENEF; j += 128) {
            float acc = cond_b[j];
            const float* cw = cond_w + (size_t)j * 128;
            for (int k = 0; k < 128; k++) acc = fmaf(pe[k], cw[k], acc);
            d_feat[g * GENEF + j] = acc;
        }
    }
}

// ------------------------- 2. SGEMM 128x128 tile, 8x8/thread, f32x2 ----------
__global__ __launch_bounds__(256) void sgemm128(int src_sel,
                                                const float* __restrict__ W,
                                                const float* __restrict__ bias,
                                                int dst_sel, int M, int N, int K) {
    const float* A = (src_sel == 0) ? d_feat : d_X;
    float* C = (dst_sel == 0) ? d_X : d_Z[dst_sel - 1];

    __shared__ __align__(16) float2 As2[2][8][128];
    __shared__ __align__(16) float Ws[2][8][132];

    int tid = threadIdx.x;
    int row0 = blockIdx.y * 128, col0 = blockIdx.x * 128;
    int lr = tid >> 1;
    int lk = (tid & 1) * 4;
    bool aval = (row0 + lr) < M;
    bool wval = (col0 + lr) < N;
    const float* Aptr = A + (size_t)(row0 + lr) * K + lk;
    const float* Wptr = W + (size_t)(col0 + lr) * K + lk;

    float4 av = aval ? *(const float4*)Aptr : make_float4(0, 0, 0, 0);
    float4 wv = wval ? *(const float4*)Wptr : make_float4(0, 0, 0, 0);
    As2[0][lk + 0][lr] = make_float2(av.x, av.x);
    As2[0][lk + 1][lr] = make_float2(av.y, av.y);
    As2[0][lk + 2][lr] = make_float2(av.z, av.z);
    As2[0][lk + 3][lr] = make_float2(av.w, av.w);
    Ws[0][lk + 0][lr] = wv.x; Ws[0][lk + 1][lr] = wv.y;
    Ws[0][lk + 2][lr] = wv.z; Ws[0][lk + 3][lr] = wv.w;
    __syncthreads();

    unsigned long long acc2[8][4];
#pragma unroll
    for (int i = 0; i < 8; i++)
#pragma unroll
        for (int j = 0; j < 4; j++) acc2[i][j] = 0ull;

    int ty = tid >> 4, tx = tid & 15;

    for (int k0 = 0; k0 < K; k0 += 8) {
        int buf = (k0 >> 3) & 1;
        bool more = (k0 + 8) < K;
        if (more) {
            av = aval ? *(const float4*)(Aptr + k0 + 8) : make_float4(0, 0, 0, 0);
            wv = wval ? *(const float4*)(Wptr + k0 + 8) : make_float4(0, 0, 0, 0);
        }
#pragma unroll
        for (int kk = 0; kk < 8; kk++) {
            const ulonglong2* Ap = (const ulonglong2*)&As2[buf][kk][ty * 8];
            const ulonglong2* Bp0 = (const ulonglong2*)&Ws[buf][kk][tx * 4];
            const ulonglong2* Bp1 = (const ulonglong2*)&Ws[buf][kk][64 + tx * 4];
            ulonglong2 b0 = Bp0[0];
            ulonglong2 b1 = Bp1[0];
            ulonglong2 a01 = Ap[0], a23 = Ap[1], a45 = Ap[2], a67 = Ap[3];
            unsigned long long ra[8] = {a01.x, a01.y, a23.x, a23.y,
                                        a45.x, a45.y, a67.x, a67.y};
#pragma unroll
            for (int i = 0; i < 8; i++) {
                FMA2(acc2[i][0], ra[i], b0.x, acc2[i][0]);
                FMA2(acc2[i][1], ra[i], b0.y, acc2[i][1]);
                FMA2(acc2[i][2], ra[i], b1.x, acc2[i][2]);
                FMA2(acc2[i][3], ra[i], b1.y, acc2[i][3]);
            }
        }
        if (more) {
            int nb = buf ^ 1;
            As2[nb][lk + 0][lr] = make_float2(av.x, av.x);
            As2[nb][lk + 1][lr] = make_float2(av.y, av.y);
            As2[nb][lk + 2][lr] = make_float2(av.z, av.z);
            As2[nb][lk + 3][lr] = make_float2(av.w, av.w);
            Ws[nb][lk + 0][lr] = wv.x; Ws[nb][lk + 1][lr] = wv.y;
            Ws[nb][lk + 2][lr] = wv.z; Ws[nb][lk + 3][lr] = wv.w;
        }
        __syncthreads();
    }
#pragma unroll
    for (int i = 0; i < 8; i++) {
        int r = row0 + ty * 8 + i;
        if (r >= M) continue;
        float vals[8] = {lo2(acc2[i][0]), hi2(acc2[i][0]), lo2(acc2[i][1]), hi2(acc2[i][1]),
                         lo2(acc2[i][2]), hi2(acc2[i][2]), lo2(acc2[i][3]), hi2(acc2[i][3])};
#pragma unroll
        for (int j = 0; j < 8; j++) {
            int c = col0 + ((j < 4) ? (tx * 4 + j) : (64 + tx * 4 + (j - 4)));
            if (c < N) C[(size_t)r * N + c] = vals[j] + (bias ? bias[c] : 0.f);
        }
    }
}

// ------------------------- 3. causal depthwise conv + silu -------------------
__global__ void conv_kernel(const float* __restrict__ cw_f, const float* __restrict__ cb_f,
                            const float* __restrict__ cw_b, const float* __restrict__ cb_b) {
    int bx = blockIdx.x;
    int dir = blockIdx.y;
    const float* cw = dir ? cw_b : cw_f;
    const float* cb = dir ? cb_b : cb_f;
    const float* Z = d_Z[dir];

    const float* rows[4];
    float* dst;
    if (bx < L_SEQ) {
        int t = bx;
        if ((dir == 0 && t < 4) || (dir == 1 && t < 1)) return;
        dst = d_xBCs[dir] + (size_t)t * CONVD;
#pragma unroll
        for (int k = 0; k < 4; k++) {
            int tau = dir ? (t + 3 - k) : (t - 3 + k);
            rows[k] = (tau <= L_SEQ - 1) ? (Z + (size_t)(tau - 1) * DPROJ + DIN) : nullptr;
        }
    } else {
        if (dir == 1) return;
        int idx = bx - L_SEQ;
        int b = idx >> 2;
        int t = idx & 3;
        dst = d_xBC0 + (size_t)(b * 4 + t) * CONVD;
#pragma unroll
        for (int k = 0; k < 4; k++) {
            int tau = t - 3 + k;
            rows[k] = (tau >= 0) ? (Z + (size_t)seq_row(b, tau) * DPROJ + DIN) : nullptr;
        }
    }
    for (int c = threadIdx.x; c < CONVD; c += blockDim.x) {
        float acc = cb[c];
#pragma unroll
        for (int k = 0; k < 4; k++)
            if (rows[k]) acc = fmaf(rows[k][c], cw[c * 4 + k], acc);
        dst[c] = fast_silu(acc);
    }
}

// ------------------------- 4. dt / dA per row --------------------------------
__global__ void dtda_kernel(const float* __restrict__ fdtb, const float* __restrict__ fAl,
                            const float* __restrict__ bdtb, const float* __restrict__ bAl) {
    int idx = blockIdx.x * blockDim.x + threadIdx.x;
    const int per = NROWS * NH;
    if (idx >= 2 * per) return;
    int dir = idx / per;
    int r = idx % per;
    int row = r >> 4;
    int h = r & 15;
    float raw = d_Z[dir][(size_t)row * DPROJ + (DIN + CONVD) + h] + (dir ? bdtb : fdtb)[h];
    float dtv = (raw > 20.f) ? raw : log1pf(expf(raw));
    float Al = (dir ? bAl : fAl)[h];
    d_dtr[dir][row * NH + h] = dtv;
    d_dAr[dir][row * NH + h] = expf(-expf(Al) * dtv);
}

// ------------------------- 4b. fwd decay cumprod -----------------------------
__global__ void decay_kernel() {
    int h = threadIdx.x;
    if (h >= NH) return;
    float acc = 1.f;
    for (int t = 4; t <= 2048; t++) {
        acc *= d_dAr[0][(t - 1) * NH + h];
        d_decayf[h * TCOR + (t - 4)] = acc;
    }
}

// ------------------------- 4c. W4[b][h][tau] = dt_tau * prod_{s>tau} dA_s ----
__global__ void w4_kernel() {
    int idx = threadIdx.x;   // 512
    if (idx >= BATCH * NH * 4) return;
    int b = idx >> 6, h = (idx >> 2) & 15, tau = idx & 3;
    int row_tau = (tau == 0) ? (2048 + b) : (tau - 1);
    float w = d_dtr[0][row_tau * NH + h];
    for (int s = tau + 1; s < 4; s++)
        w *= d_dAr[0][(s - 1) * NH + h];   // rows s>=1 are gene rows (shared)
    d_W4[idx] = w;
}

// ------------------------- 4d. dotCB[t][b][tau] = C_t . B_tau ----------------
__global__ void dotcb_kernel() {
    int t = blockIdx.x + 4;       // 4..2048
    int tid = threadIdx.x;        // 128
    int combo = tid >> 2, k = tid & 3;
    int b = combo >> 2, tau = combo & 3;
    const float* C = d_xBCs[0] + (size_t)t * CONVD + DIN + NS;
    const float* B0 = d_xBC0 + (size_t)(b * 4 + tau) * CONVD + DIN;
    float acc = 0.f;
#pragma unroll
    for (int n = 0; n < 32; n++) acc = fmaf(C[k * 32 + n], B0[k * 32 + n], acc);
    acc += __shfl_down_sync(0xffffffffu, acc, 2);
    acc += __shfl_down_sync(0xffffffffu, acc, 1);
    if (k == 0) d_dotCB[t * 32 + b * 4 + tau] = acc;
}

// ------------------------- 5. combined output vector -------------------------
__global__ void wcomb_kernel(const float* __restrict__ head_w,
                             const float* __restrict__ fow, const float* __restrict__ bow,
                             const float* __restrict__ fnw, const float* __restrict__ bnw) {
    int idx = blockIdx.x * blockDim.x + threadIdx.x;
    if (idx >= 2 * DIN) return;
    int dir = idx >> 10;
    int j = idx & 1023;
    const float* ow = dir ? bow : fow;
    float acc = 0.f;
    for (int i = 0; i < DMODEL; i++) acc = fmaf(ow[(size_t)i * DIN + j], head_w[i], acc);
    d_wcomb[dir][j] = acc * (dir ? bnw : fnw)[j];
}

// ------------------------- 5b. silu(z) per gene row --------------------------
__global__ void siluz_kernel() {
    int row = blockIdx.x;
    int dir = blockIdx.y;
    const float* z = d_Z[dir] + (size_t)row * DPROJ;
    float* P = d_P[dir] + (size_t)row * DIN;
    for (int j = threadIdx.x; j < DIN; j += 256) P[j] = fast_silu(z[j]);
}

// ------------------------- 6a. fwd per-batch prefix scan (t=0..3) ------------
__global__ __launch_bounds__(128) void prefix_kernel(const float* __restrict__ fD) {
    int blk = blockIdx.x;
    int b = blk >> 4;
    int h = blk & 15;
    int tid = threadIdx.x;
    int p = tid & 63;
    int nh = tid >> 6;
    float Dh = fD[h];

    __shared__ __align__(16) float sB[128], sC[128], sx[64];

    unsigned long long hs2[32];
#pragma unroll
    for (int i = 0; i < 32; i++) hs2[i] = 0ull;

    for (int t = 0; t < 4; t++) {
        const float* pp = xbc_fwd_ptr(b, t);
        sB[tid] = pp[DIN + tid];
        sC[tid] = pp[DIN + NS + tid];
        if (tid < 64) sx[tid] = pp[h * HD + tid];
        __syncthreads();
        int row = (t == 0) ? (2048 + b) : (t - 1);
        float dtv = d_dtr[0][row * NH + h];
        float dAv = d_dAr[0][row * NH + h];
        float xv = sx[p];
        unsigned long long coef2 = pack2(dtv * xv);
        unsigned long long dA2 = pack2(dAv);
        const ulonglong2* B4 = (const ulonglong2*)(sB + nh * 64);
        const ulonglong2* C4 = (const ulonglong2*)(sC + nh * 64);
        unsigned long long a0 = 0ull, a1 = 0ull;
#pragma unroll
        for (int i = 0; i < 16; i++) {
            ulonglong2 bv = B4[i], cv = C4[i];
            unsigned long long tm;
            MUL2(tm, coef2, bv.x);
            FMA2(hs2[2 * i + 0], dA2, hs2[2 * i + 0], tm);
            FMA2(a0, hs2[2 * i + 0], cv.x, a0);
            MUL2(tm, coef2, bv.y);
            FMA2(hs2[2 * i + 1], dA2, hs2[2 * i + 1], tm);
            FMA2(a1, hs2[2 * i + 1], cv.y, a1);
        }
        ADD2(a0, a0, a1);
        float part = sum2(a0);
        if (nh == 0) part = fmaf(Dh, xv, part);
        if (t >= 1)
            d_ypre[((size_t)(b * 3 + (t - 1)) * 16 + h) * 128 + tid] = part;
        __syncthreads();
    }
}

// ------------------------- 6b. shared scans, chunked staging -----------------
// 256 blocks = (dir, h, n-eighth q). 128 threads = 4 warps (2 blocks/SM).
// warp w: p-lane = (w&1)*32 + lane; sub = w>>1 covers 8 states of the eighth.
__global__ __launch_bounds__(128) void scan_shared(const float* __restrict__ fD,
                                                   const float* __restrict__ bD) {
    int blk = blockIdx.x;          // 0..255
    int dir = blk >> 7;
    int rest = blk & 127;
    int h = rest >> 3;
    int q = rest & 7;
    int tid = threadIdx.x;
    int wid = tid >> 5;
    int lane = tid & 31;
    int p = (wid & 1) * 32 + lane;
    int sub = wid >> 1;            // 0/1: 8-state half of eighth
    int s16 = q * 2 + sub;         // global 16th index (0..15)
    float Dh = (dir ? bD : fD)[h];
    const float* xbc = d_xBCs[dir];
    const float* dtr = d_dtr[dir];
    const float* dAr = d_dAr[dir];
    float* ysp = d_ysp[dir];

    int S = dir ? 2048 : TCOR;

    __shared__ __align__(16) float sB[TC][16];
    __shared__ __align__(16) float sC[TC][16];
    __shared__ __align__(16) float sx[TC][64];
    __shared__ float sdt[TC], sdA[TC];

    unsigned long long hs2[4] = {0ull, 0ull, 0ull, 0ull};

    for (int s0 = 0; s0 < S; s0 += TC) {
        int cnt = (S - s0 < TC) ? (S - s0) : TC;
        __syncthreads();   // previous chunk fully consumed
        // stage B, C eighths (4 float4 per row each)
        for (int i = tid; i < cnt * 4; i += 128) {
            int j = i >> 2, cc = i & 3;
            int tt = dir ? (2048 - (s0 + j)) : (4 + s0 + j);
            const float* rowp = xbc + (size_t)tt * CONVD + DIN + q * 16;
            *(float4*)&sB[j][cc * 4] = ((const float4*)rowp)[cc];
            *(float4*)&sC[j][cc * 4] = ((const float4*)(rowp + NS))[cc];
        }
        // stage x (16 float4 per row)
        for (int i = tid; i < cnt * 16; i += 128) {
            int j = i >> 4, cc = i & 15;
            int tt = dir ? (2048 - (s0 + j)) : (4 + s0 + j);
            *(float4*)&sx[j][cc * 4] =
                ((const float4*)(xbc + (size_t)tt * CONVD + h * HD))[cc];
        }
        // stage dt / dA
        if (tid < cnt) {
            int tt = dir ? (2048 - (s0 + tid)) : (4 + s0 + tid);
            sdt[tid] = dtr[(tt - 1) * NH + h];
            sdA[tid] = dAr[(tt - 1) * NH + h];
        }
        __syncthreads();

        for (int j = 0; j < cnt; j++) {
            int tt = dir ? (2048 - (s0 + j)) : (4 + s0 + j);
            float xv = sx[j][p];
            unsigned long long coef2 = pack2(sdt[j] * xv);
            unsigned long long dA2 = pack2(sdA[j]);
            const ulonglong2* B4 = (const ulonglong2*)&sB[j][sub * 8];
            const ulonglong2* C4 = (const ulonglong2*)&sC[j][sub * 8];
            ulonglong2 bv0 = B4[0], cv0 = C4[0];
            ulonglong2 bv1 = B4[1], cv1 = C4[1];
            unsigned long long a0 = 0ull, a1 = 0ull, tm;
            MUL2(tm, coef2, bv0.x);
            FMA2(hs2[0], dA2, hs2[0], tm);
            FMA2(a0, hs2[0], cv0.x, a0);
            MUL2(tm, coef2, bv0.y);
            FMA2(hs2[1], dA2, hs2[1], tm);
            FMA2(a1, hs2[1], cv0.y, a1);
            MUL2(tm, coef2, bv1.x);
            FMA2(hs2[2], dA2, hs2[2], tm);
            FMA2(a0, hs2[2], cv1.x, a0);
            MUL2(tm, coef2, bv1.y);
            FMA2(hs2[3], dA2, hs2[3], tm);
            FMA2(a1, hs2[3], cv1.y, a1);
            ADD2(a0, a0, a1);
            float y = sum2(a0);
            if (s16 == 0) y = fmaf(Dh, xv, y);
            ysp[((size_t)tt * NH + h) * 1024 + s16 * 64 + p] = y;
        }
    }
}

// ------------------------- 6c. reduce n-partials -----------------------------
__global__ __launch_bounds__(256) void reduce_ys() {
    int t = blockIdx.x;       // 0..2048
    int dir = blockIdx.y;
    const float* src = d_ysp[dir] + (size_t)t * NH * 1024;
    float* dst = d_ysum[dir] + (size_t)t * NH * 64;
    for (int j = threadIdx.x; j < DIN; j += 256) {
        int h = j >> 6, p = j & 63;
        const float* sp = src + h * 1024 + p;
        float acc = 0.f;
#pragma unroll
        for (int k = 0; k < 16; k++) acc += sp[k * 64];
        dst[j] = acc;
    }
}

// ------------------------- 7. gate + RMSnorm + fused head --------------------
__global__ __launch_bounds__(256) void final_kernel(const float* __restrict__ head_b,
                                                    float* __restrict__ out) {
    int blk = blockIdx.x;       // 0..8*2048-1
    int b = blk >> 11;
    int t = (blk & 2047) + 1;
    int tid = threadIdx.x;      // 256
    __shared__ float sh[8][4];
    __shared__ float cco[64];   // per-(h,tau) correction coefficients

    const float* Pf = d_P[0] + (size_t)(t - 1) * DIN;
    const float* Pb = d_P[1] + (size_t)(t - 1) * DIN;
    const float* ysf = d_ysum[0] + (size_t)t * DIN;
    const float* ysb = d_ysum[1] + (size_t)t * DIN;
    const float* xb = d_xBC0 + (size_t)b * 4 * CONVD;   // x rows tau=0..3 (stride CONVD)

    if (t >= 4 && tid < 64) {
        int h = tid >> 2, tau = tid & 3;
        cco[tid] = d_decayf[h * TCOR + (t - 4)] * d_W4[(b * 16 + h) * 4 + tau] *
                   d_dotCB[t * 32 + b * 4 + tau];
    }
    __syncthreads();

    float ssqf = 0.f, sdotf = 0.f, ssqb = 0.f, sdotb = 0.f;
    for (int j = tid; j < DIN; j += 256) {
        float yb = ysb[j];
        float yf;
        int h = j >> 6;
        if (t >= 4) {
            const float* cc = &cco[h * 4];
            float corr = cc[0] * xb[j] + cc[1] * xb[CONVD + j] +
                         cc[2] * xb[2 * CONVD + j] + cc[3] * xb[3 * CONVD + j];
            yf = ysf[j] + corr;
        } else {
            int p = j & 63;
            const float* yp = d_ypre + ((size_t)(b * 3 + (t - 1)) * 16 + h) * 128;
            yf = yp[p] + yp[64 + p];
        }
        float gf = yf * Pf[j];
        ssqf = fmaf(gf, gf, ssqf);
        sdotf = fmaf(gf, d_wcomb[0][j], sdotf);
        float gb = yb * Pb[j];
        ssqb = fmaf(gb, gb, ssqb);
        sdotb = fmaf(gb, d_wcomb[1][j], sdotb);
    }
#pragma unroll
    for (int off = 16; off; off >>= 1) {
        ssqf += __shfl_xor_sync(0xffffffffu, ssqf, off);
        sdotf += __shfl_xor_sync(0xffffffffu, sdotf, off);
        ssqb += __shfl_xor_sync(0xffffffffu, ssqb, off);
        sdotb += __shfl_xor_sync(0xffffffffu, sdotb, off);
    }
    int w = tid >> 5, l = tid & 31;
    if (l == 0) { sh[w][0] = ssqf; sh[w][1] = sdotf; sh[w][2] = ssqb; sh[w][3] = sdotb; }
    __syncthreads();
    if (tid == 0) {
        float a0 = 0.f, a1 = 0.f, a2 = 0.f, a3 = 0.f;
        for (int i = 0; i < 8; i++) {
            a0 += sh[i][0]; a1 += sh[i][1]; a2 += sh[i][2]; a3 += sh[i][3];
        }
        float res = rsqrtf(a0 * (1.f / 1024.f) + 1e-5f) * a1 +
                    rsqrtf(a2 * (1.f / 1024.f) + 1e-5f) * a3;
        out[blk] = res + head_b[0];
    }
}

// ------------------------- launch --------------------------------------------
extern "C" void kernel_launch(void* const* d_in, const int* in_sizes, int n_in,
                              void* d_out, int out_size) {
    const int* pidx            = (const int*)d_in[0];
    const int* chridx          = (const int*)d_in[1];
    const float* locus_fourier = (const float*)d_in[2];
    const float* pathway       = (const float*)d_in[3];
    const float* pert_emb      = (const float*)d_in[4];
    const float* gene_id       = (const float*)d_in[5];
    const float* chr_emb       = (const float*)d_in[6];
    const float* locus_w       = (const float*)d_in[7];
    const float* locus_b       = (const float*)d_in[8];
    const float* cond_w        = (const float*)d_in[9];
    const float* cond_b        = (const float*)d_in[10];
    const float* in_w          = (const float*)d_in[11];
    const float* in_b          = (const float*)d_in[12];
    const float* head_w        = (const float*)d_in[13];
    const float* head_b        = (const float*)d_in[14];
    const float* f_in_w        = (const float*)d_in[15];
    const float* f_conv_w      = (const float*)d_in[16];
    const float* f_conv_b      = (const float*)d_in[17];
    const float* f_dt_bias     = (const float*)d_in[18];
    const float* f_A_log       = (const float*)d_in[19];
    const float* f_D           = (const float*)d_in[20];
    const float* f_norm_w      = (const float*)d_in[21];
    const float* f_out_w       = (const float*)d_in[22];
    const float* b_in_w        = (const float*)d_in[23];
    const float* b_conv_w      = (const float*)d_in[24];
    const float* b_conv_b      = (const float*)d_in[25];
    const float* b_dt_bias     = (const float*)d_in[26];
    const float* b_A_log       = (const float*)d_in[27];
    const float* b_D           = (const float*)d_in[28];
    const float* b_norm_w      = (const float*)d_in[29];
    const float* b_out_w       = (const float*)d_in[30];
    float* out = (float*)d_out;

    feat_kernel<<<NROWS, 128>>>(pidx, chridx, locus_fourier, pathway, pert_emb,
                                gene_id, chr_emb, locus_w, locus_b, cond_w, cond_b);

    sgemm128<<<dim3(4, 17), 256>>>(0, in_w, in_b, 0, NROWS, DMODEL, GENEF);
    sgemm128<<<dim3(19, 17), 256>>>(1, f_in_w, nullptr, 1, NROWS, DPROJ, DMODEL);
    sgemm128<<<dim3(19, 17), 256>>>(1, b_in_w, nullptr, 2, NROWS, DPROJ, DMODEL);

    conv_kernel<<<dim3(L_SEQ + 32, 2), 256>>>(f_conv_w, f_conv_b, b_conv_w, b_conv_b);

    dtda_kernel<<<(2 * NROWS * NH + 255) / 256, 256>>>(f_dt_bias, f_A_log, b_dt_bias, b_A_log);
    decay_kernel<<<1, 32>>>();
    w4_kernel<<<1, 512>>>();
    dotcb_kernel<<<TCOR, 128>>>();

    wcomb_kernel<<<(2 * DIN + 255) / 256, 256>>>(head_w, f_out_w, b_out_w, f_norm_w, b_norm_w);
    siluz_kernel<<<dim3(2048, 2), 256>>>();

    // fwd per-batch prefix (t=0..3) -> y(1..3)
    prefix_kernel<<<128, 128>>>(f_D);

    // shared scans with chunked staging (256 blocks, 2/SM)
    scan_shared<<<256, 128>>>(f_D, b_D);

    // reduce n-sixteenth partials
    reduce_ys<<<dim3(L_SEQ, 2), 256>>>();

    final_kernel<<<BATCH * 2048, 256>>>(head_b, out);
}

// round 8
// speedup vs baseline: 2.2635x; 1.2179x over previous
#include <cuda_runtime.h>
#include <cuda_bf16.h>
#include <math.h>

#define L_SEQ 2049
#define BATCH 8
#define NH 16
#define HD 64
#define NS 128
#define DIN 1024
#define CONVD 1280
#define DPROJ 2320
#define NROWS 2056
#define GENEF 384
#define DMODEL 512
#define TCOR 2045   // corrected timesteps t=4..2048
#define TC 32       // scan chunk length
#define SSTA 24     // hgemm shared stride (A), bf16 elems: conflict-free
#define SSTB 20     // hgemm shared stride (B), bf16 elems: <=2-way

// ------------------------- scratch (static device globals) -------------------
__device__ float d_feat[NROWS * GENEF];
__device__ float d_X[NROWS * DMODEL];
__device__ float d_Z[2][NROWS * DPROJ];
__device__ float d_xBCs[2][(size_t)L_SEQ * CONVD];   // batch-shared conv out
__device__ float d_xBC0[BATCH * 4 * CONVD];          // fwd per-batch conv out, t=0..3
__device__ float d_dtr[2][NROWS * NH];
__device__ float d_dAr[2][NROWS * NH];
__device__ float d_ysp[2][(size_t)L_SEQ * NH * 16 * 64]; // scan partials [t][h][s16][p]
__device__ float d_ysum[2][(size_t)L_SEQ * NH * 64];     // reduced shared-scan y
__device__ float d_ypre[BATCH * 3 * NH * 128];       // fwd per-batch y (t=1..3), halves
__device__ float d_decayf[NH * TCOR];                // cumprod dA fwd, t=4..2048
__device__ float d_dotCB[L_SEQ * 32];                // C_t . B_tau  [t][b][tau]
__device__ float d_W4[BATCH * NH * 4];               // dt_tau * prod dA  [b][h][tau]
__device__ float d_P[2][(size_t)2048 * DIN];         // silu(z) per gene row
__device__ float d_wcomb[2][DIN];
// split-bf16 operands for tensor-core Z-GEMMs
__device__ __nv_bfloat16 d_Xhi[NROWS * DMODEL];
__device__ __nv_bfloat16 d_Xlo[NROWS * DMODEL];
__device__ __nv_bfloat16 d_Whi[2][DPROJ * DMODEL];
__device__ __nv_bfloat16 d_Wlo[2][DPROJ * DMODEL];

__device__ __forceinline__ int seq_row(int b, int t) {
    return (t == 0) ? (2048 + b) : (t - 1);
}
__device__ __forceinline__ const float* xbc_fwd_ptr(int b, int t) {
    return (t >= 4) ? (d_xBCs[0] + (size_t)t * CONVD)
                    : (d_xBC0 + (size_t)(b * 4 + t) * CONVD);
}
__device__ __forceinline__ float fast_silu(float x) {
    return __fdividef(x, 1.f + __expf(-x));
}

// f32x2 packed math (sm_100+)
#define MUL2(d, a, b) asm("mul.rn.f32x2 %0,%1,%2;" : "=l"(d) : "l"(a), "l"(b))
#define FMA2(d, a, b, c) asm("fma.rn.f32x2 %0,%1,%2,%3;" : "=l"(d) : "l"(a), "l"(b), "l"(c))
#define ADD2(d, a, b) asm("add.rn.f32x2 %0,%1,%2;" : "=l"(d) : "l"(a), "l"(b))
__device__ __forceinline__ unsigned long long pack2(float x) {
    unsigned long long r;
    asm("mov.b64 %0,{%1,%1};" : "=l"(r) : "r"(__float_as_uint(x)));
    return r;
}
__device__ __forceinline__ float sum2(unsigned long long v) {
    unsigned int lo, hi;
    asm("mov.b64 {%0,%1},%2;" : "=r"(lo), "=r"(hi) : "l"(v));
    return __uint_as_float(lo) + __uint_as_float(hi);
}
__device__ __forceinline__ float lo2(unsigned long long v) {
    unsigned int lo;
    asm("mov.b64 {%0,_},%1;" : "=r"(lo) : "l"(v));
    return __uint_as_float(lo);
}
__device__ __forceinline__ float hi2(unsigned long long v) {
    unsigned int hi;
    asm("mov.b64 {_,%0},%1;" : "=r"(hi) : "l"(v));
    return __uint_as_float(hi);
}

// bf16 mma: D += A(m16k16) * B(n8k16)^T, f32 accum
#define MMA_BF16(cc, aa, bb) \
    asm volatile("mma.sync.aligned.m16n8k16.row.col.f32.bf16.bf16.f32 " \
        "{%0,%1,%2,%3}, {%4,%5,%6,%7}, {%8,%9}, {%0,%1,%2,%3};" \
        : "+f"((cc)[0]), "+f"((cc)[1]), "+f"((cc)[2]), "+f"((cc)[3]) \
        : "r"((aa)[0]), "r"((aa)[1]), "r"((aa)[2]), "r"((aa)[3]), \
          "r"((bb)[0]), "r"((bb)[1]))

// ------------------------- 1. feature rows -----------------------------------
__global__ void feat_kernel(const int* __restrict__ pidx,
                            const int* __restrict__ chridx,
                            const float* __restrict__ locus_fourier,
                            const float* __restrict__ pathway,
                            const float* __restrict__ pert_emb,
                            const float* __restrict__ gene_id,
                            const float* __restrict__ chr_emb,
                            const float* __restrict__ locus_w,
                            const float* __restrict__ locus_b,
                            const float* __restrict__ cond_w,
                            const float* __restrict__ cond_b) {
    int g = blockIdx.x;
    int tid = threadIdx.x;  // 128
    if (g < 2048) {
        d_feat[g * GENEF + tid] = gene_id[g * 128 + tid];
        d_feat[g * GENEF + 128 + tid] = pathway[g * 128 + tid];
        if (tid < 64) {
            int ci = chridx[g];
            d_feat[g * GENEF + 256 + tid] = chr_emb[ci * 64 + tid];
        } else {
            int j = tid - 64;
            float acc = locus_b[j];
            const float* lf = locus_fourier + g * 64;
            const float* lw = locus_w + j * 64;
            for (int k = 0; k < 64; k++) acc = fmaf(lf[k], lw[k], acc);
            float ge = 0.5f * acc * (1.f + erff(acc * 0.70710678118654752f));
            d_feat[g * GENEF + 320 + j] = ge;
        }
    } else {
        int b = g - 2048;
        const float* pe = pert_emb + (size_t)pidx[b] * 128;
        for (int j = tid; j < GENEF; j += 128) {
            float acc = cond_b[j];
            const float* cw = cond_w + (size_t)j * 128;
            for (int k = 0; k < 128; k++) acc = fmaf(pe[k], cw[k], acc);
            d_feat[g * GENEF + j] = acc;
        }
    }
}

// ------------------------- 2. SGEMM (f32, used for X only) -------------------
__global__ __launch_bounds__(256) void sgemm128(int src_sel,
                                                const float* __restrict__ W,
                                                const float* __restrict__ bias,
                                                int dst_sel, int M, int N, int K) {
    const float* A = (src_sel == 0) ? d_feat : d_X;
    float* C = (dst_sel == 0) ? d_X : d_Z[dst_sel - 1];

    __shared__ __align__(16) float2 As2[2][8][128];
    __shared__ __align__(16) float Ws[2][8][132];

    int tid = threadIdx.x;
    int row0 = blockIdx.y * 128, col0 = blockIdx.x * 128;
    int lr = tid >> 1;
    int lk = (tid & 1) * 4;
    bool aval = (row0 + lr) < M;
    bool wval = (col0 + lr) < N;
    const float* Aptr = A + (size_t)(row0 + lr) * K + lk;
    const float* Wptr = W + (size_t)(col0 + lr) * K + lk;

    float4 av = aval ? *(const float4*)Aptr : make_float4(0, 0, 0, 0);
    float4 wv = wval ? *(const float4*)Wptr : make_float4(0, 0, 0, 0);
    As2[0][lk + 0][lr] = make_float2(av.x, av.x);
    As2[0][lk + 1][lr] = make_float2(av.y, av.y);
    As2[0][lk + 2][lr] = make_float2(av.z, av.z);
    As2[0][lk + 3][lr] = make_float2(av.w, av.w);
    Ws[0][lk + 0][lr] = wv.x; Ws[0][lk + 1][lr] = wv.y;
    Ws[0][lk + 2][lr] = wv.z; Ws[0][lk + 3][lr] = wv.w;
    __syncthreads();

    unsigned long long acc2[8][4];
#pragma unroll
    for (int i = 0; i < 8; i++)
#pragma unroll
        for (int j = 0; j < 4; j++) acc2[i][j] = 0ull;

    int ty = tid >> 4, tx = tid & 15;

    for (int k0 = 0; k0 < K; k0 += 8) {
        int buf = (k0 >> 3) & 1;
        bool more = (k0 + 8) < K;
        if (more) {
            av = aval ? *(const float4*)(Aptr + k0 + 8) : make_float4(0, 0, 0, 0);
            wv = wval ? *(const float4*)(Wptr + k0 + 8) : make_float4(0, 0, 0, 0);
        }
#pragma unroll
        for (int kk = 0; kk < 8; kk++) {
            const ulonglong2* Ap = (const ulonglong2*)&As2[buf][kk][ty * 8];
            const ulonglong2* Bp0 = (const ulonglong2*)&Ws[buf][kk][tx * 4];
            const ulonglong2* Bp1 = (const ulonglong2*)&Ws[buf][kk][64 + tx * 4];
            ulonglong2 b0 = Bp0[0];
            ulonglong2 b1 = Bp1[0];
            ulonglong2 a01 = Ap[0], a23 = Ap[1], a45 = Ap[2], a67 = Ap[3];
            unsigned long long ra[8] = {a01.x, a01.y, a23.x, a23.y,
                                        a45.x, a45.y, a67.x, a67.y};
#pragma unroll
            for (int i = 0; i < 8; i++) {
                FMA2(acc2[i][0], ra[i], b0.x, acc2[i][0]);
                FMA2(acc2[i][1], ra[i], b0.y, acc2[i][1]);
                FMA2(acc2[i][2], ra[i], b1.x, acc2[i][2]);
                FMA2(acc2[i][3], ra[i], b1.y, acc2[i][3]);
            }
        }
        if (more) {
            int nb = buf ^ 1;
            As2[nb][lk + 0][lr] = make_float2(av.x, av.x);
            As2[nb][lk + 1][lr] = make_float2(av.y, av.y);
            As2[nb][lk + 2][lr] = make_float2(av.z, av.z);
            As2[nb][lk + 3][lr] = make_float2(av.w, av.w);
            Ws[nb][lk + 0][lr] = wv.x; Ws[nb][lk + 1][lr] = wv.y;
            Ws[nb][lk + 2][lr] = wv.z; Ws[nb][lk + 3][lr] = wv.w;
        }
        __syncthreads();
    }
#pragma unroll
    for (int i = 0; i < 8; i++) {
        int r = row0 + ty * 8 + i;
        if (r >= M) continue;
        float vals[8] = {lo2(acc2[i][0]), hi2(acc2[i][0]), lo2(acc2[i][1]), hi2(acc2[i][1]),
                         lo2(acc2[i][2]), hi2(acc2[i][2]), lo2(acc2[i][3]), hi2(acc2[i][3])};
#pragma unroll
        for (int j = 0; j < 8; j++) {
            int c = col0 + ((j < 4) ? (tx * 4 + j) : (64 + tx * 4 + (j - 4)));
            if (c < N) C[(size_t)r * N + c] = vals[j] + (bias ? bias[c] : 0.f);
        }
    }
}

// ------------------------- 2b. split-bf16 conversions ------------------------
__global__ void cvt_x() {
    int i = blockIdx.x * 256 + threadIdx.x;
    if (i >= NROWS * DMODEL) return;
    float v = d_X[i];
    __nv_bfloat16 h = __float2bfloat16(v);
    d_Xhi[i] = h;
    d_Xlo[i] = __float2bfloat16(v - __bfloat162float(h));
}
__global__ void cvt_w(const float* __restrict__ fw, const float* __restrict__ bw) {
    int i = blockIdx.x * 256 + threadIdx.x;
    if (i >= DPROJ * DMODEL) return;
    float v = fw[i];
    __nv_bfloat16 h = __float2bfloat16(v);
    d_Whi[0][i] = h;
    d_Wlo[0][i] = __float2bfloat16(v - __bfloat162float(h));
    v = bw[i];
    h = __float2bfloat16(v);
    d_Whi[1][i] = h;
    d_Wlo[1][i] = __float2bfloat16(v - __bfloat162float(h));
}

// ------------------------- 2c. tensor-core Z-GEMM ----------------------------
// C[r][c] = sum_k X[r][k] * W[c][k], split bf16: XhiWhi + XhiWlo + XloWhi.
// 128x128 tile, BK=16 double-buffered, 8 warps of 32x64.
__global__ __launch_bounds__(256) void hgemm(int dir) {
    const __nv_bfloat16* Wh = d_Whi[dir];
    const __nv_bfloat16* Wl = d_Wlo[dir];
    float* C = d_Z[dir];

    __shared__ __align__(16) __nv_bfloat16 sA[2][2][128 * SSTA];
    __shared__ __align__(16) __nv_bfloat16 sB[2][2][128 * SSTB];

    int tid = threadIdx.x;
    int row0 = blockIdx.y * 128;
    int col0 = blockIdx.x * 128;
    int lrow = tid >> 1;      // 0..127
    int seg = tid & 1;        // 8-elem (16B) segment within 16-elem chunk row

    int arow = row0 + lrow;
    int brow = col0 + lrow;
    bool aval = arow < NROWS;
    bool bval = brow < DPROJ;
    const uint4 z4 = make_uint4(0, 0, 0, 0);

    size_t abase = (size_t)arow * DMODEL + seg * 8;
    size_t bbase = (size_t)brow * DMODEL + seg * 8;

    uint4 rAh, rAl, rBh, rBl;
    // prologue: chunk 0
    rAh = aval ? *(const uint4*)(d_Xhi + abase) : z4;
    rAl = aval ? *(const uint4*)(d_Xlo + abase) : z4;
    rBh = bval ? *(const uint4*)(Wh + bbase) : z4;
    rBl = bval ? *(const uint4*)(Wl + bbase) : z4;
    {
        // A: 16B-aligned rows (SSTA*2=48B)
        *(uint4*)&sA[0][0][lrow * SSTA + seg * 8] = rAh;
        *(uint4*)&sA[0][1][lrow * SSTA + seg * 8] = rAl;
        // B: 8B-aligned rows (SSTB*2=40B)
        char* db = (char*)&sB[0][0][0] + lrow * (SSTB * 2) + seg * 16;
        *(uint2*)db = make_uint2(rBh.x, rBh.y);
        *(uint2*)(db + 8) = make_uint2(rBh.z, rBh.w);
        char* dl = (char*)&sB[0][1][0] + lrow * (SSTB * 2) + seg * 16;
        *(uint2*)dl = make_uint2(rBl.x, rBl.y);
        *(uint2*)(dl + 8) = make_uint2(rBl.z, rBl.w);
    }
    __syncthreads();

    int w = tid >> 5, l = tid & 31;
    int mw = w >> 1, nw = w & 1;
    int g = l >> 2, q = l & 3;

    float c[2][8][4];
#pragma unroll
    for (int mt = 0; mt < 2; mt++)
#pragma unroll
        for (int nt = 0; nt < 8; nt++)
#pragma unroll
            for (int i = 0; i < 4; i++) c[mt][nt][i] = 0.f;

    const int NCH = DMODEL / 16;   // 32 chunks
    for (int kc = 0; kc < NCH; kc++) {
        int buf = kc & 1;
        bool more = (kc + 1) < NCH;
        if (more) {
            size_t ao = abase + (size_t)(kc + 1) * 16;
            size_t bo = bbase + (size_t)(kc + 1) * 16;
            rAh = aval ? *(const uint4*)(d_Xhi + ao) : z4;
            rAl = aval ? *(const uint4*)(d_Xlo + ao) : z4;
            rBh = bval ? *(const uint4*)(Wh + bo) : z4;
            rBl = bval ? *(const uint4*)(Wl + bo) : z4;
        }

        // load fragments
        unsigned a[2][2][4], b[8][2][2];
#pragma unroll
        for (int mt = 0; mt < 2; mt++) {
            int r = mw * 32 + mt * 16 + g;
#pragma unroll
            for (int v = 0; v < 2; v++) {
                const __nv_bfloat16* base = sA[buf][v];
                a[mt][v][0] = *(const unsigned*)&base[r * SSTA + q * 2];
                a[mt][v][1] = *(const unsigned*)&base[(r + 8) * SSTA + q * 2];
                a[mt][v][2] = *(const unsigned*)&base[r * SSTA + q * 2 + 8];
                a[mt][v][3] = *(const unsigned*)&base[(r + 8) * SSTA + q * 2 + 8];
            }
        }
#pragma unroll
        for (int nt = 0; nt < 8; nt++) {
            int n = nw * 64 + nt * 8 + g;
#pragma unroll
            for (int v = 0; v < 2; v++) {
                const __nv_bfloat16* base = sB[buf][v];
                b[nt][v][0] = *(const unsigned*)&base[n * SSTB + q * 2];
                b[nt][v][1] = *(const unsigned*)&base[n * SSTB + q * 2 + 8];
            }
        }
#pragma unroll
        for (int mt = 0; mt < 2; mt++)
#pragma unroll
            for (int nt = 0; nt < 8; nt++) {
                MMA_BF16(c[mt][nt], a[mt][0], b[nt][0]);   // hi*hi
                MMA_BF16(c[mt][nt], a[mt][0], b[nt][1]);   // hi*lo
                MMA_BF16(c[mt][nt], a[mt][1], b[nt][0]);   // lo*hi
            }

        if (more) {
            int nb = buf ^ 1;
            *(uint4*)&sA[nb][0][lrow * SSTA + seg * 8] = rAh;
            *(uint4*)&sA[nb][1][lrow * SSTA + seg * 8] = rAl;
            char* db = (char*)&sB[nb][0][0] + lrow * (SSTB * 2) + seg * 16;
            *(uint2*)db = make_uint2(rBh.x, rBh.y);
            *(uint2*)(db + 8) = make_uint2(rBh.z, rBh.w);
            char* dl = (char*)&sB[nb][1][0] + lrow * (SSTB * 2) + seg * 16;
            *(uint2*)dl = make_uint2(rBl.x, rBl.y);
            *(uint2*)(dl + 8) = make_uint2(rBl.z, rBl.w);
        }
        __syncthreads();
    }

    // epilogue
#pragma unroll
    for (int mt = 0; mt < 2; mt++) {
        int r0 = row0 + mw * 32 + mt * 16 + g;
#pragma unroll
        for (int nt = 0; nt < 8; nt++) {
            int cc = col0 + nw * 64 + nt * 8 + q * 2;
            if (cc < DPROJ) {
                if (r0 < NROWS)
                    *(float2*)&C[(size_t)r0 * DPROJ + cc] =
                        make_float2(c[mt][nt][0], c[mt][nt][1]);
                if (r0 + 8 < NROWS)
                    *(float2*)&C[(size_t)(r0 + 8) * DPROJ + cc] =
                        make_float2(c[mt][nt][2], c[mt][nt][3]);
            }
        }
    }
}

// ------------------------- 3. causal depthwise conv + silu -------------------
__global__ void conv_kernel(const float* __restrict__ cw_f, const float* __restrict__ cb_f,
                            const float* __restrict__ cw_b, const float* __restrict__ cb_b) {
    int bx = blockIdx.x;
    int dir = blockIdx.y;
    const float* cw = dir ? cw_b : cw_f;
    const float* cb = dir ? cb_b : cb_f;
    const float* Z = d_Z[dir];

    const float* rows[4];
    float* dst;
    if (bx < L_SEQ) {
        int t = bx;
        if ((dir == 0 && t < 4) || (dir == 1 && t < 1)) return;
        dst = d_xBCs[dir] + (size_t)t * CONVD;
#pragma unroll
        for (int k = 0; k < 4; k++) {
            int tau = dir ? (t + 3 - k) : (t - 3 + k);
            rows[k] = (tau <= L_SEQ - 1) ? (Z + (size_t)(tau - 1) * DPROJ + DIN) : nullptr;
        }
    } else {
        if (dir == 1) return;
        int idx = bx - L_SEQ;
        int b = idx >> 2;
        int t = idx & 3;
        dst = d_xBC0 + (size_t)(b * 4 + t) * CONVD;
#pragma unroll
        for (int k = 0; k < 4; k++) {
            int tau = t - 3 + k;
            rows[k] = (tau >= 0) ? (Z + (size_t)seq_row(b, tau) * DPROJ + DIN) : nullptr;
        }
    }
    for (int c = threadIdx.x; c < CONVD; c += blockDim.x) {
        float acc = cb[c];
#pragma unroll
        for (int k = 0; k < 4; k++)
            if (rows[k]) acc = fmaf(rows[k][c], cw[c * 4 + k], acc);
        dst[c] = fast_silu(acc);
    }
}

// ------------------------- 4. dt / dA per row --------------------------------
__global__ void dtda_kernel(const float* __restrict__ fdtb, const float* __restrict__ fAl,
                            const float* __restrict__ bdtb, const float* __restrict__ bAl) {
    int idx = blockIdx.x * blockDim.x + threadIdx.x;
    const int per = NROWS * NH;
    if (idx >= 2 * per) return;
    int dir = idx / per;
    int r = idx % per;
    int row = r >> 4;
    int h = r & 15;
    float raw = d_Z[dir][(size_t)row * DPROJ + (DIN + CONVD) + h] + (dir ? bdtb : fdtb)[h];
    float dtv = (raw > 20.f) ? raw : log1pf(expf(raw));
    float Al = (dir ? bAl : fAl)[h];
    d_dtr[dir][row * NH + h] = dtv;
    d_dAr[dir][row * NH + h] = expf(-expf(Al) * dtv);
}

// ------------------------- 4b. fwd decay cumprod -----------------------------
__global__ void decay_kernel() {
    int h = threadIdx.x;
    if (h >= NH) return;
    float acc = 1.f;
    for (int t = 4; t <= 2048; t++) {
        acc *= d_dAr[0][(t - 1) * NH + h];
        d_decayf[h * TCOR + (t - 4)] = acc;
    }
}

// ------------------------- 4c. W4[b][h][tau] = dt_tau * prod_{s>tau} dA_s ----
__global__ void w4_kernel() {
    int idx = threadIdx.x;   // 512
    if (idx >= BATCH * NH * 4) return;
    int b = idx >> 6, h = (idx >> 2) & 15, tau = idx & 3;
    int row_tau = (tau == 0) ? (2048 + b) : (tau - 1);
    float w = d_dtr[0][row_tau * NH + h];
    for (int s = tau + 1; s < 4; s++)
        w *= d_dAr[0][(s - 1) * NH + h];
    d_W4[idx] = w;
}

// ------------------------- 4d. dotCB[t][b][tau] = C_t . B_tau ----------------
// warp-per-combo, coalesced loads, shfl reduce
__global__ void dotcb_kernel() {
    int t = blockIdx.x + 4;       // 4..2048
    __shared__ float sC[128];
    int tid = threadIdx.x;        // 256 = 8 warps
    if (tid < 128) sC[tid] = d_xBCs[0][(size_t)t * CONVD + DIN + NS + tid];
    __syncthreads();
    int w = tid >> 5, l = tid & 31;
    for (int c = w; c < 32; c += 8) {
        const float* B0 = d_xBC0 + (size_t)c * CONVD + DIN;
        float acc = 0.f;
#pragma unroll
        for (int i = 0; i < 4; i++) acc = fmaf(B0[i * 32 + l], sC[i * 32 + l], acc);
#pragma unroll
        for (int off = 16; off; off >>= 1)
            acc += __shfl_xor_sync(0xffffffffu, acc, off);
        if (l == 0) d_dotCB[t * 32 + c] = acc;
    }
}

// ------------------------- 5. combined output vector -------------------------
__global__ void wcomb_kernel(const float* __restrict__ head_w,
                             const float* __restrict__ fow, const float* __restrict__ bow,
                             const float* __restrict__ fnw, const float* __restrict__ bnw) {
    int idx = blockIdx.x * blockDim.x + threadIdx.x;
    if (idx >= 2 * DIN) return;
    int dir = idx >> 10;
    int j = idx & 1023;
    const float* ow = dir ? bow : fow;
    float acc = 0.f;
    for (int i = 0; i < DMODEL; i++) acc = fmaf(ow[(size_t)i * DIN + j], head_w[i], acc);
    d_wcomb[dir][j] = acc * (dir ? bnw : fnw)[j];
}

// ------------------------- 5b. silu(z) per gene row --------------------------
__global__ void siluz_kernel() {
    int row = blockIdx.x;
    int dir = blockIdx.y;
    const float* z = d_Z[dir] + (size_t)row * DPROJ;
    float* P = d_P[dir] + (size_t)row * DIN;
    for (int j = threadIdx.x; j < DIN; j += 256) P[j] = fast_silu(z[j]);
}

// ------------------------- 6a. fwd per-batch prefix scan (t=0..3) ------------
__global__ __launch_bounds__(128) void prefix_kernel(const float* __restrict__ fD) {
    int blk = blockIdx.x;
    int b = blk >> 4;
    int h = blk & 15;
    int tid = threadIdx.x;
    int p = tid & 63;
    int nh = tid >> 6;
    float Dh = fD[h];

    __shared__ __align__(16) float sB[128], sC[128], sx[64];

    unsigned long long hs2[32];
#pragma unroll
    for (int i = 0; i < 32; i++) hs2[i] = 0ull;

    for (int t = 0; t < 4; t++) {
        const float* pp = xbc_fwd_ptr(b, t);
        sB[tid] = pp[DIN + tid];
        sC[tid] = pp[DIN + NS + tid];
        if (tid < 64) sx[tid] = pp[h * HD + tid];
        __syncthreads();
        int row = (t == 0) ? (2048 + b) : (t - 1);
        float dtv = d_dtr[0][row * NH + h];
        float dAv = d_dAr[0][row * NH + h];
        float xv = sx[p];
        unsigned long long coef2 = pack2(dtv * xv);
        unsigned long long dA2 = pack2(dAv);
        const ulonglong2* B4 = (const ulonglong2*)(sB + nh * 64);
        const ulonglong2* C4 = (const ulonglong2*)(sC + nh * 64);
        unsigned long long a0 = 0ull, a1 = 0ull;
#pragma unroll
        for (int i = 0; i < 16; i++) {
            ulonglong2 bv = B4[i], cv = C4[i];
            unsigned long long tm;
            MUL2(tm, coef2, bv.x);
            FMA2(hs2[2 * i + 0], dA2, hs2[2 * i + 0], tm);
            FMA2(a0, hs2[2 * i + 0], cv.x, a0);
            MUL2(tm, coef2, bv.y);
            FMA2(hs2[2 * i + 1], dA2, hs2[2 * i + 1], tm);
            FMA2(a1, hs2[2 * i + 1], cv.y, a1);
        }
        ADD2(a0, a0, a1);
        float part = sum2(a0);
        if (nh == 0) part = fmaf(Dh, xv, part);
        if (t >= 1)
            d_ypre[((size_t)(b * 3 + (t - 1)) * 16 + h) * 128 + tid] = part;
        __syncthreads();
    }
}

// ------------------------- 6b. shared scans, chunked staging -----------------
__global__ __launch_bounds__(128) void scan_shared(const float* __restrict__ fD,
                                                   const float* __restrict__ bD) {
    int blk = blockIdx.x;          // 0..255
    int dir = blk >> 7;
    int rest = blk & 127;
    int h = rest >> 3;
    int q = rest & 7;
    int tid = threadIdx.x;
    int wid = tid >> 5;
    int lane = tid & 31;
    int p = (wid & 1) * 32 + lane;
    int sub = wid >> 1;
    int s16 = q * 2 + sub;
    float Dh = (dir ? bD : fD)[h];
    const float* xbc = d_xBCs[dir];
    const float* dtr = d_dtr[dir];
    const float* dAr = d_dAr[dir];
    float* ysp = d_ysp[dir];

    int S = dir ? 2048 : TCOR;

    __shared__ __align__(16) float sB[TC][16];
    __shared__ __align__(16) float sC[TC][16];
    __shared__ __align__(16) float sx[TC][64];
    __shared__ float sdt[TC], sdA[TC];

    unsigned long long hs2[4] = {0ull, 0ull, 0ull, 0ull};

    for (int s0 = 0; s0 < S; s0 += TC) {
        int cnt = (S - s0 < TC) ? (S - s0) : TC;
        __syncthreads();
        for (int i = tid; i < cnt * 4; i += 128) {
            int j = i >> 2, cc = i & 3;
            int tt = dir ? (2048 - (s0 + j)) : (4 + s0 + j);
            const float* rowp = xbc + (size_t)tt * CONVD + DIN + q * 16;
            *(float4*)&sB[j][cc * 4] = ((const float4*)rowp)[cc];
            *(float4*)&sC[j][cc * 4] = ((const float4*)(rowp + NS))[cc];
        }
        for (int i = tid; i < cnt * 16; i += 128) {
            int j = i >> 4, cc = i & 15;
            int tt = dir ? (2048 - (s0 + j)) : (4 + s0 + j);
            *(float4*)&sx[j][cc * 4] =
                ((const float4*)(xbc + (size_t)tt * CONVD + h * HD))[cc];
        }
        if (tid < cnt) {
            int tt = dir ? (2048 - (s0 + tid)) : (4 + s0 + tid);
            sdt[tid] = dtr[(tt - 1) * NH + h];
            sdA[tid] = dAr[(tt - 1) * NH + h];
        }
        __syncthreads();

        for (int j = 0; j < cnt; j++) {
            int tt = dir ? (2048 - (s0 + j)) : (4 + s0 + j);
            float xv = sx[j][p];
            unsigned long long coef2 = pack2(sdt[j] * xv);
            unsigned long long dA2 = pack2(sdA[j]);
            const ulonglong2* B4 = (const ulonglong2*)&sB[j][sub * 8];
            const ulonglong2* C4 = (const ulonglong2*)&sC[j][sub * 8];
            ulonglong2 bv0 = B4[0], cv0 = C4[0];
            ulonglong2 bv1 = B4[1], cv1 = C4[1];
            unsigned long long a0 = 0ull, a1 = 0ull, tm;
            MUL2(tm, coef2, bv0.x);
            FMA2(hs2[0], dA2, hs2[0], tm);
            FMA2(a0, hs2[0], cv0.x, a0);
            MUL2(tm, coef2, bv0.y);
            FMA2(hs2[1], dA2, hs2[1], tm);
            FMA2(a1, hs2[1], cv0.y, a1);
            MUL2(tm, coef2, bv1.x);
            FMA2(hs2[2], dA2, hs2[2], tm);
            FMA2(a0, hs2[2], cv1.x, a0);
            MUL2(tm, coef2, bv1.y);
            FMA2(hs2[3], dA2, hs2[3], tm);
            FMA2(a1, hs2[3], cv1.y, a1);
            ADD2(a0, a0, a1);
            float y = sum2(a0);
            if (s16 == 0) y = fmaf(Dh, xv, y);
            ysp[((size_t)tt * NH + h) * 1024 + s16 * 64 + p] = y;
        }
    }
}

// ------------------------- 6c. reduce n-partials -----------------------------
__global__ __launch_bounds__(256) void reduce_ys() {
    int t = blockIdx.x;
    int dir = blockIdx.y;
    const float* src = d_ysp[dir] + (size_t)t * NH * 1024;
    float* dst = d_ysum[dir] + (size_t)t * NH * 64;
    for (int j = threadIdx.x; j < DIN; j += 256) {
        int h = j >> 6, p = j & 63;
        const float* sp = src + h * 1024 + p;
        float acc = 0.f;
#pragma unroll
        for (int k = 0; k < 16; k++) acc += sp[k * 64];
        dst[j] = acc;
    }
}

// ------------------------- 7. gate + RMSnorm + fused head --------------------
__global__ __launch_bounds__(256) void final_kernel(const float* __restrict__ head_b,
                                                    float* __restrict__ out) {
    int blk = blockIdx.x;
    int b = blk >> 11;
    int t = (blk & 2047) + 1;
    int tid = threadIdx.x;
    __shared__ float sh[8][4];
    __shared__ float cco[64];

    const float* Pf = d_P[0] + (size_t)(t - 1) * DIN;
    const float* Pb = d_P[1] + (size_t)(t - 1) * DIN;
    const float* ysf = d_ysum[0] + (size_t)t * DIN;
    const float* ysb = d_ysum[1] + (size_t)t * DIN;
    const float* xb = d_xBC0 + (size_t)b * 4 * CONVD;

    if (t >= 4 && tid < 64) {
        int h = tid >> 2, tau = tid & 3;
        cco[tid] = d_decayf[h * TCOR + (t - 4)] * d_W4[(b * 16 + h) * 4 + tau] *
                   d_dotCB[t * 32 + b * 4 + tau];
    }
    __syncthreads();

    float ssqf = 0.f, sdotf = 0.f, ssqb = 0.f, sdotb = 0.f;
    for (int j = tid; j < DIN; j += 256) {
        float yb = ysb[j];
        float yf;
        int h = j >> 6;
        if (t >= 4) {
            const float* cc = &cco[h * 4];
            float corr = cc[0] * xb[j] + cc[1] * xb[CONVD + j] +
                         cc[2] * xb[2 * CONVD + j] + cc[3] * xb[3 * CONVD + j];
            yf = ysf[j] + corr;
        } else {
            int p = j & 63;
            const float* yp = d_ypre + ((size_t)(b * 3 + (t - 1)) * 16 + h) * 128;
            yf = yp[p] + yp[64 + p];
        }
        float gf = yf * Pf[j];
        ssqf = fmaf(gf, gf, ssqf);
        sdotf = fmaf(gf, d_wcomb[0][j], sdotf);
        float gb = yb * Pb[j];
        ssqb = fmaf(gb, gb, ssqb);
        sdotb = fmaf(gb, d_wcomb[1][j], sdotb);
    }
#pragma unroll
    for (int off = 16; off; off >>= 1) {
        ssqf += __shfl_xor_sync(0xffffffffu, ssqf, off);
        sdotf += __shfl_xor_sync(0xffffffffu, sdotf, off);
        ssqb += __shfl_xor_sync(0xffffffffu, ssqb, off);
        sdotb += __shfl_xor_sync(0xffffffffu, sdotb, off);
    }
    int w = tid >> 5, l = tid & 31;
    if (l == 0) { sh[w][0] = ssqf; sh[w][1] = sdotf; sh[w][2] = ssqb; sh[w][3] = sdotb; }
    __syncthreads();
    if (tid == 0) {
        float a0 = 0.f, a1 = 0.f, a2 = 0.f, a3 = 0.f;
        for (int i = 0; i < 8; i++) {
            a0 += sh[i][0]; a1 += sh[i][1]; a2 += sh[i][2]; a3 += sh[i][3];
        }
        float res = rsqrtf(a0 * (1.f / 1024.f) + 1e-5f) * a1 +
                    rsqrtf(a2 * (1.f / 1024.f) + 1e-5f) * a3;
        out[blk] = res + head_b[0];
    }
}

// ------------------------- launch --------------------------------------------
extern "C" void kernel_launch(void* const* d_in, const int* in_sizes, int n_in,
                              void* d_out, int out_size) {
    const int* pidx            = (const int*)d_in[0];
    const int* chridx          = (const int*)d_in[1];
    const float* locus_fourier = (const float*)d_in[2];
    const float* pathway       = (const float*)d_in[3];
    const float* pert_emb      = (const float*)d_in[4];
    const float* gene_id       = (const float*)d_in[5];
    const float* chr_emb       = (const float*)d_in[6];
    const float* locus_w       = (const float*)d_in[7];
    const float* locus_b       = (const float*)d_in[8];
    const float* cond_w        = (const float*)d_in[9];
    const float* cond_b        = (const float*)d_in[10];
    const float* in_w          = (const float*)d_in[11];
    const float* in_b          = (const float*)d_in[12];
    const float* head_w        = (const float*)d_in[13];
    const float* head_b        = (const float*)d_in[14];
    const float* f_in_w        = (const float*)d_in[15];
    const float* f_conv_w      = (const float*)d_in[16];
    const float* f_conv_b      = (const float*)d_in[17];
    const float* f_dt_bias     = (const float*)d_in[18];
    const float* f_A_log       = (const float*)d_in[19];
    const float* f_D           = (const float*)d_in[20];
    const float* f_norm_w      = (const float*)d_in[21];
    const float* f_out_w       = (const float*)d_in[22];
    const float* b_in_w        = (const float*)d_in[23];
    const float* b_conv_w      = (const float*)d_in[24];
    const float* b_conv_b      = (const float*)d_in[25];
    const float* b_dt_bias     = (const float*)d_in[26];
    const float* b_A_log       = (const float*)d_in[27];
    const float* b_D           = (const float*)d_in[28];
    const float* b_norm_w      = (const float*)d_in[29];
    const float* b_out_w       = (const float*)d_in[30];
    float* out = (float*)d_out;

    feat_kernel<<<NROWS, 128>>>(pidx, chridx, locus_fourier, pathway, pert_emb,
                                gene_id, chr_emb, locus_w, locus_b, cond_w, cond_b);

    // X = feat @ in_w^T + in_b (f32 SIMT)
    sgemm128<<<dim3(4, 17), 256>>>(0, in_w, in_b, 0, NROWS, DMODEL, GENEF);

    // split-bf16 conversions (W conversion independent of X)
    cvt_w<<<(DPROJ * DMODEL + 255) / 256, 256>>>(f_in_w, b_in_w);
    cvt_x<<<(NROWS * DMODEL + 255) / 256, 256>>>();

    // Z_dir = X @ W^T via tensor cores (split bf16)
    hgemm<<<dim3(19, 17), 256>>>(0);
    hgemm<<<dim3(19, 17), 256>>>(1);

    conv_kernel<<<dim3(L_SEQ + 32, 2), 256>>>(f_conv_w, f_conv_b, b_conv_w, b_conv_b);

    dtda_kernel<<<(2 * NROWS * NH + 255) / 256, 256>>>(f_dt_bias, f_A_log, b_dt_bias, b_A_log);
    decay_kernel<<<1, 32>>>();
    w4_kernel<<<1, 512>>>();
    dotcb_kernel<<<TCOR, 256>>>();

    wcomb_kernel<<<(2 * DIN + 255) / 256, 256>>>(head_w, f_out_w, b_out_w, f_norm_w, b_norm_w);
    siluz_kernel<<<dim3(2048, 2), 256>>>();

    prefix_kernel<<<128, 128>>>(f_D);

    scan_shared<<<256, 128>>>(f_D, b_D);

    reduce_ys<<<dim3(L_SEQ, 2), 256>>>();

    final_kernel<<<BATCH * 2048, 256>>>(head_b, out);
}

// round 9
// speedup vs baseline: 2.6711x; 1.1801x over previous
#include <cuda_runtime.h>
#include <cuda_bf16.h>
#include <math.h>

#define L_SEQ 2049
#define BATCH 8
#define NH 16
#define HD 64
#define NS 128
#define DIN 1024
#define CONVD 1280
#define DPROJ 2320
#define NROWS 2056
#define GENEF 384
#define DMODEL 512
#define TCOR 2045   // corrected timesteps t=4..2048
#define TC 32       // scan chunk length
#define SSTA 24     // hgemm shared stride (A), bf16 elems
#define SSTB 20     // hgemm shared stride (B), bf16 elems

// ------------------------- scratch (static device globals) -------------------
__device__ float d_feat[NROWS * GENEF];
__device__ float d_X[NROWS * DMODEL];                // only for sgemm src_sel==1 (unused path)
__device__ float d_Z[2][NROWS * DPROJ];
__device__ float d_xBCs[2][(size_t)L_SEQ * CONVD];   // batch-shared conv out
__device__ float d_xBC0[BATCH * 4 * CONVD];          // fwd per-batch conv out, t=0..3
__device__ float d_dtr[2][NROWS * NH];
__device__ float d_dAr[2][NROWS * NH];
__device__ float d_ysum[2][(size_t)L_SEQ * NH * 64]; // scan y (atomic-accumulated)
__device__ float d_ypre[BATCH * 3 * NH * 128];       // fwd per-batch y (t=1..3), halves
__device__ float d_decayf[NH * TCOR];                // cumprod dA fwd, t=4..2048
__device__ float d_dotCB[L_SEQ * 32];                // C_t . B_tau  [t][b][tau]
__device__ float d_W4[BATCH * NH * 4];               // dt_tau * prod dA  [b][h][tau]
__device__ float d_P[2][(size_t)2048 * DIN];         // silu(z) per gene row
__device__ float d_wcomb[2][DIN];
// split-bf16 operands for tensor-core Z-GEMMs
__device__ __nv_bfloat16 d_Xhi[NROWS * DMODEL];
__device__ __nv_bfloat16 d_Xlo[NROWS * DMODEL];
__device__ __nv_bfloat16 d_Whi[2][DPROJ * DMODEL];
__device__ __nv_bfloat16 d_Wlo[2][DPROJ * DMODEL];

__device__ __forceinline__ int seq_row(int b, int t) {
    return (t == 0) ? (2048 + b) : (t - 1);
}
__device__ __forceinline__ const float* xbc_fwd_ptr(int b, int t) {
    return (t >= 4) ? (d_xBCs[0] + (size_t)t * CONVD)
                    : (d_xBC0 + (size_t)(b * 4 + t) * CONVD);
}
__device__ __forceinline__ float fast_silu(float x) {
    return __fdividef(x, 1.f + __expf(-x));
}

// f32x2 packed math (sm_100+)
#define MUL2(d, a, b) asm("mul.rn.f32x2 %0,%1,%2;" : "=l"(d) : "l"(a), "l"(b))
#define FMA2(d, a, b, c) asm("fma.rn.f32x2 %0,%1,%2,%3;" : "=l"(d) : "l"(a), "l"(b), "l"(c))
#define ADD2(d, a, b) asm("add.rn.f32x2 %0,%1,%2;" : "=l"(d) : "l"(a), "l"(b))
__device__ __forceinline__ unsigned long long pack2(float x) {
    unsigned long long r;
    asm("mov.b64 %0,{%1,%1};" : "=l"(r) : "r"(__float_as_uint(x)));
    return r;
}
__device__ __forceinline__ float sum2(unsigned long long v) {
    unsigned int lo, hi;
    asm("mov.b64 {%0,%1},%2;" : "=r"(lo), "=r"(hi) : "l"(v));
    return __uint_as_float(lo) + __uint_as_float(hi);
}
__device__ __forceinline__ float lo2(unsigned long long v) {
    unsigned int lo;
    asm("mov.b64 {%0,_},%1;" : "=r"(lo) : "l"(v));
    return __uint_as_float(lo);
}
__device__ __forceinline__ float hi2(unsigned long long v) {
    unsigned int hi;
    asm("mov.b64 {_,%0},%1;" : "=r"(hi) : "l"(v));
    return __uint_as_float(hi);
}

// bf16 mma: D += A(m16k16) * B(n8k16)^T, f32 accum
#define MMA_BF16(cc, aa, bb) \
    asm volatile("mma.sync.aligned.m16n8k16.row.col.f32.bf16.bf16.f32 " \
        "{%0,%1,%2,%3}, {%4,%5,%6,%7}, {%8,%9}, {%0,%1,%2,%3};" \
        : "+f"((cc)[0]), "+f"((cc)[1]), "+f"((cc)[2]), "+f"((cc)[3]) \
        : "r"((aa)[0]), "r"((aa)[1]), "r"((aa)[2]), "r"((aa)[3]), \
          "r"((bb)[0]), "r"((bb)[1]))

// ------------------------- 0. zero ysum --------------------------------------
__global__ void zero_ysum() {
    size_t i = ((size_t)blockIdx.x * 256 + threadIdx.x) * 4;
    const size_t total = 2 * (size_t)L_SEQ * NH * 64;
    float* base = &d_ysum[0][0];
    if (i + 3 < total) *(float4*)&base[i] = make_float4(0, 0, 0, 0);
    else for (size_t k = i; k < total; k++) base[k] = 0.f;
}

// ------------------------- 1. feature rows -----------------------------------
__global__ void feat_kernel(const int* __restrict__ pidx,
                            const int* __restrict__ chridx,
                            const float* __restrict__ locus_fourier,
                            const float* __restrict__ pathway,
                            const float* __restrict__ pert_emb,
                            const float* __restrict__ gene_id,
                            const float* __restrict__ chr_emb,
                            const float* __restrict__ locus_w,
                            const float* __restrict__ locus_b,
                            const float* __restrict__ cond_w,
                            const float* __restrict__ cond_b) {
    int g = blockIdx.x;
    int tid = threadIdx.x;  // 128
    if (g < 2048) {
        d_feat[g * GENEF + tid] = gene_id[g * 128 + tid];
        d_feat[g * GENEF + 128 + tid] = pathway[g * 128 + tid];
        if (tid < 64) {
            int ci = chridx[g];
            d_feat[g * GENEF + 256 + tid] = chr_emb[ci * 64 + tid];
        } else {
            int j = tid - 64;
            float acc = locus_b[j];
            const float* lf = locus_fourier + g * 64;
            const float* lw = locus_w + j * 64;
            for (int k = 0; k < 64; k++) acc = fmaf(lf[k], lw[k], acc);
            float ge = 0.5f * acc * (1.f + erff(acc * 0.70710678118654752f));
            d_feat[g * GENEF + 320 + j] = ge;
        }
    } else {
        int b = g - 2048;
        const float* pe = pert_emb + (size_t)pidx[b] * 128;
        for (int j = tid; j < GENEF; j += 128) {
            float acc = cond_b[j];
            const float* cw = cond_w + (size_t)j * 128;
            for (int k = 0; k < 128; k++) acc = fmaf(pe[k], cw[k], acc);
            d_feat[g * GENEF + j] = acc;
        }
    }
}

// ------------------------- 2. SGEMM (f32) — X GEMM writes split-bf16 ---------
__global__ __launch_bounds__(256) void sgemm128(int src_sel,
                                                const float* __restrict__ W,
                                                const float* __restrict__ bias,
                                                int dst_sel, int M, int N, int K) {
    const float* A = (src_sel == 0) ? d_feat : d_X;
    float* C = (dst_sel == 0) ? d_X : d_Z[dst_sel - 1];

    __shared__ __align__(16) float2 As2[2][8][128];
    __shared__ __align__(16) float Ws[2][8][132];

    int tid = threadIdx.x;
    int row0 = blockIdx.y * 128, col0 = blockIdx.x * 128;
    int lr = tid >> 1;
    int lk = (tid & 1) * 4;
    bool aval = (row0 + lr) < M;
    bool wval = (col0 + lr) < N;
    const float* Aptr = A + (size_t)(row0 + lr) * K + lk;
    const float* Wptr = W + (size_t)(col0 + lr) * K + lk;

    float4 av = aval ? *(const float4*)Aptr : make_float4(0, 0, 0, 0);
    float4 wv = wval ? *(const float4*)Wptr : make_float4(0, 0, 0, 0);
    As2[0][lk + 0][lr] = make_float2(av.x, av.x);
    As2[0][lk + 1][lr] = make_float2(av.y, av.y);
    As2[0][lk + 2][lr] = make_float2(av.z, av.z);
    As2[0][lk + 3][lr] = make_float2(av.w, av.w);
    Ws[0][lk + 0][lr] = wv.x; Ws[0][lk + 1][lr] = wv.y;
    Ws[0][lk + 2][lr] = wv.z; Ws[0][lk + 3][lr] = wv.w;
    __syncthreads();

    unsigned long long acc2[8][4];
#pragma unroll
    for (int i = 0; i < 8; i++)
#pragma unroll
        for (int j = 0; j < 4; j++) acc2[i][j] = 0ull;

    int ty = tid >> 4, tx = tid & 15;

    for (int k0 = 0; k0 < K; k0 += 8) {
        int buf = (k0 >> 3) & 1;
        bool more = (k0 + 8) < K;
        if (more) {
            av = aval ? *(const float4*)(Aptr + k0 + 8) : make_float4(0, 0, 0, 0);
            wv = wval ? *(const float4*)(Wptr + k0 + 8) : make_float4(0, 0, 0, 0);
        }
#pragma unroll
        for (int kk = 0; kk < 8; kk++) {
            const ulonglong2* Ap = (const ulonglong2*)&As2[buf][kk][ty * 8];
            const ulonglong2* Bp0 = (const ulonglong2*)&Ws[buf][kk][tx * 4];
            const ulonglong2* Bp1 = (const ulonglong2*)&Ws[buf][kk][64 + tx * 4];
            ulonglong2 b0 = Bp0[0];
            ulonglong2 b1 = Bp1[0];
            ulonglong2 a01 = Ap[0], a23 = Ap[1], a45 = Ap[2], a67 = Ap[3];
            unsigned long long ra[8] = {a01.x, a01.y, a23.x, a23.y,
                                        a45.x, a45.y, a67.x, a67.y};
#pragma unroll
            for (int i = 0; i < 8; i++) {
                FMA2(acc2[i][0], ra[i], b0.x, acc2[i][0]);
                FMA2(acc2[i][1], ra[i], b0.y, acc2[i][1]);
                FMA2(acc2[i][2], ra[i], b1.x, acc2[i][2]);
                FMA2(acc2[i][3], ra[i], b1.y, acc2[i][3]);
            }
        }
        if (more) {
            int nb = buf ^ 1;
            As2[nb][lk + 0][lr] = make_float2(av.x, av.x);
            As2[nb][lk + 1][lr] = make_float2(av.y, av.y);
            As2[nb][lk + 2][lr] = make_float2(av.z, av.z);
            As2[nb][lk + 3][lr] = make_float2(av.w, av.w);
            Ws[nb][lk + 0][lr] = wv.x; Ws[nb][lk + 1][lr] = wv.y;
            Ws[nb][lk + 2][lr] = wv.z; Ws[nb][lk + 3][lr] = wv.w;
        }
        __syncthreads();
    }
#pragma unroll
    for (int i = 0; i < 8; i++) {
        int r = row0 + ty * 8 + i;
        if (r >= M) continue;
        float vals[8] = {lo2(acc2[i][0]), hi2(acc2[i][0]), lo2(acc2[i][1]), hi2(acc2[i][1]),
                         lo2(acc2[i][2]), hi2(acc2[i][2]), lo2(acc2[i][3]), hi2(acc2[i][3])};
#pragma unroll
        for (int j = 0; j < 8; j++) {
            int c = col0 + ((j < 4) ? (tx * 4 + j) : (64 + tx * 4 + (j - 4)));
            if (c >= N) continue;
            float v = vals[j] + (bias ? bias[c] : 0.f);
            if (dst_sel == 0) {
                __nv_bfloat16 hh = __float2bfloat16(v);
                d_Xhi[(size_t)r * N + c] = hh;
                d_Xlo[(size_t)r * N + c] = __float2bfloat16(v - __bfloat162float(hh));
            } else {
                C[(size_t)r * N + c] = v;
            }
        }
    }
}

// ------------------------- 2b. split-bf16 W conversion -----------------------
__global__ void cvt_w(const float* __restrict__ fw, const float* __restrict__ bw) {
    int i = blockIdx.x * 256 + threadIdx.x;
    if (i >= DPROJ * DMODEL) return;
    float v = fw[i];
    __nv_bfloat16 h = __float2bfloat16(v);
    d_Whi[0][i] = h;
    d_Wlo[0][i] = __float2bfloat16(v - __bfloat162float(h));
    v = bw[i];
    h = __float2bfloat16(v);
    d_Whi[1][i] = h;
    d_Wlo[1][i] = __float2bfloat16(v - __bfloat162float(h));
}

// ------------------------- 2c. tensor-core Z-GEMM ----------------------------
__global__ __launch_bounds__(256) void hgemm(int dir) {
    const __nv_bfloat16* Wh = d_Whi[dir];
    const __nv_bfloat16* Wl = d_Wlo[dir];
    float* C = d_Z[dir];

    __shared__ __align__(16) __nv_bfloat16 sA[2][2][128 * SSTA];
    __shared__ __align__(16) __nv_bfloat16 sB[2][2][128 * SSTB];

    int tid = threadIdx.x;
    int row0 = blockIdx.y * 128;
    int col0 = blockIdx.x * 128;
    int lrow = tid >> 1;
    int seg = tid & 1;

    int arow = row0 + lrow;
    int brow = col0 + lrow;
    bool aval = arow < NROWS;
    bool bval = brow < DPROJ;
    const uint4 z4 = make_uint4(0, 0, 0, 0);

    size_t abase = (size_t)arow * DMODEL + seg * 8;
    size_t bbase = (size_t)brow * DMODEL + seg * 8;

    uint4 rAh, rAl, rBh, rBl;
    rAh = aval ? *(const uint4*)(d_Xhi + abase) : z4;
    rAl = aval ? *(const uint4*)(d_Xlo + abase) : z4;
    rBh = bval ? *(const uint4*)(Wh + bbase) : z4;
    rBl = bval ? *(const uint4*)(Wl + bbase) : z4;
    {
        *(uint4*)&sA[0][0][lrow * SSTA + seg * 8] = rAh;
        *(uint4*)&sA[0][1][lrow * SSTA + seg * 8] = rAl;
        char* db = (char*)&sB[0][0][0] + lrow * (SSTB * 2) + seg * 16;
        *(uint2*)db = make_uint2(rBh.x, rBh.y);
        *(uint2*)(db + 8) = make_uint2(rBh.z, rBh.w);
        char* dl = (char*)&sB[0][1][0] + lrow * (SSTB * 2) + seg * 16;
        *(uint2*)dl = make_uint2(rBl.x, rBl.y);
        *(uint2*)(dl + 8) = make_uint2(rBl.z, rBl.w);
    }
    __syncthreads();

    int w = tid >> 5, l = tid & 31;
    int mw = w >> 1, nw = w & 1;
    int g = l >> 2, q = l & 3;

    float c[2][8][4];
#pragma unroll
    for (int mt = 0; mt < 2; mt++)
#pragma unroll
        for (int nt = 0; nt < 8; nt++)
#pragma unroll
            for (int i = 0; i < 4; i++) c[mt][nt][i] = 0.f;

    const int NCH = DMODEL / 16;
    for (int kc = 0; kc < NCH; kc++) {
        int buf = kc & 1;
        bool more = (kc + 1) < NCH;
        if (more) {
            size_t ao = abase + (size_t)(kc + 1) * 16;
            size_t bo = bbase + (size_t)(kc + 1) * 16;
            rAh = aval ? *(const uint4*)(d_Xhi + ao) : z4;
            rAl = aval ? *(const uint4*)(d_Xlo + ao) : z4;
            rBh = bval ? *(const uint4*)(Wh + bo) : z4;
            rBl = bval ? *(const uint4*)(Wl + bo) : z4;
        }

        unsigned a[2][2][4], b[8][2][2];
#pragma unroll
        for (int mt = 0; mt < 2; mt++) {
            int r = mw * 32 + mt * 16 + g;
#pragma unroll
            for (int v = 0; v < 2; v++) {
                const __nv_bfloat16* base = sA[buf][v];
                a[mt][v][0] = *(const unsigned*)&base[r * SSTA + q * 2];
                a[mt][v][1] = *(const unsigned*)&base[(r + 8) * SSTA + q * 2];
                a[mt][v][2] = *(const unsigned*)&base[r * SSTA + q * 2 + 8];
                a[mt][v][3] = *(const unsigned*)&base[(r + 8) * SSTA + q * 2 + 8];
            }
        }
#pragma unroll
        for (int nt = 0; nt < 8; nt++) {
            int n = nw * 64 + nt * 8 + g;
#pragma unroll
            for (int v = 0; v < 2; v++) {
                const __nv_bfloat16* base = sB[buf][v];
                b[nt][v][0] = *(const unsigned*)&base[n * SSTB + q * 2];
                b[nt][v][1] = *(const unsigned*)&base[n * SSTB + q * 2 + 8];
            }
        }
#pragma unroll
        for (int mt = 0; mt < 2; mt++)
#pragma unroll
            for (int nt = 0; nt < 8; nt++) {
                MMA_BF16(c[mt][nt], a[mt][0], b[nt][0]);
                MMA_BF16(c[mt][nt], a[mt][0], b[nt][1]);
                MMA_BF16(c[mt][nt], a[mt][1], b[nt][0]);
            }

        if (more) {
            int nb = buf ^ 1;
            *(uint4*)&sA[nb][0][lrow * SSTA + seg * 8] = rAh;
            *(uint4*)&sA[nb][1][lrow * SSTA + seg * 8] = rAl;
            char* db = (char*)&sB[nb][0][0] + lrow * (SSTB * 2) + seg * 16;
            *(uint2*)db = make_uint2(rBh.x, rBh.y);
            *(uint2*)(db + 8) = make_uint2(rBh.z, rBh.w);
            char* dl = (char*)&sB[nb][1][0] + lrow * (SSTB * 2) + seg * 16;
            *(uint2*)dl = make_uint2(rBl.x, rBl.y);
            *(uint2*)(dl + 8) = make_uint2(rBl.z, rBl.w);
        }
        __syncthreads();
    }

#pragma unroll
    for (int mt = 0; mt < 2; mt++) {
        int r0 = row0 + mw * 32 + mt * 16 + g;
#pragma unroll
        for (int nt = 0; nt < 8; nt++) {
            int cc = col0 + nw * 64 + nt * 8 + q * 2;
            if (cc < DPROJ) {
                if (r0 < NROWS)
                    *(float2*)&C[(size_t)r0 * DPROJ + cc] =
                        make_float2(c[mt][nt][0], c[mt][nt][1]);
                if (r0 + 8 < NROWS)
                    *(float2*)&C[(size_t)(r0 + 8) * DPROJ + cc] =
                        make_float2(c[mt][nt][2], c[mt][nt][3]);
            }
        }
    }
}

// ------------------------- 3. causal depthwise conv + silu -------------------
__global__ void conv_kernel(const float* __restrict__ cw_f, const float* __restrict__ cb_f,
                            const float* __restrict__ cw_b, const float* __restrict__ cb_b) {
    int bx = blockIdx.x;
    int dir = blockIdx.y;
    const float* cw = dir ? cw_b : cw_f;
    const float* cb = dir ? cb_b : cb_f;
    const float* Z = d_Z[dir];

    const float* rows[4];
    float* dst;
    if (bx < L_SEQ) {
        int t = bx;
        if ((dir == 0 && t < 4) || (dir == 1 && t < 1)) return;
        dst = d_xBCs[dir] + (size_t)t * CONVD;
#pragma unroll
        for (int k = 0; k < 4; k++) {
            int tau = dir ? (t + 3 - k) : (t - 3 + k);
            rows[k] = (tau <= L_SEQ - 1) ? (Z + (size_t)(tau - 1) * DPROJ + DIN) : nullptr;
        }
    } else {
        if (dir == 1) return;
        int idx = bx - L_SEQ;
        int b = idx >> 2;
        int t = idx & 3;
        dst = d_xBC0 + (size_t)(b * 4 + t) * CONVD;
#pragma unroll
        for (int k = 0; k < 4; k++) {
            int tau = t - 3 + k;
            rows[k] = (tau >= 0) ? (Z + (size_t)seq_row(b, tau) * DPROJ + DIN) : nullptr;
        }
    }
    for (int c = threadIdx.x; c < CONVD; c += blockDim.x) {
        float acc = cb[c];
#pragma unroll
        for (int k = 0; k < 4; k++)
            if (rows[k]) acc = fmaf(rows[k][c], cw[c * 4 + k], acc);
        dst[c] = fast_silu(acc);
    }
}

// ------------------------- 4. dt / dA per row --------------------------------
__global__ void dtda_kernel(const float* __restrict__ fdtb, const float* __restrict__ fAl,
                            const float* __restrict__ bdtb, const float* __restrict__ bAl) {
    int idx = blockIdx.x * blockDim.x + threadIdx.x;
    const int per = NROWS * NH;
    if (idx >= 2 * per) return;
    int dir = idx / per;
    int r = idx % per;
    int row = r >> 4;
    int h = r & 15;
    float raw = d_Z[dir][(size_t)row * DPROJ + (DIN + CONVD) + h] + (dir ? bdtb : fdtb)[h];
    float dtv = (raw > 20.f) ? raw : log1pf(expf(raw));
    float Al = (dir ? bAl : fAl)[h];
    d_dtr[dir][row * NH + h] = dtv;
    d_dAr[dir][row * NH + h] = expf(-expf(Al) * dtv);
}

// ------------------------- 4b. fwd decay cumprod -----------------------------
__global__ void decay_kernel() {
    int h = threadIdx.x;
    if (h >= NH) return;
    float acc = 1.f;
    for (int t = 4; t <= 2048; t++) {
        acc *= d_dAr[0][(t - 1) * NH + h];
        d_decayf[h * TCOR + (t - 4)] = acc;
    }
}

// ------------------------- 4c. W4 --------------------------------------------
__global__ void w4_kernel() {
    int idx = threadIdx.x;   // 512
    if (idx >= BATCH * NH * 4) return;
    int b = idx >> 6, h = (idx >> 2) & 15, tau = idx & 3;
    int row_tau = (tau == 0) ? (2048 + b) : (tau - 1);
    float w = d_dtr[0][row_tau * NH + h];
    for (int s = tau + 1; s < 4; s++)
        w *= d_dAr[0][(s - 1) * NH + h];
    d_W4[idx] = w;
}

// ------------------------- 4d. dotCB -----------------------------------------
__global__ void dotcb_kernel() {
    int t = blockIdx.x + 4;       // 4..2048
    __shared__ float sC[128];
    int tid = threadIdx.x;        // 256 = 8 warps
    if (tid < 128) sC[tid] = d_xBCs[0][(size_t)t * CONVD + DIN + NS + tid];
    __syncthreads();
    int w = tid >> 5, l = tid & 31;
    for (int c = w; c < 32; c += 8) {
        const float* B0 = d_xBC0 + (size_t)c * CONVD + DIN;
        float acc = 0.f;
#pragma unroll
        for (int i = 0; i < 4; i++) acc = fmaf(B0[i * 32 + l], sC[i * 32 + l], acc);
#pragma unroll
        for (int off = 16; off; off >>= 1)
            acc += __shfl_xor_sync(0xffffffffu, acc, off);
        if (l == 0) d_dotCB[t * 32 + c] = acc;
    }
}

// ------------------------- 5. combined output vector -------------------------
__global__ void wcomb_kernel(const float* __restrict__ head_w,
                             const float* __restrict__ fow, const float* __restrict__ bow,
                             const float* __restrict__ fnw, const float* __restrict__ bnw) {
    int idx = blockIdx.x * blockDim.x + threadIdx.x;
    if (idx >= 2 * DIN) return;
    int dir = idx >> 10;
    int j = idx & 1023;
    const float* ow = dir ? bow : fow;
    float acc = 0.f;
    for (int i = 0; i < DMODEL; i++) acc = fmaf(ow[(size_t)i * DIN + j], head_w[i], acc);
    d_wcomb[dir][j] = acc * (dir ? bnw : fnw)[j];
}

// ------------------------- 5b. silu(z) per gene row --------------------------
__global__ void siluz_kernel() {
    int row = blockIdx.x;
    int dir = blockIdx.y;
    const float* z = d_Z[dir] + (size_t)row * DPROJ;
    float* P = d_P[dir] + (size_t)row * DIN;
    for (int j = threadIdx.x; j < DIN; j += 256) P[j] = fast_silu(z[j]);
}

// ------------------------- 6a. fwd per-batch prefix scan (t=0..3) ------------
__global__ __launch_bounds__(128) void prefix_kernel(const float* __restrict__ fD) {
    int blk = blockIdx.x;
    int b = blk >> 4;
    int h = blk & 15;
    int tid = threadIdx.x;
    int p = tid & 63;
    int nh = tid >> 6;
    float Dh = fD[h];

    __shared__ __align__(16) float sB[128], sC[128], sx[64];

    unsigned long long hs2[32];
#pragma unroll
    for (int i = 0; i < 32; i++) hs2[i] = 0ull;

    for (int t = 0; t < 4; t++) {
        const float* pp = xbc_fwd_ptr(b, t);
        sB[tid] = pp[DIN + tid];
        sC[tid] = pp[DIN + NS + tid];
        if (tid < 64) sx[tid] = pp[h * HD + tid];
        __syncthreads();
        int row = (t == 0) ? (2048 + b) : (t - 1);
        float dtv = d_dtr[0][row * NH + h];
        float dAv = d_dAr[0][row * NH + h];
        float xv = sx[p];
        unsigned long long coef2 = pack2(dtv * xv);
        unsigned long long dA2 = pack2(dAv);
        const ulonglong2* B4 = (const ulonglong2*)(sB + nh * 64);
        const ulonglong2* C4 = (const ulonglong2*)(sC + nh * 64);
        unsigned long long a0 = 0ull, a1 = 0ull;
#pragma unroll
        for (int i = 0; i < 16; i++) {
            ulonglong2 bv = B4[i], cv = C4[i];
            unsigned long long tm;
            MUL2(tm, coef2, bv.x);
            FMA2(hs2[2 * i + 0], dA2, hs2[2 * i + 0], tm);
            FMA2(a0, hs2[2 * i + 0], cv.x, a0);
            MUL2(tm, coef2, bv.y);
            FMA2(hs2[2 * i + 1], dA2, hs2[2 * i + 1], tm);
            FMA2(a1, hs2[2 * i + 1], cv.y, a1);
        }
        ADD2(a0, a0, a1);
        float part = sum2(a0);
        if (nh == 0) part = fmaf(Dh, xv, part);
        if (t >= 1)
            d_ypre[((size_t)(b * 3 + (t - 1)) * 16 + h) * 128 + tid] = part;
        __syncthreads();
    }
}

// ------------------------- 6b. shared scans, pipelined chunks ----------------
// 256 blocks = (dir, h, n-eighth q). 128 threads = 4 warps (2 blocks/SM).
// Chunk c+1 prefetched into registers during chunk c compute; double-buffered
// shared; one barrier per chunk. Output accumulated via RED into d_ysum.
__global__ __launch_bounds__(128) void scan_shared(const float* __restrict__ fD,
                                                   const float* __restrict__ bD) {
    int blk = blockIdx.x;          // 0..255
    int dir = blk >> 7;
    int rest = blk & 127;
    int h = rest >> 3;
    int q = rest & 7;
    int tid = threadIdx.x;
    int wid = tid >> 5;
    int lane = tid & 31;
    int p = (wid & 1) * 32 + lane;
    int sub = wid >> 1;
    int s16 = q * 2 + sub;
    float Dh = (dir ? bD : fD)[h];
    const float* xbc = d_xBCs[dir];
    const float* dtr = d_dtr[dir];
    const float* dAr = d_dAr[dir];
    float* ysum = d_ysum[dir];

    int S = dir ? 2048 : TCOR;
    int nch = (S + TC - 1) / TC;

    __shared__ __align__(16) float sB[2][TC][16];
    __shared__ __align__(16) float sC[2][TC][16];
    __shared__ __align__(16) float sx[2][TC][64];
    __shared__ float sdt[2][TC], sdA[2][TC];

    unsigned long long hs2[4] = {0ull, 0ull, 0ull, 0ull};

    int j0 = tid >> 2, c0 = tid & 3;    // B/C staging: row j0, seg c0
    int jx = tid >> 4, cx = tid & 15;   // x staging: rows jx+8k, seg cx

    float4 rB, rC, rx[4];
    float rdt = 0.f, rdA = 0.f;

    // ---- load chunk starting at s0 into registers ----
#define SCAN_LOAD(s0_)                                                          \
    {                                                                           \
        int lim = S - 1 - (s0_);                                                \
        {                                                                       \
            int j = (j0 < lim) ? j0 : lim;                                      \
            int tt = dir ? (2048 - ((s0_) + j)) : (4 + (s0_) + j);              \
            const float* rowp = xbc + (size_t)tt * CONVD + DIN + q * 16;        \
            rB = ((const float4*)rowp)[c0];                                     \
            rC = ((const float4*)(rowp + NS))[c0];                              \
        }                                                                       \
        _Pragma("unroll")                                                       \
        for (int k = 0; k < 4; k++) {                                           \
            int j = jx + k * 8; if (j > lim) j = lim;                           \
            int tt = dir ? (2048 - ((s0_) + j)) : (4 + (s0_) + j);              \
            rx[k] = ((const float4*)(xbc + (size_t)tt * CONVD + h * HD))[cx];   \
        }                                                                       \
        if (tid < TC) {                                                         \
            int j = (tid > lim) ? lim : tid;                                    \
            int tt = dir ? (2048 - ((s0_) + j)) : (4 + (s0_) + j);              \
            rdt = dtr[(tt - 1) * NH + h];                                       \
            rdA = dAr[(tt - 1) * NH + h];                                       \
        }                                                                       \
    }
#define SCAN_STORE(bb_)                                                         \
    {                                                                           \
        *(float4*)&sB[bb_][j0][c0 * 4] = rB;                                    \
        *(float4*)&sC[bb_][j0][c0 * 4] = rC;                                    \
        _Pragma("unroll")                                                       \
        for (int k = 0; k < 4; k++)                                             \
            *(float4*)&sx[bb_][jx + k * 8][cx * 4] = rx[k];                     \
        if (tid < TC) { sdt[bb_][tid] = rdt; sdA[bb_][tid] = rdA; }             \
    }

    SCAN_LOAD(0);
    SCAN_STORE(0);
    __syncthreads();

    for (int c = 0; c < nch; c++) {
        int s0 = c * TC;
        int cnt = (S - s0 < TC) ? (S - s0) : TC;
        bool more = (c + 1) < nch;
        if (more) SCAN_LOAD(s0 + TC);
        int bb = c & 1;
        for (int j = 0; j < cnt; j++) {
            int tt = dir ? (2048 - (s0 + j)) : (4 + s0 + j);
            float xv = sx[bb][j][p];
            unsigned long long coef2 = pack2(sdt[bb][j] * xv);
            unsigned long long dA2 = pack2(sdA[bb][j]);
            const ulonglong2* B4 = (const ulonglong2*)&sB[bb][j][sub * 8];
            const ulonglong2* C4 = (const ulonglong2*)&sC[bb][j][sub * 8];
            ulonglong2 bv0 = B4[0], cv0 = C4[0];
            ulonglong2 bv1 = B4[1], cv1 = C4[1];
            unsigned long long a0 = 0ull, a1 = 0ull, tm;
            MUL2(tm, coef2, bv0.x);
            FMA2(hs2[0], dA2, hs2[0], tm);
            FMA2(a0, hs2[0], cv0.x, a0);
            MUL2(tm, coef2, bv0.y);
            FMA2(hs2[1], dA2, hs2[1], tm);
            FMA2(a1, hs2[1], cv0.y, a1);
            MUL2(tm, coef2, bv1.x);
            FMA2(hs2[2], dA2, hs2[2], tm);
            FMA2(a0, hs2[2], cv1.x, a0);
            MUL2(tm, coef2, bv1.y);
            FMA2(hs2[3], dA2, hs2[3], tm);
            FMA2(a1, hs2[3], cv1.y, a1);
            ADD2(a0, a0, a1);
            float y = sum2(a0);
            if (s16 == 0) y = fmaf(Dh, xv, y);
            atomicAdd(&ysum[(size_t)tt * 1024 + h * 64 + p], y);
        }
        if (more) SCAN_STORE((c + 1) & 1);
        __syncthreads();
    }
#undef SCAN_LOAD
#undef SCAN_STORE
}

// ------------------------- 7. gate + RMSnorm + fused head (per-t, all b) -----
__global__ __launch_bounds__(256) void final_kernel(const float* __restrict__ head_b,
                                                    float* __restrict__ out) {
    int t = blockIdx.x + 1;     // 1..2048
    int tid = threadIdx.x;      // 256
    __shared__ float cco[8][64];
    __shared__ float sh[8][18];

    if (t >= 4) {
        for (int i = tid; i < 512; i += 256) {
            int b = i >> 6;
            int r = i & 63;             // h*4+tau
            int hh = r >> 2, tau = r & 3;
            cco[b][r] = d_decayf[hh * TCOR + (t - 4)] *
                        d_W4[(b * 16 + hh) * 4 + tau] *
                        d_dotCB[t * 32 + b * 4 + tau];
        }
    }
    __syncthreads();

    int j0 = tid * 4;
    int h = tid >> 4;
    float4 ysf4 = *(const float4*)&d_ysum[0][(size_t)t * DIN + j0];
    float4 ysb4 = *(const float4*)&d_ysum[1][(size_t)t * DIN + j0];
    float4 pf4 = *(const float4*)&d_P[0][(size_t)(t - 1) * DIN + j0];
    float4 pb4 = *(const float4*)&d_P[1][(size_t)(t - 1) * DIN + j0];
    float4 w04 = *(const float4*)&d_wcomb[0][j0];
    float4 w14 = *(const float4*)&d_wcomb[1][j0];

    // backward: batch-shared
    float ssqb = 0.f, sdotb = 0.f;
    {
        float g;
        g = ysb4.x * pb4.x; ssqb = fmaf(g, g, ssqb); sdotb = fmaf(g, w14.x, sdotb);
        g = ysb4.y * pb4.y; ssqb = fmaf(g, g, ssqb); sdotb = fmaf(g, w14.y, sdotb);
        g = ysb4.z * pb4.z; ssqb = fmaf(g, g, ssqb); sdotb = fmaf(g, w14.z, sdotb);
        g = ysb4.w * pb4.w; ssqb = fmaf(g, g, ssqb); sdotb = fmaf(g, w14.w, sdotb);
    }

    float ssqf[8], sdotf[8];
    if (t >= 4) {
#pragma unroll
        for (int b = 0; b < 8; b++) {
            const float* xbb = d_xBC0 + (size_t)b * 4 * CONVD + j0;
            float4 x0 = *(const float4*)&xbb[0];
            float4 x1 = *(const float4*)&xbb[CONVD];
            float4 x2 = *(const float4*)&xbb[2 * CONVD];
            float4 x3 = *(const float4*)&xbb[3 * CONVD];
            float cc0 = cco[b][h * 4 + 0], cc1 = cco[b][h * 4 + 1];
            float cc2 = cco[b][h * 4 + 2], cc3 = cco[b][h * 4 + 3];
            float sq = 0.f, sd = 0.f, yf, g;
            yf = ysf4.x + cc0 * x0.x + cc1 * x1.x + cc2 * x2.x + cc3 * x3.x;
            g = yf * pf4.x; sq = fmaf(g, g, sq); sd = fmaf(g, w04.x, sd);
            yf = ysf4.y + cc0 * x0.y + cc1 * x1.y + cc2 * x2.y + cc3 * x3.y;
            g = yf * pf4.y; sq = fmaf(g, g, sq); sd = fmaf(g, w04.y, sd);
            yf = ysf4.z + cc0 * x0.z + cc1 * x1.z + cc2 * x2.z + cc3 * x3.z;
            g = yf * pf4.z; sq = fmaf(g, g, sq); sd = fmaf(g, w04.z, sd);
            yf = ysf4.w + cc0 * x0.w + cc1 * x1.w + cc2 * x2.w + cc3 * x3.w;
            g = yf * pf4.w; sq = fmaf(g, g, sq); sd = fmaf(g, w04.w, sd);
            ssqf[b] = sq; sdotf[b] = sd;
        }
    } else {
        int p0 = j0 & 63;
#pragma unroll
        for (int b = 0; b < 8; b++) {
            const float* yp = d_ypre + ((size_t)(b * 3 + (t - 1)) * 16 + h) * 128;
            float sq = 0.f, sd = 0.f;
            float pf[4] = {pf4.x, pf4.y, pf4.z, pf4.w};
            float w0[4] = {w04.x, w04.y, w04.z, w04.w};
#pragma unroll
            for (int k = 0; k < 4; k++) {
                float yf = yp[p0 + k] + yp[64 + p0 + k];
                float g = yf * pf[k];
                sq = fmaf(g, g, sq); sd = fmaf(g, w0[k], sd);
            }
            ssqf[b] = sq; sdotf[b] = sd;
        }
    }

#pragma unroll
    for (int off = 16; off; off >>= 1) {
        ssqb += __shfl_xor_sync(0xffffffffu, ssqb, off);
        sdotb += __shfl_xor_sync(0xffffffffu, sdotb, off);
#pragma unroll
        for (int b = 0; b < 8; b++) {
            ssqf[b] += __shfl_xor_sync(0xffffffffu, ssqf[b], off);
            sdotf[b] += __shfl_xor_sync(0xffffffffu, sdotf[b], off);
        }
    }
    int w = tid >> 5, l = tid & 31;
    if (l == 0) {
        sh[w][0] = ssqb; sh[w][1] = sdotb;
#pragma unroll
        for (int b = 0; b < 8; b++) { sh[w][2 + b] = ssqf[b]; sh[w][10 + b] = sdotf[b]; }
    }
    __syncthreads();
    if (tid < 8) {
        float qb = 0.f, db = 0.f, a = 0.f, d = 0.f;
        for (int i = 0; i < 8; i++) {
            qb += sh[i][0]; db += sh[i][1];
            a += sh[i][2 + tid]; d += sh[i][10 + tid];
        }
        float resb = rsqrtf(qb * (1.f / 1024.f) + 1e-5f) * db;
        float resf = rsqrtf(a * (1.f / 1024.f) + 1e-5f) * d;
        out[tid * 2048 + (t - 1)] = resf + resb + head_b[0];
    }
}

// ------------------------- launch --------------------------------------------
extern "C" void kernel_launch(void* const* d_in, const int* in_sizes, int n_in,
                              void* d_out, int out_size) {
    const int* pidx            = (const int*)d_in[0];
    const int* chridx          = (const int*)d_in[1];
    const float* locus_fourier = (const float*)d_in[2];
    const float* pathway       = (const float*)d_in[3];
    const float* pert_emb      = (const float*)d_in[4];
    const float* gene_id       = (const float*)d_in[5];
    const float* chr_emb       = (const float*)d_in[6];
    const float* locus_w       = (const float*)d_in[7];
    const float* locus_b       = (const float*)d_in[8];
    const float* cond_w        = (const float*)d_in[9];
    const float* cond_b        = (const float*)d_in[10];
    const float* in_w          = (const float*)d_in[11];
    const float* in_b          = (const float*)d_in[12];
    const float* head_w        = (const float*)d_in[13];
    const float* head_b        = (const float*)d_in[14];
    const float* f_in_w        = (const float*)d_in[15];
    const float* f_conv_w      = (const float*)d_in[16];
    const float* f_conv_b      = (const float*)d_in[17];
    const float* f_dt_bias     = (const float*)d_in[18];
    const float* f_A_log       = (const float*)d_in[19];
    const float* f_D           = (const float*)d_in[20];
    const float* f_norm_w      = (const float*)d_in[21];
    const float* f_out_w       = (const float*)d_in[22];
    const float* b_in_w        = (const float*)d_in[23];
    const float* b_conv_w      = (const float*)d_in[24];
    const float* b_conv_b      = (const float*)d_in[25];
    const float* b_dt_bias     = (const float*)d_in[26];
    const float* b_A_log       = (const float*)d_in[27];
    const float* b_D           = (const float*)d_in[28];
    const float* b_norm_w      = (const float*)d_in[29];
    const float* b_out_w       = (const float*)d_in[30];
    float* out = (float*)d_out;

    feat_kernel<<<NROWS, 128>>>(pidx, chridx, locus_fourier, pathway, pert_emb,
                                gene_id, chr_emb, locus_w, locus_b, cond_w, cond_b);
    zero_ysum<<<4099, 256>>>();

    // X = feat @ in_w^T + in_b — writes split-bf16 Xhi/Xlo directly
    sgemm128<<<dim3(4, 17), 256>>>(0, in_w, in_b, 0, NROWS, DMODEL, GENEF);
    cvt_w<<<(DPROJ * DMODEL + 255) / 256, 256>>>(f_in_w, b_in_w);

    // Z_dir = X @ W^T via tensor cores (split bf16)
    hgemm<<<dim3(19, 17), 256>>>(0);
    hgemm<<<dim3(19, 17), 256>>>(1);

    conv_kernel<<<dim3(L_SEQ + 32, 2), 256>>>(f_conv_w, f_conv_b, b_conv_w, b_conv_b);

    dtda_kernel<<<(2 * NROWS * NH + 255) / 256, 256>>>(f_dt_bias, f_A_log, b_dt_bias, b_A_log);
    decay_kernel<<<1, 32>>>();
    w4_kernel<<<1, 512>>>();
    dotcb_kernel<<<TCOR, 256>>>();

    wcomb_kernel<<<(2 * DIN + 255) / 256, 256>>>(head_w, f_out_w, b_out_w, f_norm_w, b_norm_w);
    siluz_kernel<<<dim3(2048, 2), 256>>>();

    prefix_kernel<<<128, 128>>>(f_D);

    // pipelined shared scans; RED-accumulate into d_ysum
    scan_shared<<<256, 128>>>(f_D, b_D);

    // per-t final: all 8 batches, backward reduction shared
    final_kernel<<<2048, 256>>>(head_b, out);
}

// round 11
// speedup vs baseline: 3.7693x; 1.4111x over previous
#include <cuda_runtime.h>
#include <cuda_bf16.h>
#include <math.h>

#define L_SEQ 2049
#define BATCH 8
#define NH 16
#define HD 64
#define NS 128
#define DIN 1024
#define CONVD 1280
#define DPROJ 2320
#define NROWS 2056
#define GENEF 384
#define DMODEL 512
#define TCOR 2045   // corrected timesteps t=4..2048
#define TC 16       // scan chunk length
#define SSTA 24     // hgemm shared stride (A), bf16 elems
#define SSTB 20     // hgemm shared stride (B), bf16 elems

// ------------------------- scratch (static device globals) -------------------
__device__ float d_Z[2][NROWS * DPROJ];
__device__ float d_xBCs[2][(size_t)L_SEQ * CONVD];   // batch-shared conv out
__device__ float d_xBC0[BATCH * 4 * CONVD];          // fwd per-batch conv out, t=0..3
__device__ float d_dtr[2][NROWS * NH];
__device__ float d_dAr[2][NROWS * NH];
__device__ float d_ysum[2][(size_t)L_SEQ * NH * 64]; // scan y (each elem written once)
__device__ float d_ypre[BATCH * 3 * NH * 128];       // fwd per-batch y (t=1..3), halves
__device__ float d_decayf[NH * TCOR];                // cumprod dA fwd, t=4..2048
__device__ float d_dotCB[L_SEQ * 32];                // C_t . B_tau  [t][b][tau]
__device__ float d_W4[BATCH * NH * 4];               // dt_tau * prod dA  [b][h][tau]
__device__ float d_P[2][(size_t)2048 * DIN];         // silu(z) per gene row
__device__ float d_wcomb[2][DIN];
// split-bf16 operands for tensor-core GEMMs
__device__ __nv_bfloat16 d_Fhi[NROWS * GENEF];
__device__ __nv_bfloat16 d_Flo[NROWS * GENEF];
__device__ __nv_bfloat16 d_IWhi[DMODEL * GENEF];
__device__ __nv_bfloat16 d_IWlo[DMODEL * GENEF];
__device__ __nv_bfloat16 d_Xhi[NROWS * DMODEL];
__device__ __nv_bfloat16 d_Xlo[NROWS * DMODEL];
__device__ __nv_bfloat16 d_Whi[2][DPROJ * DMODEL];
__device__ __nv_bfloat16 d_Wlo[2][DPROJ * DMODEL];

__device__ __forceinline__ int seq_row(int b, int t) {
    return (t == 0) ? (2048 + b) : (t - 1);
}
__device__ __forceinline__ const float* xbc_fwd_ptr(int b, int t) {
    return (t >= 4) ? (d_xBCs[0] + (size_t)t * CONVD)
                    : (d_xBC0 + (size_t)(b * 4 + t) * CONVD);
}
__device__ __forceinline__ float fast_silu(float x) {
    return __fdividef(x, 1.f + __expf(-x));
}
__device__ __forceinline__ void store_split(__nv_bfloat16* hi, __nv_bfloat16* lo,
                                            size_t i, float v) {
    __nv_bfloat16 h = __float2bfloat16(v);
    hi[i] = h;
    lo[i] = __float2bfloat16(v - __bfloat162float(h));
}

// f32x2 packed math (sm_100+)
#define MUL2(d, a, b) asm("mul.rn.f32x2 %0,%1,%2;" : "=l"(d) : "l"(a), "l"(b))
#define FMA2(d, a, b, c) asm("fma.rn.f32x2 %0,%1,%2,%3;" : "=l"(d) : "l"(a), "l"(b), "l"(c))
#define ADD2(d, a, b) asm("add.rn.f32x2 %0,%1,%2;" : "=l"(d) : "l"(a), "l"(b))
__device__ __forceinline__ unsigned long long pack2(float x) {
    unsigned long long r;
    asm("mov.b64 %0,{%1,%1};" : "=l"(r) : "r"(__float_as_uint(x)));
    return r;
}
__device__ __forceinline__ float sum2(unsigned long long v) {
    unsigned int lo, hi;
    asm("mov.b64 {%0,%1},%2;" : "=r"(lo), "=r"(hi) : "l"(v));
    return __uint_as_float(lo) + __uint_as_float(hi);
}

// bf16 mma: D += A(m16k16) * B(n8k16)^T, f32 accum
#define MMA_BF16(cc, aa, bb) \
    asm volatile("mma.sync.aligned.m16n8k16.row.col.f32.bf16.bf16.f32 " \
        "{%0,%1,%2,%3}, {%4,%5,%6,%7}, {%8,%9}, {%0,%1,%2,%3};" \
        : "+f"((cc)[0]), "+f"((cc)[1]), "+f"((cc)[2]), "+f"((cc)[3]) \
        : "r"((aa)[0]), "r"((aa)[1]), "r"((aa)[2]), "r"((aa)[3]), \
          "r"((bb)[0]), "r"((bb)[1]))

// ------------------------- 1. feature rows (split-bf16 output) ---------------
__global__ void feat_kernel(const int* __restrict__ pidx,
                            const int* __restrict__ chridx,
                            const float* __restrict__ locus_fourier,
                            const float* __restrict__ pathway,
                            const float* __restrict__ pert_emb,
                            const float* __restrict__ gene_id,
                            const float* __restrict__ chr_emb,
                            const float* __restrict__ locus_w,
                            const float* __restrict__ locus_b,
                            const float* __restrict__ cond_w,
                            const float* __restrict__ cond_b) {
    int g = blockIdx.x;
    int tid = threadIdx.x;  // 128
    if (g < 2048) {
        store_split(d_Fhi, d_Flo, (size_t)g * GENEF + tid, gene_id[g * 128 + tid]);
        store_split(d_Fhi, d_Flo, (size_t)g * GENEF + 128 + tid, pathway[g * 128 + tid]);
        if (tid < 64) {
            int ci = chridx[g];
            store_split(d_Fhi, d_Flo, (size_t)g * GENEF + 256 + tid, chr_emb[ci * 64 + tid]);
        } else {
            int j = tid - 64;
            float acc = locus_b[j];
            const float* lf = locus_fourier + g * 64;
            const float* lw = locus_w + j * 64;
            for (int k = 0; k < 64; k++) acc = fmaf(lf[k], lw[k], acc);
            float ge = 0.5f * acc * (1.f + erff(acc * 0.70710678118654752f));
            store_split(d_Fhi, d_Flo, (size_t)g * GENEF + 320 + j, ge);
        }
    } else {
        int b = g - 2048;
        const float* pe = pert_emb + (size_t)pidx[b] * 128;
        for (int j = tid; j < GENEF; j += 128) {
            float acc = cond_b[j];
            const float* cw = cond_w + (size_t)j * 128;
            for (int k = 0; k < 128; k++) acc = fmaf(pe[k], cw[k], acc);
            store_split(d_Fhi, d_Flo, (size_t)g * GENEF + j, acc);
        }
    }
}

// ------------------------- 2a. weight conversions ----------------------------
__global__ void cvt_w(const float* __restrict__ fw, const float* __restrict__ bw) {
    int i = blockIdx.x * 256 + threadIdx.x;
    if (i >= DPROJ * DMODEL) return;
    store_split(d_Whi[0], d_Wlo[0], i, fw[i]);
    store_split(d_Whi[1], d_Wlo[1], i, bw[i]);
}
__global__ void cvt_inw(const float* __restrict__ iw) {
    int i = blockIdx.x * 256 + threadIdx.x;
    if (i >= DMODEL * GENEF) return;
    store_split(d_IWhi, d_IWlo, i, iw[i]);
}

// ------------------------- 2b. generalized tensor-core GEMM ------------------
// mode 0: A=feat(split), B=in_w(split), out=X split-bf16, M=NROWS,N=DMODEL,K=GENEF
// mode 1/2: A=X(split), B=W[dir](split), out=Z[dir] f32, M=NROWS,N=DPROJ,K=DMODEL
// Pointers resolved INSIDE the kernel (device globals are not host-passable).
__global__ __launch_bounds__(256) void hgemm(int mode, const float* __restrict__ bias) {
    const __nv_bfloat16 *Ah, *Al, *Bh, *Bl;
    float* Cf = nullptr;
    __nv_bfloat16 *Chi = nullptr, *Clo = nullptr;
    int M, N, K;
    if (mode == 0) {
        Ah = d_Fhi; Al = d_Flo; Bh = d_IWhi; Bl = d_IWlo;
        Chi = d_Xhi; Clo = d_Xlo;
        M = NROWS; N = DMODEL; K = GENEF;
    } else {
        int dir = mode - 1;
        Ah = d_Xhi; Al = d_Xlo; Bh = d_Whi[dir]; Bl = d_Wlo[dir];
        Cf = d_Z[dir];
        M = NROWS; N = DPROJ; K = DMODEL;
    }

    __shared__ __align__(16) __nv_bfloat16 sA[2][2][128 * SSTA];
    __shared__ __align__(16) __nv_bfloat16 sB[2][2][128 * SSTB];

    int tid = threadIdx.x;
    int row0 = blockIdx.y * 128;
    int col0 = blockIdx.x * 128;
    int lrow = tid >> 1;
    int seg = tid & 1;

    int arow = row0 + lrow;
    int brow = col0 + lrow;
    bool aval = arow < M;
    bool bval = brow < N;
    const uint4 z4 = make_uint4(0, 0, 0, 0);

    size_t abase = (size_t)arow * K + seg * 8;
    size_t bbase = (size_t)brow * K + seg * 8;

    uint4 rAh, rAl, rBh, rBl;
    rAh = aval ? *(const uint4*)(Ah + abase) : z4;
    rAl = aval ? *(const uint4*)(Al + abase) : z4;
    rBh = bval ? *(const uint4*)(Bh + bbase) : z4;
    rBl = bval ? *(const uint4*)(Bl + bbase) : z4;
    {
        *(uint4*)&sA[0][0][lrow * SSTA + seg * 8] = rAh;
        *(uint4*)&sA[0][1][lrow * SSTA + seg * 8] = rAl;
        char* db = (char*)&sB[0][0][0] + lrow * (SSTB * 2) + seg * 16;
        *(uint2*)db = make_uint2(rBh.x, rBh.y);
        *(uint2*)(db + 8) = make_uint2(rBh.z, rBh.w);
        char* dl = (char*)&sB[0][1][0] + lrow * (SSTB * 2) + seg * 16;
        *(uint2*)dl = make_uint2(rBl.x, rBl.y);
        *(uint2*)(dl + 8) = make_uint2(rBl.z, rBl.w);
    }
    __syncthreads();

    int w = tid >> 5, l = tid & 31;
    int mw = w >> 1, nw = w & 1;
    int g = l >> 2, q = l & 3;

    float c[2][8][4];
#pragma unroll
    for (int mt = 0; mt < 2; mt++)
#pragma unroll
        for (int nt = 0; nt < 8; nt++)
#pragma unroll
            for (int i = 0; i < 4; i++) c[mt][nt][i] = 0.f;

    const int NCH = K >> 4;
    for (int kc = 0; kc < NCH; kc++) {
        int buf = kc & 1;
        bool more = (kc + 1) < NCH;
        if (more) {
            size_t ao = abase + (size_t)(kc + 1) * 16;
            size_t bo = bbase + (size_t)(kc + 1) * 16;
            rAh = aval ? *(const uint4*)(Ah + ao) : z4;
            rAl = aval ? *(const uint4*)(Al + ao) : z4;
            rBh = bval ? *(const uint4*)(Bh + bo) : z4;
            rBl = bval ? *(const uint4*)(Bl + bo) : z4;
        }

        unsigned a[2][2][4], b[8][2][2];
#pragma unroll
        for (int mt = 0; mt < 2; mt++) {
            int r = mw * 32 + mt * 16 + g;
#pragma unroll
            for (int v = 0; v < 2; v++) {
                const __nv_bfloat16* base = sA[buf][v];
                a[mt][v][0] = *(const unsigned*)&base[r * SSTA + q * 2];
                a[mt][v][1] = *(const unsigned*)&base[(r + 8) * SSTA + q * 2];
                a[mt][v][2] = *(const unsigned*)&base[r * SSTA + q * 2 + 8];
                a[mt][v][3] = *(const unsigned*)&base[(r + 8) * SSTA + q * 2 + 8];
            }
        }
#pragma unroll
        for (int nt = 0; nt < 8; nt++) {
            int n = nw * 64 + nt * 8 + g;
#pragma unroll
            for (int v = 0; v < 2; v++) {
                const __nv_bfloat16* base = sB[buf][v];
                b[nt][v][0] = *(const unsigned*)&base[n * SSTB + q * 2];
                b[nt][v][1] = *(const unsigned*)&base[n * SSTB + q * 2 + 8];
            }
        }
#pragma unroll
        for (int mt = 0; mt < 2; mt++)
#pragma unroll
            for (int nt = 0; nt < 8; nt++) {
                MMA_BF16(c[mt][nt], a[mt][0], b[nt][0]);
                MMA_BF16(c[mt][nt], a[mt][0], b[nt][1]);
                MMA_BF16(c[mt][nt], a[mt][1], b[nt][0]);
            }

        if (more) {
            int nb = buf ^ 1;
            *(uint4*)&sA[nb][0][lrow * SSTA + seg * 8] = rAh;
            *(uint4*)&sA[nb][1][lrow * SSTA + seg * 8] = rAl;
            char* db = (char*)&sB[nb][0][0] + lrow * (SSTB * 2) + seg * 16;
            *(uint2*)db = make_uint2(rBh.x, rBh.y);
            *(uint2*)(db + 8) = make_uint2(rBh.z, rBh.w);
            char* dl = (char*)&sB[nb][1][0] + lrow * (SSTB * 2) + seg * 16;
            *(uint2*)dl = make_uint2(rBl.x, rBl.y);
            *(uint2*)(dl + 8) = make_uint2(rBl.z, rBl.w);
        }
        __syncthreads();
    }

#pragma unroll
    for (int mt = 0; mt < 2; mt++) {
        int r0 = row0 + mw * 32 + mt * 16 + g;
#pragma unroll
        for (int nt = 0; nt < 8; nt++) {
            int cc = col0 + nw * 64 + nt * 8 + q * 2;
            if (cc >= N) continue;
            float b0 = bias ? bias[cc] : 0.f;
            float b1 = bias ? bias[cc + 1] : 0.f;
#pragma unroll
            for (int half = 0; half < 2; half++) {
                int r = r0 + half * 8;
                if (r >= M) continue;
                float v0 = c[mt][nt][half * 2 + 0] + b0;
                float v1 = c[mt][nt][half * 2 + 1] + b1;
                if (Cf) {
                    *(float2*)&Cf[(size_t)r * N + cc] = make_float2(v0, v1);
                } else {
                    store_split(Chi, Clo, (size_t)r * N + cc, v0);
                    store_split(Chi, Clo, (size_t)r * N + cc + 1, v1);
                }
            }
        }
    }
}

// ------------------------- 3. causal depthwise conv + silu -------------------
__global__ void conv_kernel(const float* __restrict__ cw_f, const float* __restrict__ cb_f,
                            const float* __restrict__ cw_b, const float* __restrict__ cb_b) {
    int bx = blockIdx.x;
    int dir = blockIdx.y;
    const float* cw = dir ? cw_b : cw_f;
    const float* cb = dir ? cb_b : cb_f;
    const float* Z = d_Z[dir];

    const float* rows[4];
    float* dst;
    if (bx < L_SEQ) {
        int t = bx;
        if ((dir == 0 && t < 4) || (dir == 1 && t < 1)) return;
        dst = d_xBCs[dir] + (size_t)t * CONVD;
#pragma unroll
        for (int k = 0; k < 4; k++) {
            int tau = dir ? (t + 3 - k) : (t - 3 + k);
            rows[k] = (tau <= L_SEQ - 1) ? (Z + (size_t)(tau - 1) * DPROJ + DIN) : nullptr;
        }
    } else {
        if (dir == 1) return;
        int idx = bx - L_SEQ;
        int b = idx >> 2;
        int t = idx & 3;
        dst = d_xBC0 + (size_t)(b * 4 + t) * CONVD;
#pragma unroll
        for (int k = 0; k < 4; k++) {
            int tau = t - 3 + k;
            rows[k] = (tau >= 0) ? (Z + (size_t)seq_row(b, tau) * DPROJ + DIN) : nullptr;
        }
    }
    for (int c = threadIdx.x; c < CONVD; c += blockDim.x) {
        float acc = cb[c];
#pragma unroll
        for (int k = 0; k < 4; k++)
            if (rows[k]) acc = fmaf(rows[k][c], cw[c * 4 + k], acc);
        dst[c] = fast_silu(acc);
    }
}

// ------------------------- 4. dt / dA per row --------------------------------
__global__ void dtda_kernel(const float* __restrict__ fdtb, const float* __restrict__ fAl,
                            const float* __restrict__ bdtb, const float* __restrict__ bAl) {
    int idx = blockIdx.x * blockDim.x + threadIdx.x;
    const int per = NROWS * NH;
    if (idx >= 2 * per) return;
    int dir = idx / per;
    int r = idx % per;
    int row = r >> 4;
    int h = r & 15;
    float raw = d_Z[dir][(size_t)row * DPROJ + (DIN + CONVD) + h] + (dir ? bdtb : fdtb)[h];
    float dtv = (raw > 20.f) ? raw : log1pf(expf(raw));
    float Al = (dir ? bAl : fAl)[h];
    d_dtr[dir][row * NH + h] = dtv;
    d_dAr[dir][row * NH + h] = expf(-expf(Al) * dtv);
}

// ------------------------- 4b. fwd decay cumprod (parallel) ------------------
__global__ void decay_kernel() {
    int tid = threadIdx.x;    // 512
    int h = tid >> 5;
    int lane = tid & 31;
    int s0 = lane * 64;
    int len = (s0 < TCOR) ? ((TCOR - s0 < 64) ? (TCOR - s0) : 64) : 0;
    float prod = 1.f;
    for (int i = 0; i < len; i++) prod *= d_dAr[0][(size_t)(3 + s0 + i) * NH + h];
    float inc = prod;
#pragma unroll
    for (int off = 1; off < 32; off <<= 1) {
        float v = __shfl_up_sync(0xffffffffu, inc, off);
        if (lane >= off) inc *= v;
    }
    float excl = __shfl_up_sync(0xffffffffu, inc, 1);
    if (lane == 0) excl = 1.f;
    float run = excl;
    for (int i = 0; i < len; i++) {
        run *= d_dAr[0][(size_t)(3 + s0 + i) * NH + h];
        d_decayf[h * TCOR + s0 + i] = run;
    }
}

// ------------------------- 4c. W4 --------------------------------------------
__global__ void w4_kernel() {
    int idx = threadIdx.x;   // 512
    if (idx >= BATCH * NH * 4) return;
    int b = idx >> 6, h = (idx >> 2) & 15, tau = idx & 3;
    int row_tau = (tau == 0) ? (2048 + b) : (tau - 1);
    float w = d_dtr[0][row_tau * NH + h];
    for (int s = tau + 1; s < 4; s++)
        w *= d_dAr[0][(s - 1) * NH + h];
    d_W4[idx] = w;
}

// ------------------------- 4d. dotCB -----------------------------------------
__global__ void dotcb_kernel() {
    int t = blockIdx.x + 4;       // 4..2048
    __shared__ float sC[128];
    int tid = threadIdx.x;        // 256 = 8 warps
    if (tid < 128) sC[tid] = d_xBCs[0][(size_t)t * CONVD + DIN + NS + tid];
    __syncthreads();
    int w = tid >> 5, l = tid & 31;
    for (int c = w; c < 32; c += 8) {
        const float* B0 = d_xBC0 + (size_t)c * CONVD + DIN;
        float acc = 0.f;
#pragma unroll
        for (int i = 0; i < 4; i++) acc = fmaf(B0[i * 32 + l], sC[i * 32 + l], acc);
#pragma unroll
        for (int off = 16; off; off >>= 1)
            acc += __shfl_xor_sync(0xffffffffu, acc, off);
        if (l == 0) d_dotCB[t * 32 + c] = acc;
    }
}

// ------------------------- 5. combined output vector -------------------------
__global__ void wcomb_kernel(const float* __restrict__ head_w,
                             const float* __restrict__ fow, const float* __restrict__ bow,
                             const float* __restrict__ fnw, const float* __restrict__ bnw) {
    int idx = blockIdx.x * blockDim.x + threadIdx.x;
    if (idx >= 2 * DIN) return;
    int dir = idx >> 10;
    int j = idx & 1023;
    const float* ow = dir ? bow : fow;
    float acc = 0.f;
    for (int i = 0; i < DMODEL; i++) acc = fmaf(ow[(size_t)i * DIN + j], head_w[i], acc);
    d_wcomb[dir][j] = acc * (dir ? bnw : fnw)[j];
}

// ------------------------- 5b. silu(z) per gene row --------------------------
__global__ void siluz_kernel() {
    int row = blockIdx.x;
    int dir = blockIdx.y;
    const float* z = d_Z[dir] + (size_t)row * DPROJ;
    float* P = d_P[dir] + (size_t)row * DIN;
    for (int j = threadIdx.x; j < DIN; j += 256) P[j] = fast_silu(z[j]);
}

// ------------------------- 6a. fwd per-batch prefix scan (t=0..3) ------------
__global__ __launch_bounds__(128) void prefix_kernel(const float* __restrict__ fD) {
    int blk = blockIdx.x;
    int b = blk >> 4;
    int h = blk & 15;
    int tid = threadIdx.x;
    int p = tid & 63;
    int nh = tid >> 6;
    float Dh = fD[h];

    __shared__ __align__(16) float sB[128], sC[128], sx[64];

    unsigned long long hs2[32];
#pragma unroll
    for (int i = 0; i < 32; i++) hs2[i] = 0ull;

    for (int t = 0; t < 4; t++) {
        const float* pp = xbc_fwd_ptr(b, t);
        sB[tid] = pp[DIN + tid];
        sC[tid] = pp[DIN + NS + tid];
        if (tid < 64) sx[tid] = pp[h * HD + tid];
        __syncthreads();
        int row = (t == 0) ? (2048 + b) : (t - 1);
        float dtv = d_dtr[0][row * NH + h];
        float dAv = d_dAr[0][row * NH + h];
        float xv = sx[p];
        unsigned long long coef2 = pack2(dtv * xv);
        unsigned long long dA2 = pack2(dAv);
        const ulonglong2* B4 = (const ulonglong2*)(sB + nh * 64);
        const ulonglong2* C4 = (const ulonglong2*)(sC + nh * 64);
        unsigned long long a0 = 0ull, a1 = 0ull;
#pragma unroll
        for (int i = 0; i < 16; i++) {
            ulonglong2 bv = B4[i], cv = C4[i];
            unsigned long long tm;
            MUL2(tm, coef2, bv.x);
            FMA2(hs2[2 * i + 0], dA2, hs2[2 * i + 0], tm);
            FMA2(a0, hs2[2 * i + 0], cv.x, a0);
            MUL2(tm, coef2, bv.y);
            FMA2(hs2[2 * i + 1], dA2, hs2[2 * i + 1], tm);
            FMA2(a1, hs2[2 * i + 1], cv.y, a1);
        }
        ADD2(a0, a0, a1);
        float part = sum2(a0);
        if (nh == 0) part = fmaf(Dh, xv, part);
        if (t >= 1)
            d_ypre[((size_t)(b * 3 + (t - 1)) * 16 + h) * 128 + tid] = part;
        __syncthreads();
    }
}

// ------------------------- 6b. shared scans — p-split, no atomics ------------
// 256 blocks = (dir, h, p-eighth pq). 128 threads: p8 = tid&7, nsix = tid>>3.
// Thread owns 8 states (n = nsix*8..+7). Per-step partial -> shared sy;
// per-chunk reduction over the 16 nsix partials -> single STG per (t,p).
__global__ __launch_bounds__(128) void scan_shared(const float* __restrict__ fD,
                                                   const float* __restrict__ bD) {
    int blk = blockIdx.x;          // 0..255
    int dir = blk >> 7;
    int rest = blk & 127;
    int h = rest >> 3;
    int pq = rest & 7;
    int tid = threadIdx.x;
    int p8 = tid & 7;
    int nsix = tid >> 3;
    float Dh = (dir ? bD : fD)[h];
    const float* xbc = d_xBCs[dir];
    const float* dtr = d_dtr[dir];
    const float* dAr = d_dAr[dir];
    float* ysum = d_ysum[dir];

    int S = dir ? 2048 : TCOR;
    int nch = (S + TC - 1) / TC;

    __shared__ __align__(16) float sB[2][TC][128];
    __shared__ __align__(16) float sC[2][TC][128];
    __shared__ __align__(16) float sx[2][TC][8];
    __shared__ float sdt[2][TC], sdA[2][TC];
    __shared__ __align__(16) float sy[TC][128];

    unsigned long long hs2[4] = {0ull, 0ull, 0ull, 0ull};

    float4 rB[4], rC[4], rx;
    float rdt = 0.f, rdA = 0.f;

#define SCAN_LOAD(s0_)                                                          \
    {                                                                           \
        int lim = S - 1 - (s0_);                                                \
        _Pragma("unroll")                                                       \
        for (int k = 0; k < 4; k++) {                                           \
            int idx = tid + k * 128;                                            \
            int j = idx >> 5; if (j > lim) j = lim;                             \
            int tt = dir ? (2048 - ((s0_) + j)) : (4 + (s0_) + j);              \
            const float* rowp = xbc + (size_t)tt * CONVD + DIN;                 \
            rB[k] = ((const float4*)rowp)[idx & 31];                            \
            rC[k] = ((const float4*)(rowp + NS))[idx & 31];                     \
        }                                                                       \
        if (tid < 2 * TC) {                                                     \
            int j = tid >> 1; if (j > lim) j = lim;                             \
            int tt = dir ? (2048 - ((s0_) + j)) : (4 + (s0_) + j);              \
            rx = ((const float4*)(xbc + (size_t)tt * CONVD + h * HD + pq * 8))[tid & 1]; \
        }                                                                       \
        if (tid < TC) {                                                         \
            int j = (tid > lim) ? lim : tid;                                    \
            int tt = dir ? (2048 - ((s0_) + j)) : (4 + (s0_) + j);              \
            rdt = dtr[(tt - 1) * NH + h];                                       \
            rdA = dAr[(tt - 1) * NH + h];                                       \
        }                                                                       \
    }
#define SCAN_STORE(bb_)                                                         \
    {                                                                           \
        _Pragma("unroll")                                                       \
        for (int k = 0; k < 4; k++) {                                           \
            int idx = tid + k * 128;                                            \
            *(float4*)&sB[bb_][idx >> 5][(idx & 31) * 4] = rB[k];               \
            *(float4*)&sC[bb_][idx >> 5][(idx & 31) * 4] = rC[k];               \
        }                                                                       \
        if (tid < 2 * TC) *(float4*)&sx[bb_][tid >> 1][(tid & 1) * 4] = rx;     \
        if (tid < TC) { sdt[bb_][tid] = rdt; sdA[bb_][tid] = rdA; }             \
    }

    SCAN_LOAD(0);
    SCAN_STORE(0);
    __syncthreads();

    for (int c = 0; c < nch; c++) {
        int s0 = c * TC;
        int cnt = (S - s0 < TC) ? (S - s0) : TC;
        bool more = (c + 1) < nch;
        if (more) SCAN_LOAD(s0 + TC);
        int bb = c & 1;
        for (int j = 0; j < cnt; j++) {
            float xv = sx[bb][j][p8];
            unsigned long long coef2 = pack2(sdt[bb][j] * xv);
            unsigned long long dA2 = pack2(sdA[bb][j]);
            const ulonglong2* B4 = (const ulonglong2*)&sB[bb][j][nsix * 8];
            const ulonglong2* C4 = (const ulonglong2*)&sC[bb][j][nsix * 8];
            ulonglong2 bv0 = B4[0], cv0 = C4[0];
            ulonglong2 bv1 = B4[1], cv1 = C4[1];
            unsigned long long a0 = 0ull, a1 = 0ull, tm;
            MUL2(tm, coef2, bv0.x);
            FMA2(hs2[0], dA2, hs2[0], tm);
            FMA2(a0, hs2[0], cv0.x, a0);
            MUL2(tm, coef2, bv0.y);
            FMA2(hs2[1], dA2, hs2[1], tm);
            FMA2(a1, hs2[1], cv0.y, a1);
            MUL2(tm, coef2, bv1.x);
            FMA2(hs2[2], dA2, hs2[2], tm);
            FMA2(a0, hs2[2], cv1.x, a0);
            MUL2(tm, coef2, bv1.y);
            FMA2(hs2[3], dA2, hs2[3], tm);
            FMA2(a1, hs2[3], cv1.y, a1);
            ADD2(a0, a0, a1);
            sy[j][tid] = sum2(a0);
        }
        if (more) SCAN_STORE(bb ^ 1);
        __syncthreads();
        // reduce 16 nsix-partials -> one output per (j, p8)
        {
            int jo = tid >> 3;
            int po = tid & 7;
            if (jo < cnt) {
                const float* sp = &sy[jo][po];
                float s = 0.f;
#pragma unroll
                for (int k = 0; k < 16; k++) s += sp[k * 8];
                s = fmaf(Dh, sx[bb][jo][po], s);
                int tt = dir ? (2048 - (s0 + jo)) : (4 + s0 + jo);
                ysum[(size_t)tt * 1024 + h * 64 + pq * 8 + po] = s;
            }
        }
        __syncthreads();
    }
#undef SCAN_LOAD
#undef SCAN_STORE
}

// ------------------------- 7. gate + RMSnorm + fused head (per-t, all b) -----
__global__ __launch_bounds__(256) void final_kernel(const float* __restrict__ head_b,
                                                    float* __restrict__ out) {
    int t = blockIdx.x + 1;     // 1..2048
    int tid = threadIdx.x;      // 256
    __shared__ float cco[8][64];
    __shared__ float sh[8][18];

    if (t >= 4) {
        for (int i = tid; i < 512; i += 256) {
            int b = i >> 6;
            int r = i & 63;             // h*4+tau
            int hh = r >> 2, tau = r & 3;
            cco[b][r] = d_decayf[hh * TCOR + (t - 4)] *
                        d_W4[(b * 16 + hh) * 4 + tau] *
                        d_dotCB[t * 32 + b * 4 + tau];
        }
    }
    __syncthreads();

    int j0 = tid * 4;
    int h = tid >> 4;
    float4 ysf4 = *(const float4*)&d_ysum[0][(size_t)t * DIN + j0];
    float4 ysb4 = *(const float4*)&d_ysum[1][(size_t)t * DIN + j0];
    float4 pf4 = *(const float4*)&d_P[0][(size_t)(t - 1) * DIN + j0];
    float4 pb4 = *(const float4*)&d_P[1][(size_t)(t - 1) * DIN + j0];
    float4 w04 = *(const float4*)&d_wcomb[0][j0];
    float4 w14 = *(const float4*)&d_wcomb[1][j0];

    // backward: batch-shared
    float ssqb = 0.f, sdotb = 0.f;
    {
        float g;
        g = ysb4.x * pb4.x; ssqb = fmaf(g, g, ssqb); sdotb = fmaf(g, w14.x, sdotb);
        g = ysb4.y * pb4.y; ssqb = fmaf(g, g, ssqb); sdotb = fmaf(g, w14.y, sdotb);
        g = ysb4.z * pb4.z; ssqb = fmaf(g, g, ssqb); sdotb = fmaf(g, w14.z, sdotb);
        g = ysb4.w * pb4.w; ssqb = fmaf(g, g, ssqb); sdotb = fmaf(g, w14.w, sdotb);
    }

    float ssqf[8], sdotf[8];
    if (t >= 4) {
#pragma unroll
        for (int b = 0; b < 8; b++) {
            const float* xbb = d_xBC0 + (size_t)b * 4 * CONVD + j0;
            float4 x0 = *(const float4*)&xbb[0];
            float4 x1 = *(const float4*)&xbb[CONVD];
            float4 x2 = *(const float4*)&xbb[2 * CONVD];
            float4 x3 = *(const float4*)&xbb[3 * CONVD];
            float cc0 = cco[b][h * 4 + 0], cc1 = cco[b][h * 4 + 1];
            float cc2 = cco[b][h * 4 + 2], cc3 = cco[b][h * 4 + 3];
            float sq = 0.f, sd = 0.f, yf, g;
            yf = ysf4.x + cc0 * x0.x + cc1 * x1.x + cc2 * x2.x + cc3 * x3.x;
            g = yf * pf4.x; sq = fmaf(g, g, sq); sd = fmaf(g, w04.x, sd);
            yf = ysf4.y + cc0 * x0.y + cc1 * x1.y + cc2 * x2.y + cc3 * x3.y;
            g = yf * pf4.y; sq = fmaf(g, g, sq); sd = fmaf(g, w04.y, sd);
            yf = ysf4.z + cc0 * x0.z + cc1 * x1.z + cc2 * x2.z + cc3 * x3.z;
            g = yf * pf4.z; sq = fmaf(g, g, sq); sd = fmaf(g, w04.z, sd);
            yf = ysf4.w + cc0 * x0.w + cc1 * x1.w + cc2 * x2.w + cc3 * x3.w;
            g = yf * pf4.w; sq = fmaf(g, g, sq); sd = fmaf(g, w04.w, sd);
            ssqf[b] = sq; sdotf[b] = sd;
        }
    } else {
        int p0 = j0 & 63;
#pragma unroll
        for (int b = 0; b < 8; b++) {
            const float* yp = d_ypre + ((size_t)(b * 3 + (t - 1)) * 16 + h) * 128;
            float sq = 0.f, sd = 0.f;
            float pf[4] = {pf4.x, pf4.y, pf4.z, pf4.w};
            float w0[4] = {w04.x, w04.y, w04.z, w04.w};
#pragma unroll
            for (int k = 0; k < 4; k++) {
                float yf = yp[p0 + k] + yp[64 + p0 + k];
                float g = yf * pf[k];
                sq = fmaf(g, g, sq); sd = fmaf(g, w0[k], sd);
            }
            ssqf[b] = sq; sdotf[b] = sd;
        }
    }

#pragma unroll
    for (int off = 16; off; off >>= 1) {
        ssqb += __shfl_xor_sync(0xffffffffu, ssqb, off);
        sdotb += __shfl_xor_sync(0xffffffffu, sdotb, off);
#pragma unroll
        for (int b = 0; b < 8; b++) {
            ssqf[b] += __shfl_xor_sync(0xffffffffu, ssqf[b], off);
            sdotf[b] += __shfl_xor_sync(0xffffffffu, sdotf[b], off);
        }
    }
    int w = tid >> 5, l = tid & 31;
    if (l == 0) {
        sh[w][0] = ssqb; sh[w][1] = sdotb;
#pragma unroll
        for (int b = 0; b < 8; b++) { sh[w][2 + b] = ssqf[b]; sh[w][10 + b] = sdotf[b]; }
    }
    __syncthreads();
    if (tid < 8) {
        float qb = 0.f, db = 0.f, a = 0.f, d = 0.f;
        for (int i = 0; i < 8; i++) {
            qb += sh[i][0]; db += sh[i][1];
            a += sh[i][2 + tid]; d += sh[i][10 + tid];
        }
        float resb = rsqrtf(qb * (1.f / 1024.f) + 1e-5f) * db;
        float resf = rsqrtf(a * (1.f / 1024.f) + 1e-5f) * d;
        out[tid * 2048 + (t - 1)] = resf + resb + head_b[0];
    }
}

// ------------------------- launch --------------------------------------------
extern "C" void kernel_launch(void* const* d_in, const int* in_sizes, int n_in,
                              void* d_out, int out_size) {
    const int* pidx            = (const int*)d_in[0];
    const int* chridx          = (const int*)d_in[1];
    const float* locus_fourier = (const float*)d_in[2];
    const float* pathway       = (const float*)d_in[3];
    const float* pert_emb      = (const float*)d_in[4];
    const float* gene_id       = (const float*)d_in[5];
    const float* chr_emb       = (const float*)d_in[6];
    const float* locus_w       = (const float*)d_in[7];
    const float* locus_b       = (const float*)d_in[8];
    const float* cond_w        = (const float*)d_in[9];
    const float* cond_b        = (const float*)d_in[10];
    const float* in_w          = (const float*)d_in[11];
    const float* in_b          = (const float*)d_in[12];
    const float* head_w        = (const float*)d_in[13];
    const float* head_b        = (const float*)d_in[14];
    const float* f_in_w        = (const float*)d_in[15];
    const float* f_conv_w      = (const float*)d_in[16];
    const float* f_conv_b      = (const float*)d_in[17];
    const float* f_dt_bias     = (const float*)d_in[18];
    const float* f_A_log       = (const float*)d_in[19];
    const float* f_D           = (const float*)d_in[20];
    const float* f_norm_w      = (const float*)d_in[21];
    const float* f_out_w       = (const float*)d_in[22];
    const float* b_in_w        = (const float*)d_in[23];
    const float* b_conv_w      = (const float*)d_in[24];
    const float* b_conv_b      = (const float*)d_in[25];
    const float* b_dt_bias     = (const float*)d_in[26];
    const float* b_A_log       = (const float*)d_in[27];
    const float* b_D           = (const float*)d_in[28];
    const float* b_norm_w      = (const float*)d_in[29];
    const float* b_out_w       = (const float*)d_in[30];
    float* out = (float*)d_out;

    feat_kernel<<<NROWS, 128>>>(pidx, chridx, locus_fourier, pathway, pert_emb,
                                gene_id, chr_emb, locus_w, locus_b, cond_w, cond_b);
    cvt_inw<<<(DMODEL * GENEF + 255) / 256, 256>>>(in_w);
    cvt_w<<<(DPROJ * DMODEL + 255) / 256, 256>>>(f_in_w, b_in_w);

    // X = feat @ in_w^T + in_b (tensor cores; split-bf16 out)
    hgemm<<<dim3(4, 17), 256>>>(0, in_b);
    // Z_dir = X @ W^T (tensor cores; f32 out)
    hgemm<<<dim3(19, 17), 256>>>(1, nullptr);
    hgemm<<<dim3(19, 17), 256>>>(2, nullptr);

    conv_kernel<<<dim3(L_SEQ + 32, 2), 256>>>(f_conv_w, f_conv_b, b_conv_w, b_conv_b);

    dtda_kernel<<<(2 * NROWS * NH + 255) / 256, 256>>>(f_dt_bias, f_A_log, b_dt_bias, b_A_log);
    decay_kernel<<<1, 512>>>();
    w4_kernel<<<1, 512>>>();
    dotcb_kernel<<<TCOR, 256>>>();

    wcomb_kernel<<<(2 * DIN + 255) / 256, 256>>>(head_w, f_out_w, b_out_w, f_norm_w, b_norm_w);
    siluz_kernel<<<dim3(2048, 2), 256>>>();

    prefix_kernel<<<128, 128>>>(f_D);

    // p-split scans: block-internal n-reduction, single STG per output
    scan_shared<<<256, 128>>>(f_D, b_D);

    final_kernel<<<2048, 256>>>(head_b, out);
}

// round 12
// speedup vs baseline: 4.0293x; 1.0690x over previous
#include <cuda_runtime.h>
#include <cuda_bf16.h>
#include <math.h>

#define L_SEQ 2049
#define BATCH 8
#define NH 16
#define HD 64
#define NS 128
#define DIN 1024
#define CONVD 1280
#define DPROJ 2320
#define NROWS 2056
#define GENEF 384
#define DMODEL 512
#define TCOR 2045   // corrected timesteps t=4..2048
#define TC 16       // scan chunk length
#define SSTA 24     // hgemm shared stride (A), bf16 elems
#define SSTB 20     // hgemm shared stride (B), bf16 elems

// ------------------------- scratch (static device globals) -------------------
__device__ float d_Z[2][NROWS * DPROJ];
__device__ float d_xBCs[2][(size_t)L_SEQ * CONVD];   // batch-shared conv out
__device__ float d_xBC0[BATCH * 4 * CONVD];          // fwd per-batch conv out, t=0..3
__device__ float d_dtr[2][NROWS * NH];
__device__ float d_dAr[2][NROWS * NH];
__device__ float d_ysum[2][(size_t)L_SEQ * NH * 64]; // scan y (each elem written once)
__device__ float d_ypre[BATCH * 3 * NH * 128];       // fwd per-batch y (t=1..3), halves
__device__ float d_decayf[NH * TCOR];                // cumprod dA fwd, t=4..2048
__device__ float d_dotCB[L_SEQ * 32];                // C_t . B_tau  [t][b][tau]
__device__ float d_W4[BATCH * NH * 4];               // dt_tau * prod dA  [b][h][tau]
__device__ float d_P[2][(size_t)2048 * DIN];         // silu(z) per gene row
__device__ float d_wcomb[2][DIN];
// split-bf16 operands for tensor-core GEMMs
__device__ __nv_bfloat16 d_Fhi[NROWS * GENEF];
__device__ __nv_bfloat16 d_Flo[NROWS * GENEF];
__device__ __nv_bfloat16 d_IWhi[DMODEL * GENEF];
__device__ __nv_bfloat16 d_IWlo[DMODEL * GENEF];
__device__ __nv_bfloat16 d_Xhi[NROWS * DMODEL];
__device__ __nv_bfloat16 d_Xlo[NROWS * DMODEL];
__device__ __nv_bfloat16 d_Whi[2][DPROJ * DMODEL];
__device__ __nv_bfloat16 d_Wlo[2][DPROJ * DMODEL];

__device__ __forceinline__ int seq_row(int b, int t) {
    return (t == 0) ? (2048 + b) : (t - 1);
}
__device__ __forceinline__ const float* xbc_fwd_ptr(int b, int t) {
    return (t >= 4) ? (d_xBCs[0] + (size_t)t * CONVD)
                    : (d_xBC0 + (size_t)(b * 4 + t) * CONVD);
}
// silu via hw tanh: silu(x) = 0.5x(1+tanh(x/2)) — 1 MUFU instead of 2
__device__ __forceinline__ float fast_silu(float x) {
    float t;
    asm("tanh.approx.f32 %0, %1;" : "=f"(t) : "f"(x * 0.5f));
    return fmaf(0.5f * x, t, 0.5f * x);
}
__device__ __forceinline__ void store_split(__nv_bfloat16* hi, __nv_bfloat16* lo,
                                            size_t i, float v) {
    __nv_bfloat16 h = __float2bfloat16(v);
    hi[i] = h;
    lo[i] = __float2bfloat16(v - __bfloat162float(h));
}

// f32x2 packed math (sm_100+)
#define MUL2(d, a, b) asm("mul.rn.f32x2 %0,%1,%2;" : "=l"(d) : "l"(a), "l"(b))
#define FMA2(d, a, b, c) asm("fma.rn.f32x2 %0,%1,%2,%3;" : "=l"(d) : "l"(a), "l"(b), "l"(c))
#define ADD2(d, a, b) asm("add.rn.f32x2 %0,%1,%2;" : "=l"(d) : "l"(a), "l"(b))
__device__ __forceinline__ unsigned long long pack2(float x) {
    unsigned long long r;
    asm("mov.b64 %0,{%1,%1};" : "=l"(r) : "r"(__float_as_uint(x)));
    return r;
}
__device__ __forceinline__ float sum2(unsigned long long v) {
    unsigned int lo, hi;
    asm("mov.b64 {%0,%1},%2;" : "=r"(lo), "=r"(hi) : "l"(v));
    return __uint_as_float(lo) + __uint_as_float(hi);
}

// bf16 mma: D += A(m16k16) * B(n8k16)^T, f32 accum
#define MMA_BF16(cc, aa, bb) \
    asm volatile("mma.sync.aligned.m16n8k16.row.col.f32.bf16.bf16.f32 " \
        "{%0,%1,%2,%3}, {%4,%5,%6,%7}, {%8,%9}, {%0,%1,%2,%3};" \
        : "+f"((cc)[0]), "+f"((cc)[1]), "+f"((cc)[2]), "+f"((cc)[3]) \
        : "r"((aa)[0]), "r"((aa)[1]), "r"((aa)[2]), "r"((aa)[3]), \
          "r"((bb)[0]), "r"((bb)[1]))

// ------------------------- 1. feature rows (split-bf16 output) ---------------
__global__ void feat_kernel(const int* __restrict__ pidx,
                            const int* __restrict__ chridx,
                            const float* __restrict__ locus_fourier,
                            const float* __restrict__ pathway,
                            const float* __restrict__ pert_emb,
                            const float* __restrict__ gene_id,
                            const float* __restrict__ chr_emb,
                            const float* __restrict__ locus_w,
                            const float* __restrict__ locus_b,
                            const float* __restrict__ cond_w,
                            const float* __restrict__ cond_b) {
    int g = blockIdx.x;
    int tid = threadIdx.x;  // 128
    if (g < 2048) {
        store_split(d_Fhi, d_Flo, (size_t)g * GENEF + tid, gene_id[g * 128 + tid]);
        store_split(d_Fhi, d_Flo, (size_t)g * GENEF + 128 + tid, pathway[g * 128 + tid]);
        if (tid < 64) {
            int ci = chridx[g];
            store_split(d_Fhi, d_Flo, (size_t)g * GENEF + 256 + tid, chr_emb[ci * 64 + tid]);
        } else {
            int j = tid - 64;
            float acc = locus_b[j];
            const float* lf = locus_fourier + g * 64;
            const float* lw = locus_w + j * 64;
            for (int k = 0; k < 64; k++) acc = fmaf(lf[k], lw[k], acc);
            float ge = 0.5f * acc * (1.f + erff(acc * 0.70710678118654752f));
            store_split(d_Fhi, d_Flo, (size_t)g * GENEF + 320 + j, ge);
        }
    } else {
        int b = g - 2048;
        const float* pe = pert_emb + (size_t)pidx[b] * 128;
        for (int j = tid; j < GENEF; j += 128) {
            float acc = cond_b[j];
            const float* cw = cond_w + (size_t)j * 128;
            for (int k = 0; k < 128; k++) acc = fmaf(pe[k], cw[k], acc);
            store_split(d_Fhi, d_Flo, (size_t)g * GENEF + j, acc);
        }
    }
}

// ------------------------- 2a. weight conversions (merged) -------------------
__global__ void cvt_weights(const float* __restrict__ fw, const float* __restrict__ bw,
                            const float* __restrict__ iw) {
    int i = blockIdx.x * 256 + threadIdx.x;
    if (i < DPROJ * DMODEL) {
        store_split(d_Whi[0], d_Wlo[0], i, fw[i]);
        store_split(d_Whi[1], d_Wlo[1], i, bw[i]);
    }
    if (i < DMODEL * GENEF)
        store_split(d_IWhi, d_IWlo, i, iw[i]);
}

// ------------------------- 2b. tensor-core GEMM (templated tiles) ------------
// CFG 0: X-GEMM — BM=64, tile 64x128, grid (4, 33); A=feat, B=in_w, out split X.
// CFG 1: Z-GEMM — BM=128, tile 128x128, grid (19, 17, 2); dir = blockIdx.z.
template <int CFG>
__global__ __launch_bounds__(256) void hgemm(const float* __restrict__ bias) {
    constexpr int BM = (CFG == 0) ? 64 : 128;
    constexpr int MT = 2;
    constexpr int NT = (CFG == 0) ? 4 : 8;
    constexpr int NWC = (CFG == 0) ? 32 : 64;   // cols per n-warp

    const __nv_bfloat16 *Ah, *Al, *Bh, *Bl;
    float* Cf = nullptr;
    __nv_bfloat16 *Chi = nullptr, *Clo = nullptr;
    int M, N, K;
    if (CFG == 0) {
        Ah = d_Fhi; Al = d_Flo; Bh = d_IWhi; Bl = d_IWlo;
        Chi = d_Xhi; Clo = d_Xlo;
        M = NROWS; N = DMODEL; K = GENEF;
    } else {
        int dir = blockIdx.z;
        Ah = d_Xhi; Al = d_Xlo; Bh = d_Whi[dir]; Bl = d_Wlo[dir];
        Cf = d_Z[dir];
        M = NROWS; N = DPROJ; K = DMODEL;
    }

    __shared__ __align__(16) __nv_bfloat16 sA[2][2][128 * SSTA];
    __shared__ __align__(16) __nv_bfloat16 sB[2][2][128 * SSTB];

    int tid = threadIdx.x;
    int row0 = blockIdx.y * BM;
    int col0 = blockIdx.x * 128;
    int lrow = tid >> 1;
    int seg = tid & 1;
    int lrowA = lrow & (BM - 1);    // for BM=64 rows are staged twice (benign)

    int arow = row0 + lrowA;
    int brow = col0 + lrow;
    bool aval = arow < M;
    bool bval = brow < N;
    const uint4 z4 = make_uint4(0, 0, 0, 0);

    size_t abase = (size_t)arow * K + seg * 8;
    size_t bbase = (size_t)brow * K + seg * 8;

    uint4 rAh, rAl, rBh, rBl;
    rAh = aval ? *(const uint4*)(Ah + abase) : z4;
    rAl = aval ? *(const uint4*)(Al + abase) : z4;
    rBh = bval ? *(const uint4*)(Bh + bbase) : z4;
    rBl = bval ? *(const uint4*)(Bl + bbase) : z4;
    {
        *(uint4*)&sA[0][0][lrow * SSTA + seg * 8] = rAh;
        *(uint4*)&sA[0][1][lrow * SSTA + seg * 8] = rAl;
        char* db = (char*)&sB[0][0][0] + lrow * (SSTB * 2) + seg * 16;
        *(uint2*)db = make_uint2(rBh.x, rBh.y);
        *(uint2*)(db + 8) = make_uint2(rBh.z, rBh.w);
        char* dl = (char*)&sB[0][1][0] + lrow * (SSTB * 2) + seg * 16;
        *(uint2*)dl = make_uint2(rBl.x, rBl.y);
        *(uint2*)(dl + 8) = make_uint2(rBl.z, rBl.w);
    }
    __syncthreads();

    int w = tid >> 5, l = tid & 31;
    int mw = (CFG == 0) ? (w >> 2) : (w >> 1);
    int nw = (CFG == 0) ? (w & 3) : (w & 1);
    int g = l >> 2, q = l & 3;

    float c[MT][NT][4];
#pragma unroll
    for (int mt = 0; mt < MT; mt++)
#pragma unroll
        for (int nt = 0; nt < NT; nt++)
#pragma unroll
            for (int i = 0; i < 4; i++) c[mt][nt][i] = 0.f;

    const int NCH = K >> 4;
    for (int kc = 0; kc < NCH; kc++) {
        int buf = kc & 1;
        bool more = (kc + 1) < NCH;
        if (more) {
            size_t ao = abase + (size_t)(kc + 1) * 16;
            size_t bo = bbase + (size_t)(kc + 1) * 16;
            rAh = aval ? *(const uint4*)(Ah + ao) : z4;
            rAl = aval ? *(const uint4*)(Al + ao) : z4;
            rBh = bval ? *(const uint4*)(Bh + bo) : z4;
            rBl = bval ? *(const uint4*)(Bl + bo) : z4;
        }

        unsigned a[MT][2][4], b[NT][2][2];
#pragma unroll
        for (int mt = 0; mt < MT; mt++) {
            int r = mw * 32 + mt * 16 + g;
#pragma unroll
            for (int v = 0; v < 2; v++) {
                const __nv_bfloat16* base = sA[buf][v];
                a[mt][v][0] = *(const unsigned*)&base[r * SSTA + q * 2];
                a[mt][v][1] = *(const unsigned*)&base[(r + 8) * SSTA + q * 2];
                a[mt][v][2] = *(const unsigned*)&base[r * SSTA + q * 2 + 8];
                a[mt][v][3] = *(const unsigned*)&base[(r + 8) * SSTA + q * 2 + 8];
            }
        }
#pragma unroll
        for (int nt = 0; nt < NT; nt++) {
            int n = nw * NWC + nt * 8 + g;
#pragma unroll
            for (int v = 0; v < 2; v++) {
                const __nv_bfloat16* base = sB[buf][v];
                b[nt][v][0] = *(const unsigned*)&base[n * SSTB + q * 2];
                b[nt][v][1] = *(const unsigned*)&base[n * SSTB + q * 2 + 8];
            }
        }
#pragma unroll
        for (int mt = 0; mt < MT; mt++)
#pragma unroll
            for (int nt = 0; nt < NT; nt++) {
                MMA_BF16(c[mt][nt], a[mt][0], b[nt][0]);
                MMA_BF16(c[mt][nt], a[mt][0], b[nt][1]);
                MMA_BF16(c[mt][nt], a[mt][1], b[nt][0]);
            }

        if (more) {
            int nb = buf ^ 1;
            *(uint4*)&sA[nb][0][lrow * SSTA + seg * 8] = rAh;
            *(uint4*)&sA[nb][1][lrow * SSTA + seg * 8] = rAl;
            char* db = (char*)&sB[nb][0][0] + lrow * (SSTB * 2) + seg * 16;
            *(uint2*)db = make_uint2(rBh.x, rBh.y);
            *(uint2*)(db + 8) = make_uint2(rBh.z, rBh.w);
            char* dl = (char*)&sB[nb][1][0] + lrow * (SSTB * 2) + seg * 16;
            *(uint2*)dl = make_uint2(rBl.x, rBl.y);
            *(uint2*)(dl + 8) = make_uint2(rBl.z, rBl.w);
        }
        __syncthreads();
    }

#pragma unroll
    for (int mt = 0; mt < MT; mt++) {
        int r0 = row0 + mw * 32 + mt * 16 + g;
#pragma unroll
        for (int nt = 0; nt < NT; nt++) {
            int cc = col0 + nw * NWC + nt * 8 + q * 2;
            if (cc >= N) continue;
            float b0 = bias ? bias[cc] : 0.f;
            float b1 = bias ? bias[cc + 1] : 0.f;
#pragma unroll
            for (int half = 0; half < 2; half++) {
                int r = r0 + half * 8;
                if (r >= M) continue;
                float v0 = c[mt][nt][half * 2 + 0] + b0;
                float v1 = c[mt][nt][half * 2 + 1] + b1;
                if (CFG != 0) {
                    *(float2*)&Cf[(size_t)r * N + cc] = make_float2(v0, v1);
                } else {
                    store_split(Chi, Clo, (size_t)r * N + cc, v0);
                    store_split(Chi, Clo, (size_t)r * N + cc + 1, v1);
                }
            }
        }
    }
}

// ------------------------- 3. causal depthwise conv + silu -------------------
__global__ void conv_kernel(const float* __restrict__ cw_f, const float* __restrict__ cb_f,
                            const float* __restrict__ cw_b, const float* __restrict__ cb_b) {
    int bx = blockIdx.x;
    int dir = blockIdx.y;
    const float* cw = dir ? cw_b : cw_f;
    const float* cb = dir ? cb_b : cb_f;
    const float* Z = d_Z[dir];

    const float* rows[4];
    float* dst;
    if (bx < L_SEQ) {
        int t = bx;
        if ((dir == 0 && t < 4) || (dir == 1 && t < 1)) return;
        dst = d_xBCs[dir] + (size_t)t * CONVD;
#pragma unroll
        for (int k = 0; k < 4; k++) {
            int tau = dir ? (t + 3 - k) : (t - 3 + k);
            rows[k] = (tau <= L_SEQ - 1) ? (Z + (size_t)(tau - 1) * DPROJ + DIN) : nullptr;
        }
    } else {
        if (dir == 1) return;
        int idx = bx - L_SEQ;
        int b = idx >> 2;
        int t = idx & 3;
        dst = d_xBC0 + (size_t)(b * 4 + t) * CONVD;
#pragma unroll
        for (int k = 0; k < 4; k++) {
            int tau = t - 3 + k;
            rows[k] = (tau >= 0) ? (Z + (size_t)seq_row(b, tau) * DPROJ + DIN) : nullptr;
        }
    }
    for (int c = threadIdx.x; c < CONVD; c += blockDim.x) {
        float acc = cb[c];
#pragma unroll
        for (int k = 0; k < 4; k++)
            if (rows[k]) acc = fmaf(rows[k][c], cw[c * 4 + k], acc);
        dst[c] = fast_silu(acc);
    }
}

// ------------------------- 4. dt / dA per row --------------------------------
__global__ void dtda_kernel(const float* __restrict__ fdtb, const float* __restrict__ fAl,
                            const float* __restrict__ bdtb, const float* __restrict__ bAl) {
    int idx = blockIdx.x * blockDim.x + threadIdx.x;
    const int per = NROWS * NH;
    if (idx >= 2 * per) return;
    int dir = idx / per;
    int r = idx % per;
    int row = r >> 4;
    int h = r & 15;
    float raw = d_Z[dir][(size_t)row * DPROJ + (DIN + CONVD) + h] + (dir ? bdtb : fdtb)[h];
    float dtv = (raw > 20.f) ? raw : log1pf(expf(raw));
    float Al = (dir ? bAl : fAl)[h];
    d_dtr[dir][row * NH + h] = dtv;
    d_dAr[dir][row * NH + h] = expf(-expf(Al) * dtv);
}

// ------------------------- 4b. fwd decay cumprod (parallel) ------------------
__global__ void decay_kernel() {
    int tid = threadIdx.x;    // 512
    int h = tid >> 5;
    int lane = tid & 31;
    int s0 = lane * 64;
    int len = (s0 < TCOR) ? ((TCOR - s0 < 64) ? (TCOR - s0) : 64) : 0;
    float prod = 1.f;
    for (int i = 0; i < len; i++) prod *= d_dAr[0][(size_t)(3 + s0 + i) * NH + h];
    float inc = prod;
#pragma unroll
    for (int off = 1; off < 32; off <<= 1) {
        float v = __shfl_up_sync(0xffffffffu, inc, off);
        if (lane >= off) inc *= v;
    }
    float excl = __shfl_up_sync(0xffffffffu, inc, 1);
    if (lane == 0) excl = 1.f;
    float run = excl;
    for (int i = 0; i < len; i++) {
        run *= d_dAr[0][(size_t)(3 + s0 + i) * NH + h];
        d_decayf[h * TCOR + s0 + i] = run;
    }
}

// ------------------------- 4c. W4 --------------------------------------------
__global__ void w4_kernel() {
    int idx = threadIdx.x;   // 512
    if (idx >= BATCH * NH * 4) return;
    int b = idx >> 6, h = (idx >> 2) & 15, tau = idx & 3;
    int row_tau = (tau == 0) ? (2048 + b) : (tau - 1);
    float w = d_dtr[0][row_tau * NH + h];
    for (int s = tau + 1; s < 4; s++)
        w *= d_dAr[0][(s - 1) * NH + h];
    d_W4[idx] = w;
}

// ------------------------- 4d. dotCB -----------------------------------------
__global__ void dotcb_kernel() {
    int t = blockIdx.x + 4;       // 4..2048
    __shared__ float sC[128];
    int tid = threadIdx.x;        // 256 = 8 warps
    if (tid < 128) sC[tid] = d_xBCs[0][(size_t)t * CONVD + DIN + NS + tid];
    __syncthreads();
    int w = tid >> 5, l = tid & 31;
    for (int c = w; c < 32; c += 8) {
        const float* B0 = d_xBC0 + (size_t)c * CONVD + DIN;
        float acc = 0.f;
#pragma unroll
        for (int i = 0; i < 4; i++) acc = fmaf(B0[i * 32 + l], sC[i * 32 + l], acc);
#pragma unroll
        for (int off = 16; off; off >>= 1)
            acc += __shfl_xor_sync(0xffffffffu, acc, off);
        if (l == 0) d_dotCB[t * 32 + c] = acc;
    }
}

// ------------------------- 5. combined output vector -------------------------
__global__ void wcomb_kernel(const float* __restrict__ head_w,
                             const float* __restrict__ fow, const float* __restrict__ bow,
                             const float* __restrict__ fnw, const float* __restrict__ bnw) {
    int idx = blockIdx.x * blockDim.x + threadIdx.x;
    if (idx >= 2 * DIN) return;
    int dir = idx >> 10;
    int j = idx & 1023;
    const float* ow = dir ? bow : fow;
    float acc = 0.f;
    for (int i = 0; i < DMODEL; i++) acc = fmaf(ow[(size_t)i * DIN + j], head_w[i], acc);
    d_wcomb[dir][j] = acc * (dir ? bnw : fnw)[j];
}

// ------------------------- 5b. silu(z) per gene row --------------------------
__global__ void siluz_kernel() {
    int row = blockIdx.x;
    int dir = blockIdx.y;
    const float* z = d_Z[dir] + (size_t)row * DPROJ;
    float* P = d_P[dir] + (size_t)row * DIN;
    for (int j = threadIdx.x; j < DIN; j += 256) P[j] = fast_silu(z[j]);
}

// ------------------------- 6a. fwd per-batch prefix scan (t=0..3) ------------
__global__ __launch_bounds__(128) void prefix_kernel(const float* __restrict__ fD) {
    int blk = blockIdx.x;
    int b = blk >> 4;
    int h = blk & 15;
    int tid = threadIdx.x;
    int p = tid & 63;
    int nh = tid >> 6;
    float Dh = fD[h];

    __shared__ __align__(16) float sB[128], sC[128], sx[64];

    unsigned long long hs2[32];
#pragma unroll
    for (int i = 0; i < 32; i++) hs2[i] = 0ull;

    for (int t = 0; t < 4; t++) {
        const float* pp = xbc_fwd_ptr(b, t);
        sB[tid] = pp[DIN + tid];
        sC[tid] = pp[DIN + NS + tid];
        if (tid < 64) sx[tid] = pp[h * HD + tid];
        __syncthreads();
        int row = (t == 0) ? (2048 + b) : (t - 1);
        float dtv = d_dtr[0][row * NH + h];
        float dAv = d_dAr[0][row * NH + h];
        float xv = sx[p];
        unsigned long long coef2 = pack2(dtv * xv);
        unsigned long long dA2 = pack2(dAv);
        const ulonglong2* B4 = (const ulonglong2*)(sB + nh * 64);
        const ulonglong2* C4 = (const ulonglong2*)(sC + nh * 64);
        unsigned long long a0 = 0ull, a1 = 0ull;
#pragma unroll
        for (int i = 0; i < 16; i++) {
            ulonglong2 bv = B4[i], cv = C4[i];
            unsigned long long tm;
            MUL2(tm, coef2, bv.x);
            FMA2(hs2[2 * i + 0], dA2, hs2[2 * i + 0], tm);
            FMA2(a0, hs2[2 * i + 0], cv.x, a0);
            MUL2(tm, coef2, bv.y);
            FMA2(hs2[2 * i + 1], dA2, hs2[2 * i + 1], tm);
            FMA2(a1, hs2[2 * i + 1], cv.y, a1);
        }
        ADD2(a0, a0, a1);
        float part = sum2(a0);
        if (nh == 0) part = fmaf(Dh, xv, part);
        if (t >= 1)
            d_ypre[((size_t)(b * 3 + (t - 1)) * 16 + h) * 128 + tid] = part;
        __syncthreads();
    }
}

// ------------------------- 6b. shared scans — p-split, no atomics ------------
__global__ __launch_bounds__(128) void scan_shared(const float* __restrict__ fD,
                                                   const float* __restrict__ bD) {
    int blk = blockIdx.x;          // 0..255
    int dir = blk >> 7;
    int rest = blk & 127;
    int h = rest >> 3;
    int pq = rest & 7;
    int tid = threadIdx.x;
    int p8 = tid & 7;
    int nsix = tid >> 3;
    float Dh = (dir ? bD : fD)[h];
    const float* xbc = d_xBCs[dir];
    const float* dtr = d_dtr[dir];
    const float* dAr = d_dAr[dir];
    float* ysum = d_ysum[dir];

    int S = dir ? 2048 : TCOR;
    int nch = (S + TC - 1) / TC;

    __shared__ __align__(16) float sB[2][TC][128];
    __shared__ __align__(16) float sC[2][TC][128];
    __shared__ __align__(16) float sx[2][TC][8];
    __shared__ float sdt[2][TC], sdA[2][TC];
    __shared__ __align__(16) float sy[TC][128];

    unsigned long long hs2[4] = {0ull, 0ull, 0ull, 0ull};

    float4 rB[4], rC[4], rx;
    float rdt = 0.f, rdA = 0.f;

#define SCAN_LOAD(s0_)                                                          \
    {                                                                           \
        int lim = S - 1 - (s0_);                                                \
        _Pragma("unroll")                                                       \
        for (int k = 0; k < 4; k++) {                                           \
            int idx = tid + k * 128;                                            \
            int j = idx >> 5; if (j > lim) j = lim;                             \
            int tt = dir ? (2048 - ((s0_) + j)) : (4 + (s0_) + j);              \
            const float* rowp = xbc + (size_t)tt * CONVD + DIN;                 \
            rB[k] = ((const float4*)rowp)[idx & 31];                            \
            rC[k] = ((const float4*)(rowp + NS))[idx & 31];                     \
        }                                                                       \
        if (tid < 2 * TC) {                                                     \
            int j = tid >> 1; if (j > lim) j = lim;                             \
            int tt = dir ? (2048 - ((s0_) + j)) : (4 + (s0_) + j);              \
            rx = ((const float4*)(xbc + (size_t)tt * CONVD + h * HD + pq * 8))[tid & 1]; \
        }                                                                       \
        if (tid < TC) {                                                         \
            int j = (tid > lim) ? lim : tid;                                    \
            int tt = dir ? (2048 - ((s0_) + j)) : (4 + (s0_) + j);              \
            rdt = dtr[(tt - 1) * NH + h];                                       \
            rdA = dAr[(tt - 1) * NH + h];                                       \
        }                                                                       \
    }
#define SCAN_STORE(bb_)                                                         \
    {                                                                           \
        _Pragma("unroll")                                                       \
        for (int k = 0; k < 4; k++) {                                           \
            int idx = tid + k * 128;                                            \
            *(float4*)&sB[bb_][idx >> 5][(idx & 31) * 4] = rB[k];               \
            *(float4*)&sC[bb_][idx >> 5][(idx & 31) * 4] = rC[k];               \
        }                                                                       \
        if (tid < 2 * TC) *(float4*)&sx[bb_][tid >> 1][(tid & 1) * 4] = rx;     \
        if (tid < TC) { sdt[bb_][tid] = rdt; sdA[bb_][tid] = rdA; }             \
    }

    SCAN_LOAD(0);
    SCAN_STORE(0);
    __syncthreads();

    for (int c = 0; c < nch; c++) {
        int s0 = c * TC;
        int cnt = (S - s0 < TC) ? (S - s0) : TC;
        bool more = (c + 1) < nch;
        if (more) SCAN_LOAD(s0 + TC);
        int bb = c & 1;
        for (int j = 0; j < cnt; j++) {
            float xv = sx[bb][j][p8];
            unsigned long long coef2 = pack2(sdt[bb][j] * xv);
            unsigned long long dA2 = pack2(sdA[bb][j]);
            const ulonglong2* B4 = (const ulonglong2*)&sB[bb][j][nsix * 8];
            const ulonglong2* C4 = (const ulonglong2*)&sC[bb][j][nsix * 8];
            ulonglong2 bv0 = B4[0], cv0 = C4[0];
            ulonglong2 bv1 = B4[1], cv1 = C4[1];
            unsigned long long a0 = 0ull, a1 = 0ull, tm;
            MUL2(tm, coef2, bv0.x);
            FMA2(hs2[0], dA2, hs2[0], tm);
            FMA2(a0, hs2[0], cv0.x, a0);
            MUL2(tm, coef2, bv0.y);
            FMA2(hs2[1], dA2, hs2[1], tm);
            FMA2(a1, hs2[1], cv0.y, a1);
            MUL2(tm, coef2, bv1.x);
            FMA2(hs2[2], dA2, hs2[2], tm);
            FMA2(a0, hs2[2], cv1.x, a0);
            MUL2(tm, coef2, bv1.y);
            FMA2(hs2[3], dA2, hs2[3], tm);
            FMA2(a1, hs2[3], cv1.y, a1);
            ADD2(a0, a0, a1);
            sy[j][tid] = sum2(a0);
        }
        if (more) SCAN_STORE(bb ^ 1);
        __syncthreads();
        {
            int jo = tid >> 3;
            int po = tid & 7;
            if (jo < cnt) {
                const float* sp = &sy[jo][po];
                float s = 0.f;
#pragma unroll
                for (int k = 0; k < 16; k++) s += sp[k * 8];
                s = fmaf(Dh, sx[bb][jo][po], s);
                int tt = dir ? (2048 - (s0 + jo)) : (4 + s0 + jo);
                ysum[(size_t)tt * 1024 + h * 64 + pq * 8 + po] = s;
            }
        }
        __syncthreads();
    }
#undef SCAN_LOAD
#undef SCAN_STORE
}

// ------------------------- 7. gate + RMSnorm + fused head (per-t, all b) -----
__global__ __launch_bounds__(256) void final_kernel(const float* __restrict__ head_b,
                                                    float* __restrict__ out) {
    int t = blockIdx.x + 1;     // 1..2048
    int tid = threadIdx.x;      // 256
    __shared__ float cco[8][64];
    __shared__ float sh[8][18];

    if (t >= 4) {
        for (int i = tid; i < 512; i += 256) {
            int b = i >> 6;
            int r = i & 63;             // h*4+tau
            int hh = r >> 2, tau = r & 3;
            cco[b][r] = d_decayf[hh * TCOR + (t - 4)] *
                        d_W4[(b * 16 + hh) * 4 + tau] *
                        d_dotCB[t * 32 + b * 4 + tau];
        }
    }
    __syncthreads();

    int j0 = tid * 4;
    int h = tid >> 4;
    float4 ysf4 = *(const float4*)&d_ysum[0][(size_t)t * DIN + j0];
    float4 ysb4 = *(const float4*)&d_ysum[1][(size_t)t * DIN + j0];
    float4 pf4 = *(const float4*)&d_P[0][(size_t)(t - 1) * DIN + j0];
    float4 pb4 = *(const float4*)&d_P[1][(size_t)(t - 1) * DIN + j0];
    float4 w04 = *(const float4*)&d_wcomb[0][j0];
    float4 w14 = *(const float4*)&d_wcomb[1][j0];

    float ssqb = 0.f, sdotb = 0.f;
    {
        float g;
        g = ysb4.x * pb4.x; ssqb = fmaf(g, g, ssqb); sdotb = fmaf(g, w14.x, sdotb);
        g = ysb4.y * pb4.y; ssqb = fmaf(g, g, ssqb); sdotb = fmaf(g, w14.y, sdotb);
        g = ysb4.z * pb4.z; ssqb = fmaf(g, g, ssqb); sdotb = fmaf(g, w14.z, sdotb);
        g = ysb4.w * pb4.w; ssqb = fmaf(g, g, ssqb); sdotb = fmaf(g, w14.w, sdotb);
    }

    float ssqf[8], sdotf[8];
    if (t >= 4) {
#pragma unroll
        for (int b = 0; b < 8; b++) {
            const float* xbb = d_xBC0 + (size_t)b * 4 * CONVD + j0;
            float4 x0 = *(const float4*)&xbb[0];
            float4 x1 = *(const float4*)&xbb[CONVD];
            float4 x2 = *(const float4*)&xbb[2 * CONVD];
            float4 x3 = *(const float4*)&xbb[3 * CONVD];
            float cc0 = cco[b][h * 4 + 0], cc1 = cco[b][h * 4 + 1];
            float cc2 = cco[b][h * 4 + 2], cc3 = cco[b][h * 4 + 3];
            float sq = 0.f, sd = 0.f, yf, g;
            yf = ysf4.x + cc0 * x0.x + cc1 * x1.x + cc2 * x2.x + cc3 * x3.x;
            g = yf * pf4.x; sq = fmaf(g, g, sq); sd = fmaf(g, w04.x, sd);
            yf = ysf4.y + cc0 * x0.y + cc1 * x1.y + cc2 * x2.y + cc3 * x3.y;
            g = yf * pf4.y; sq = fmaf(g, g, sq); sd = fmaf(g, w04.y, sd);
            yf = ysf4.z + cc0 * x0.z + cc1 * x1.z + cc2 * x2.z + cc3 * x3.z;
            g = yf * pf4.z; sq = fmaf(g, g, sq); sd = fmaf(g, w04.z, sd);
            yf = ysf4.w + cc0 * x0.w + cc1 * x1.w + cc2 * x2.w + cc3 * x3.w;
            g = yf * pf4.w; sq = fmaf(g, g, sq); sd = fmaf(g, w04.w, sd);
            ssqf[b] = sq; sdotf[b] = sd;
        }
    } else {
        int p0 = j0 & 63;
#pragma unroll
        for (int b = 0; b < 8; b++) {
            const float* yp = d_ypre + ((size_t)(b * 3 + (t - 1)) * 16 + h) * 128;
            float sq = 0.f, sd = 0.f;
            float pf[4] = {pf4.x, pf4.y, pf4.z, pf4.w};
            float w0[4] = {w04.x, w04.y, w04.z, w04.w};
#pragma unroll
            for (int k = 0; k < 4; k++) {
                float yf = yp[p0 + k] + yp[64 + p0 + k];
                float g = yf * pf[k];
                sq = fmaf(g, g, sq); sd = fmaf(g, w0[k], sd);
            }
            ssqf[b] = sq; sdotf[b] = sd;
        }
    }

#pragma unroll
    for (int off = 16; off; off >>= 1) {
        ssqb += __shfl_xor_sync(0xffffffffu, ssqb, off);
        sdotb += __shfl_xor_sync(0xffffffffu, sdotb, off);
#pragma unroll
        for (int b = 0; b < 8; b++) {
            ssqf[b] += __shfl_xor_sync(0xffffffffu, ssqf[b], off);
            sdotf[b] += __shfl_xor_sync(0xffffffffu, sdotf[b], off);
        }
    }
    int w = tid >> 5, l = tid & 31;
    if (l == 0) {
        sh[w][0] = ssqb; sh[w][1] = sdotb;
#pragma unroll
        for (int b = 0; b < 8; b++) { sh[w][2 + b] = ssqf[b]; sh[w][10 + b] = sdotf[b]; }
    }
    __syncthreads();
    if (tid < 8) {
        float qb = 0.f, db = 0.f, a = 0.f, d = 0.f;
        for (int i = 0; i < 8; i++) {
            qb += sh[i][0]; db += sh[i][1];
            a += sh[i][2 + tid]; d += sh[i][10 + tid];
        }
        float resb = rsqrtf(qb * (1.f / 1024.f) + 1e-5f) * db;
        float resf = rsqrtf(a * (1.f / 1024.f) + 1e-5f) * d;
        out[tid * 2048 + (t - 1)] = resf + resb + head_b[0];
    }
}

// ------------------------- launch --------------------------------------------
extern "C" void kernel_launch(void* const* d_in, const int* in_sizes, int n_in,
                              void* d_out, int out_size) {
    const int* pidx            = (const int*)d_in[0];
    const int* chridx          = (const int*)d_in[1];
    const float* locus_fourier = (const float*)d_in[2];
    const float* pathway       = (const float*)d_in[3];
    const float* pert_emb      = (const float*)d_in[4];
    const float* gene_id       = (const float*)d_in[5];
    const float* chr_emb       = (const float*)d_in[6];
    const float* locus_w       = (const float*)d_in[7];
    const float* locus_b       = (const float*)d_in[8];
    const float* cond_w        = (const float*)d_in[9];
    const float* cond_b        = (const float*)d_in[10];
    const float* in_w          = (const float*)d_in[11];
    const float* in_b          = (const float*)d_in[12];
    const float* head_w        = (const float*)d_in[13];
    const float* head_b        = (const float*)d_in[14];
    const float* f_in_w        = (const float*)d_in[15];
    const float* f_conv_w      = (const float*)d_in[16];
    const float* f_conv_b      = (const float*)d_in[17];
    const float* f_dt_bias     = (const float*)d_in[18];
    const float* f_A_log       = (const float*)d_in[19];
    const float* f_D           = (const float*)d_in[20];
    const float* f_norm_w      = (const float*)d_in[21];
    const float* f_out_w       = (const float*)d_in[22];
    const float* b_in_w        = (const float*)d_in[23];
    const float* b_conv_w      = (const float*)d_in[24];
    const float* b_conv_b      = (const float*)d_in[25];
    const float* b_dt_bias     = (const float*)d_in[26];
    const float* b_A_log       = (const float*)d_in[27];
    const float* b_D           = (const float*)d_in[28];
    const float* b_norm_w      = (const float*)d_in[29];
    const float* b_out_w       = (const float*)d_in[30];
    float* out = (float*)d_out;

    feat_kernel<<<NROWS, 128>>>(pidx, chridx, locus_fourier, pathway, pert_emb,
                                gene_id, chr_emb, locus_w, locus_b, cond_w, cond_b);
    cvt_weights<<<(DPROJ * DMODEL + 255) / 256, 256>>>(f_in_w, b_in_w, in_w);

    // X = feat @ in_w^T + in_b (64x128 tiles, fills chip)
    hgemm<0><<<dim3(4, 33), 256>>>(in_b);
    // Z_dir = X @ W^T (128x128 tiles, both dirs in one launch)
    hgemm<1><<<dim3(19, 17, 2), 256>>>(nullptr);

    conv_kernel<<<dim3(L_SEQ + 32, 2), 256>>>(f_conv_w, f_conv_b, b_conv_w, b_conv_b);

    dtda_kernel<<<(2 * NROWS * NH + 255) / 256, 256>>>(f_dt_bias, f_A_log, b_dt_bias, b_A_log);
    decay_kernel<<<1, 512>>>();
    w4_kernel<<<1, 512>>>();
    dotcb_kernel<<<TCOR, 256>>>();

    wcomb_kernel<<<(2 * DIN + 255) / 256, 256>>>(head_w, f_out_w, b_out_w, f_norm_w, b_norm_w);
    siluz_kernel<<<dim3(2048, 2), 256>>>();

    prefix_kernel<<<128, 128>>>(f_D);

    scan_shared<<<256, 128>>>(f_D, b_D);

    final_kernel<<<2048, 256>>>(head_b, out);
}

// round 13
// speedup vs baseline: 4.2289x; 1.0495x over previous
#include <cuda_runtime.h>
#include <cuda_bf16.h>
#include <math.h>

#define L_SEQ 2049
#define BATCH 8
#define NH 16
#define HD 64
#define NS 128
#define DIN 1024
#define CONVD 1280
#define DPROJ 2320
#define NROWS 2056
#define GENEF 384
#define DMODEL 512
#define TCOR 2045   // corrected timesteps t=4..2048
#define TC 16       // scan chunk length
#define SST 24      // hgemm shared stride (A and B), bf16 elems (48B rows)

// ------------------------- scratch (static device globals) -------------------
__device__ float d_Z[2][NROWS * DPROJ];
__device__ float d_xBCs[2][(size_t)L_SEQ * CONVD];   // batch-shared conv out
__device__ float d_xBC0[BATCH * 4 * CONVD];          // fwd per-batch conv out, t=0..3
__device__ float d_dtr[2][NROWS * NH];
__device__ float d_dAr[2][NROWS * NH];
__device__ float d_ysum[2][(size_t)L_SEQ * NH * 64]; // scan y (each elem written once)
__device__ float d_ypre[BATCH * 3 * NH * 128];       // fwd per-batch y (t=1..3), halves
__device__ float d_decayf[NH * TCOR];                // cumprod dA fwd, t=4..2048
__device__ float d_dotCB[L_SEQ * 32];                // C_t . B_tau  [t][b][tau]
__device__ float d_W4[BATCH * NH * 4];               // dt_tau * prod dA  [b][h][tau]
__device__ float d_P[2][(size_t)2048 * DIN];         // silu(z) per gene row
__device__ float d_wcomb[2][DIN];
// split-bf16 operands for tensor-core GEMMs
__device__ __nv_bfloat16 d_Fhi[NROWS * GENEF];
__device__ __nv_bfloat16 d_Flo[NROWS * GENEF];
__device__ __nv_bfloat16 d_IWhi[DMODEL * GENEF];
__device__ __nv_bfloat16 d_IWlo[DMODEL * GENEF];
__device__ __nv_bfloat16 d_Xhi[NROWS * DMODEL];
__device__ __nv_bfloat16 d_Xlo[NROWS * DMODEL];
__device__ __nv_bfloat16 d_Whi[2][DPROJ * DMODEL];
__device__ __nv_bfloat16 d_Wlo[2][DPROJ * DMODEL];

__device__ __forceinline__ int seq_row(int b, int t) {
    return (t == 0) ? (2048 + b) : (t - 1);
}
__device__ __forceinline__ const float* xbc_fwd_ptr(int b, int t) {
    return (t >= 4) ? (d_xBCs[0] + (size_t)t * CONVD)
                    : (d_xBC0 + (size_t)(b * 4 + t) * CONVD);
}
// silu via hw tanh: silu(x) = 0.5x(1+tanh(x/2)) — 1 MUFU
__device__ __forceinline__ float fast_silu(float x) {
    float t;
    asm("tanh.approx.f32 %0, %1;" : "=f"(t) : "f"(x * 0.5f));
    return fmaf(0.5f * x, t, 0.5f * x);
}
__device__ __forceinline__ void store_split(__nv_bfloat16* hi, __nv_bfloat16* lo,
                                            size_t i, float v) {
    __nv_bfloat16 h = __float2bfloat16(v);
    hi[i] = h;
    lo[i] = __float2bfloat16(v - __bfloat162float(h));
}

// f32x2 packed math (sm_100+)
#define MUL2(d, a, b) asm("mul.rn.f32x2 %0,%1,%2;" : "=l"(d) : "l"(a), "l"(b))
#define FMA2(d, a, b, c) asm("fma.rn.f32x2 %0,%1,%2,%3;" : "=l"(d) : "l"(a), "l"(b), "l"(c))
#define ADD2(d, a, b) asm("add.rn.f32x2 %0,%1,%2;" : "=l"(d) : "l"(a), "l"(b))
__device__ __forceinline__ unsigned long long pack2(float x) {
    unsigned long long r;
    asm("mov.b64 %0,{%1,%1};" : "=l"(r) : "r"(__float_as_uint(x)));
    return r;
}
__device__ __forceinline__ float sum2(unsigned long long v) {
    unsigned int lo, hi;
    asm("mov.b64 {%0,%1},%2;" : "=r"(lo), "=r"(hi) : "l"(v));
    return __uint_as_float(lo) + __uint_as_float(hi);
}

// bf16 mma: D += A(m16k16) * B(n8k16)^T, f32 accum
#define MMA_BF16(cc, aa, bb) \
    asm volatile("mma.sync.aligned.m16n8k16.row.col.f32.bf16.bf16.f32 " \
        "{%0,%1,%2,%3}, {%4,%5,%6,%7}, {%8,%9}, {%0,%1,%2,%3};" \
        : "+f"((cc)[0]), "+f"((cc)[1]), "+f"((cc)[2]), "+f"((cc)[3]) \
        : "r"((aa)[0]), "r"((aa)[1]), "r"((aa)[2]), "r"((aa)[3]), \
          "r"((bb)[0]), "r"((bb)[1]))

#define LDSM_X4(r0, r1, r2, r3, addr) \
    asm volatile("ldmatrix.sync.aligned.m8n8.x4.shared.b16 {%0,%1,%2,%3}, [%4];" \
        : "=r"(r0), "=r"(r1), "=r"(r2), "=r"(r3) : "r"(addr))

__device__ __forceinline__ unsigned smem_u32(const void* p) {
    return (unsigned)__cvta_generic_to_shared(p);
}

// ------------------------- 1. feature rows (split-bf16 output) ---------------
__global__ void feat_kernel(const int* __restrict__ pidx,
                            const int* __restrict__ chridx,
                            const float* __restrict__ locus_fourier,
                            const float* __restrict__ pathway,
                            const float* __restrict__ pert_emb,
                            const float* __restrict__ gene_id,
                            const float* __restrict__ chr_emb,
                            const float* __restrict__ locus_w,
                            const float* __restrict__ locus_b,
                            const float* __restrict__ cond_w,
                            const float* __restrict__ cond_b) {
    int g = blockIdx.x;
    int tid = threadIdx.x;  // 128
    if (g < 2048) {
        store_split(d_Fhi, d_Flo, (size_t)g * GENEF + tid, gene_id[g * 128 + tid]);
        store_split(d_Fhi, d_Flo, (size_t)g * GENEF + 128 + tid, pathway[g * 128 + tid]);
        if (tid < 64) {
            int ci = chridx[g];
            store_split(d_Fhi, d_Flo, (size_t)g * GENEF + 256 + tid, chr_emb[ci * 64 + tid]);
        } else {
            int j = tid - 64;
            float acc = locus_b[j];
            const float* lf = locus_fourier + g * 64;
            const float* lw = locus_w + j * 64;
            for (int k = 0; k < 64; k++) acc = fmaf(lf[k], lw[k], acc);
            float ge = 0.5f * acc * (1.f + erff(acc * 0.70710678118654752f));
            store_split(d_Fhi, d_Flo, (size_t)g * GENEF + 320 + j, ge);
        }
    } else {
        int b = g - 2048;
        const float* pe = pert_emb + (size_t)pidx[b] * 128;
        for (int j = tid; j < GENEF; j += 128) {
            float acc = cond_b[j];
            const float* cw = cond_w + (size_t)j * 128;
            for (int k = 0; k < 128; k++) acc = fmaf(pe[k], cw[k], acc);
            store_split(d_Fhi, d_Flo, (size_t)g * GENEF + j, acc);
        }
    }
}

// ------------------------- 2a. weight conversions (merged) -------------------
__global__ void cvt_weights(const float* __restrict__ fw, const float* __restrict__ bw,
                            const float* __restrict__ iw) {
    int i = blockIdx.x * 256 + threadIdx.x;
    if (i < DPROJ * DMODEL) {
        store_split(d_Whi[0], d_Wlo[0], i, fw[i]);
        store_split(d_Whi[1], d_Wlo[1], i, bw[i]);
    }
    if (i < DMODEL * GENEF)
        store_split(d_IWhi, d_IWlo, i, iw[i]);
}

// ------------------------- 2b. tensor-core GEMM (ldmatrix fragments) ---------
// CFG 0: X-GEMM — BM=64, tile 64x128, grid (4, 33).
// CFG 1: Z-GEMM — BM=128, tile 128x128, grid (19, 17, 2); dir = blockIdx.z.
template <int CFG>
__global__ __launch_bounds__(256) void hgemm(const float* __restrict__ bias) {
    constexpr int BM = (CFG == 0) ? 64 : 128;
    constexpr int MT = 2;
    constexpr int NT = (CFG == 0) ? 4 : 8;
    constexpr int NWC = (CFG == 0) ? 32 : 64;   // cols per n-warp

    const __nv_bfloat16 *Ah, *Al, *Bh, *Bl;
    float* Cf = nullptr;
    __nv_bfloat16 *Chi = nullptr, *Clo = nullptr;
    int M, N, K;
    if (CFG == 0) {
        Ah = d_Fhi; Al = d_Flo; Bh = d_IWhi; Bl = d_IWlo;
        Chi = d_Xhi; Clo = d_Xlo;
        M = NROWS; N = DMODEL; K = GENEF;
    } else {
        int dir = blockIdx.z;
        Ah = d_Xhi; Al = d_Xlo; Bh = d_Whi[dir]; Bl = d_Wlo[dir];
        Cf = d_Z[dir];
        M = NROWS; N = DPROJ; K = DMODEL;
    }

    __shared__ __align__(16) __nv_bfloat16 sA[2][2][128 * SST];
    __shared__ __align__(16) __nv_bfloat16 sB[2][2][128 * SST];

    int tid = threadIdx.x;
    int row0 = blockIdx.y * BM;
    int col0 = blockIdx.x * 128;
    int lrow = tid >> 1;
    int seg = tid & 1;
    int lrowA = lrow & (BM - 1);

    int arow = row0 + lrowA;
    int brow = col0 + lrow;
    bool aval = arow < M;
    bool bval = brow < N;
    const uint4 z4 = make_uint4(0, 0, 0, 0);

    size_t abase = (size_t)arow * K + seg * 8;
    size_t bbase = (size_t)brow * K + seg * 8;

    uint4 rAh, rAl, rBh, rBl;
    rAh = aval ? *(const uint4*)(Ah + abase) : z4;
    rAl = aval ? *(const uint4*)(Al + abase) : z4;
    rBh = bval ? *(const uint4*)(Bh + bbase) : z4;
    rBl = bval ? *(const uint4*)(Bl + bbase) : z4;
    {
        *(uint4*)&sA[0][0][lrow * SST + seg * 8] = rAh;
        *(uint4*)&sA[0][1][lrow * SST + seg * 8] = rAl;
        *(uint4*)&sB[0][0][lrow * SST + seg * 8] = rBh;
        *(uint4*)&sB[0][1][lrow * SST + seg * 8] = rBl;
    }
    __syncthreads();

    int w = tid >> 5, l = tid & 31;
    int mw = (CFG == 0) ? (w >> 2) : (w >> 1);
    int nw = (CFG == 0) ? (w & 3) : (w & 1);
    int g = l >> 2, q = l & 3;

    // ldmatrix lane address offsets (element units within a [128*SST] plane)
    // A x4: mats {rows r..r+7 k0-7, r+8..r+15 k0-7, r..r+7 k8-15, r+8..r+15 k8-15}
    int aoff = (mw * 32 + (l & 15)) * SST + (l >> 4) * 8;
    // B x4 (two n-tiles): row = n0 + (l&7) + (l>=16 ? 8 : 0), col = ((l>>3)&1)*8
    int boff = (nw * NWC + (l & 7) + (l >> 4) * 8) * SST + ((l >> 3) & 1) * 8;

    float c[MT][NT][4];
#pragma unroll
    for (int mt = 0; mt < MT; mt++)
#pragma unroll
        for (int nt = 0; nt < NT; nt++)
#pragma unroll
            for (int i = 0; i < 4; i++) c[mt][nt][i] = 0.f;

    const int NCH = K >> 4;
    for (int kc = 0; kc < NCH; kc++) {
        int buf = kc & 1;
        bool more = (kc + 1) < NCH;
        if (more) {
            size_t ao = abase + (size_t)(kc + 1) * 16;
            size_t bo = bbase + (size_t)(kc + 1) * 16;
            rAh = aval ? *(const uint4*)(Ah + ao) : z4;
            rAl = aval ? *(const uint4*)(Al + ao) : z4;
            rBh = bval ? *(const uint4*)(Bh + bo) : z4;
            rBl = bval ? *(const uint4*)(Bl + bo) : z4;
        }

        unsigned a[MT][2][4], b[NT][2][2];
#pragma unroll
        for (int v = 0; v < 2; v++) {
#pragma unroll
            for (int mt = 0; mt < MT; mt++) {
                unsigned ad = smem_u32(&sA[buf][v][aoff + mt * 16 * SST]);
                LDSM_X4(a[mt][v][0], a[mt][v][1], a[mt][v][2], a[mt][v][3], ad);
            }
#pragma unroll
            for (int jp = 0; jp < NT / 2; jp++) {
                unsigned bd = smem_u32(&sB[buf][v][boff + jp * 16 * SST]);
                LDSM_X4(b[2 * jp][v][0], b[2 * jp][v][1],
                        b[2 * jp + 1][v][0], b[2 * jp + 1][v][1], bd);
            }
        }
#pragma unroll
        for (int mt = 0; mt < MT; mt++)
#pragma unroll
            for (int nt = 0; nt < NT; nt++) {
                MMA_BF16(c[mt][nt], a[mt][0], b[nt][0]);
                MMA_BF16(c[mt][nt], a[mt][0], b[nt][1]);
                MMA_BF16(c[mt][nt], a[mt][1], b[nt][0]);
            }

        if (more) {
            int nb = buf ^ 1;
            *(uint4*)&sA[nb][0][lrow * SST + seg * 8] = rAh;
            *(uint4*)&sA[nb][1][lrow * SST + seg * 8] = rAl;
            *(uint4*)&sB[nb][0][lrow * SST + seg * 8] = rBh;
            *(uint4*)&sB[nb][1][lrow * SST + seg * 8] = rBl;
        }
        __syncthreads();
    }

#pragma unroll
    for (int mt = 0; mt < MT; mt++) {
        int r0 = row0 + mw * 32 + mt * 16 + g;
#pragma unroll
        for (int nt = 0; nt < NT; nt++) {
            int cc = col0 + nw * NWC + nt * 8 + q * 2;
            if (cc >= N) continue;
            float b0 = bias ? bias[cc] : 0.f;
            float b1 = bias ? bias[cc + 1] : 0.f;
#pragma unroll
            for (int half = 0; half < 2; half++) {
                int r = r0 + half * 8;
                if (r >= M) continue;
                float v0 = c[mt][nt][half * 2 + 0] + b0;
                float v1 = c[mt][nt][half * 2 + 1] + b1;
                if (CFG != 0) {
                    *(float2*)&Cf[(size_t)r * N + cc] = make_float2(v0, v1);
                } else {
                    store_split(Chi, Clo, (size_t)r * N + cc, v0);
                    store_split(Chi, Clo, (size_t)r * N + cc + 1, v1);
                }
            }
        }
    }
}

// ------------------------- 3. causal depthwise conv + silu -------------------
__global__ void conv_kernel(const float* __restrict__ cw_f, const float* __restrict__ cb_f,
                            const float* __restrict__ cw_b, const float* __restrict__ cb_b) {
    int bx = blockIdx.x;
    int dir = blockIdx.y;
    const float* cw = dir ? cw_b : cw_f;
    const float* cb = dir ? cb_b : cb_f;
    const float* Z = d_Z[dir];

    const float* rows[4];
    float* dst;
    if (bx < L_SEQ) {
        int t = bx;
        if ((dir == 0 && t < 4) || (dir == 1 && t < 1)) return;
        dst = d_xBCs[dir] + (size_t)t * CONVD;
#pragma unroll
        for (int k = 0; k < 4; k++) {
            int tau = dir ? (t + 3 - k) : (t - 3 + k);
            rows[k] = (tau <= L_SEQ - 1) ? (Z + (size_t)(tau - 1) * DPROJ + DIN) : nullptr;
        }
    } else {
        if (dir == 1) return;
        int idx = bx - L_SEQ;
        int b = idx >> 2;
        int t = idx & 3;
        dst = d_xBC0 + (size_t)(b * 4 + t) * CONVD;
#pragma unroll
        for (int k = 0; k < 4; k++) {
            int tau = t - 3 + k;
            rows[k] = (tau >= 0) ? (Z + (size_t)seq_row(b, tau) * DPROJ + DIN) : nullptr;
        }
    }
    for (int c = threadIdx.x; c < CONVD; c += blockDim.x) {
        float acc = cb[c];
#pragma unroll
        for (int k = 0; k < 4; k++)
            if (rows[k]) acc = fmaf(rows[k][c], cw[c * 4 + k], acc);
        dst[c] = fast_silu(acc);
    }
}

// ------------------------- 4. dt / dA per row --------------------------------
__global__ void dtda_kernel(const float* __restrict__ fdtb, const float* __restrict__ fAl,
                            const float* __restrict__ bdtb, const float* __restrict__ bAl) {
    int idx = blockIdx.x * blockDim.x + threadIdx.x;
    const int per = NROWS * NH;
    if (idx >= 2 * per) return;
    int dir = idx / per;
    int r = idx % per;
    int row = r >> 4;
    int h = r & 15;
    float raw = d_Z[dir][(size_t)row * DPROJ + (DIN + CONVD) + h] + (dir ? bdtb : fdtb)[h];
    float dtv = (raw > 20.f) ? raw : log1pf(expf(raw));
    float Al = (dir ? bAl : fAl)[h];
    d_dtr[dir][row * NH + h] = dtv;
    d_dAr[dir][row * NH + h] = expf(-expf(Al) * dtv);
}

// ------------------------- 4b. fwd decay cumprod (parallel) ------------------
__global__ void decay_kernel() {
    int tid = threadIdx.x;    // 512
    int h = tid >> 5;
    int lane = tid & 31;
    int s0 = lane * 64;
    int len = (s0 < TCOR) ? ((TCOR - s0 < 64) ? (TCOR - s0) : 64) : 0;
    float prod = 1.f;
    for (int i = 0; i < len; i++) prod *= d_dAr[0][(size_t)(3 + s0 + i) * NH + h];
    float inc = prod;
#pragma unroll
    for (int off = 1; off < 32; off <<= 1) {
        float v = __shfl_up_sync(0xffffffffu, inc, off);
        if (lane >= off) inc *= v;
    }
    float excl = __shfl_up_sync(0xffffffffu, inc, 1);
    if (lane == 0) excl = 1.f;
    float run = excl;
    for (int i = 0; i < len; i++) {
        run *= d_dAr[0][(size_t)(3 + s0 + i) * NH + h];
        d_decayf[h * TCOR + s0 + i] = run;
    }
}

// ------------------------- 4c. W4 --------------------------------------------
__global__ void w4_kernel() {
    int idx = threadIdx.x;   // 512
    if (idx >= BATCH * NH * 4) return;
    int b = idx >> 6, h = (idx >> 2) & 15, tau = idx & 3;
    int row_tau = (tau == 0) ? (2048 + b) : (tau - 1);
    float w = d_dtr[0][row_tau * NH + h];
    for (int s = tau + 1; s < 4; s++)
        w *= d_dAr[0][(s - 1) * NH + h];
    d_W4[idx] = w;
}

// ------------------------- 4d. dotCB -----------------------------------------
__global__ void dotcb_kernel() {
    int t = blockIdx.x + 4;       // 4..2048
    __shared__ float sC[128];
    int tid = threadIdx.x;        // 256 = 8 warps
    if (tid < 128) sC[tid] = d_xBCs[0][(size_t)t * CONVD + DIN + NS + tid];
    __syncthreads();
    int w = tid >> 5, l = tid & 31;
    for (int c = w; c < 32; c += 8) {
        const float* B0 = d_xBC0 + (size_t)c * CONVD + DIN;
        float acc = 0.f;
#pragma unroll
        for (int i = 0; i < 4; i++) acc = fmaf(B0[i * 32 + l], sC[i * 32 + l], acc);
#pragma unroll
        for (int off = 16; off; off >>= 1)
            acc += __shfl_xor_sync(0xffffffffu, acc, off);
        if (l == 0) d_dotCB[t * 32 + c] = acc;
    }
}

// ------------------------- 5. combined output vector -------------------------
__global__ void wcomb_kernel(const float* __restrict__ head_w,
                             const float* __restrict__ fow, const float* __restrict__ bow,
                             const float* __restrict__ fnw, const float* __restrict__ bnw) {
    int idx = blockIdx.x * blockDim.x + threadIdx.x;
    if (idx >= 2 * DIN) return;
    int dir = idx >> 10;
    int j = idx & 1023;
    const float* ow = dir ? bow : fow;
    float acc = 0.f;
    for (int i = 0; i < DMODEL; i++) acc = fmaf(ow[(size_t)i * DIN + j], head_w[i], acc);
    d_wcomb[dir][j] = acc * (dir ? bnw : fnw)[j];
}

// ------------------------- 5b. silu(z) per gene row --------------------------
__global__ void siluz_kernel() {
    int row = blockIdx.x;
    int dir = blockIdx.y;
    const float* z = d_Z[dir] + (size_t)row * DPROJ;
    float* P = d_P[dir] + (size_t)row * DIN;
    for (int j = threadIdx.x; j < DIN; j += 256) P[j] = fast_silu(z[j]);
}

// ------------------------- 6a. fwd per-batch prefix scan (t=0..3) ------------
__global__ __launch_bounds__(128) void prefix_kernel(const float* __restrict__ fD) {
    int blk = blockIdx.x;
    int b = blk >> 4;
    int h = blk & 15;
    int tid = threadIdx.x;
    int p = tid & 63;
    int nh = tid >> 6;
    float Dh = fD[h];

    __shared__ __align__(16) float sB[128], sC[128], sx[64];

    unsigned long long hs2[32];
#pragma unroll
    for (int i = 0; i < 32; i++) hs2[i] = 0ull;

    for (int t = 0; t < 4; t++) {
        const float* pp = xbc_fwd_ptr(b, t);
        sB[tid] = pp[DIN + tid];
        sC[tid] = pp[DIN + NS + tid];
        if (tid < 64) sx[tid] = pp[h * HD + tid];
        __syncthreads();
        int row = (t == 0) ? (2048 + b) : (t - 1);
        float dtv = d_dtr[0][row * NH + h];
        float dAv = d_dAr[0][row * NH + h];
        float xv = sx[p];
        unsigned long long coef2 = pack2(dtv * xv);
        unsigned long long dA2 = pack2(dAv);
        const ulonglong2* B4 = (const ulonglong2*)(sB + nh * 64);
        const ulonglong2* C4 = (const ulonglong2*)(sC + nh * 64);
        unsigned long long a0 = 0ull, a1 = 0ull;
#pragma unroll
        for (int i = 0; i < 16; i++) {
            ulonglong2 bv = B4[i], cv = C4[i];
            unsigned long long tm;
            MUL2(tm, coef2, bv.x);
            FMA2(hs2[2 * i + 0], dA2, hs2[2 * i + 0], tm);
            FMA2(a0, hs2[2 * i + 0], cv.x, a0);
            MUL2(tm, coef2, bv.y);
            FMA2(hs2[2 * i + 1], dA2, hs2[2 * i + 1], tm);
            FMA2(a1, hs2[2 * i + 1], cv.y, a1);
        }
        ADD2(a0, a0, a1);
        float part = sum2(a0);
        if (nh == 0) part = fmaf(Dh, xv, part);
        if (t >= 1)
            d_ypre[((size_t)(b * 3 + (t - 1)) * 16 + h) * 128 + tid] = part;
        __syncthreads();
    }
}

// ------------------------- 6b. shared scans — p-split, no atomics ------------
__global__ __launch_bounds__(128) void scan_shared(const float* __restrict__ fD,
                                                   const float* __restrict__ bD) {
    int blk = blockIdx.x;          // 0..255
    int dir = blk >> 7;
    int rest = blk & 127;
    int h = rest >> 3;
    int pq = rest & 7;
    int tid = threadIdx.x;
    int p8 = tid & 7;
    int nsix = tid >> 3;
    float Dh = (dir ? bD : fD)[h];
    const float* xbc = d_xBCs[dir];
    const float* dtr = d_dtr[dir];
    const float* dAr = d_dAr[dir];
    float* ysum = d_ysum[dir];

    int S = dir ? 2048 : TCOR;
    int nch = (S + TC - 1) / TC;

    __shared__ __align__(16) float sB[2][TC][128];
    __shared__ __align__(16) float sC[2][TC][128];
    __shared__ __align__(16) float sx[2][TC][8];
    __shared__ float sdt[2][TC], sdA[2][TC];
    __shared__ __align__(16) float sy[TC][128];

    unsigned long long hs2[4] = {0ull, 0ull, 0ull, 0ull};

    float4 rB[4], rC[4], rx;
    float rdt = 0.f, rdA = 0.f;

#define SCAN_LOAD(s0_)                                                          \
    {                                                                           \
        int lim = S - 1 - (s0_);                                                \
        _Pragma("unroll")                                                       \
        for (int k = 0; k < 4; k++) {                                           \
            int idx = tid + k * 128;                                            \
            int j = idx >> 5; if (j > lim) j = lim;                             \
            int tt = dir ? (2048 - ((s0_) + j)) : (4 + (s0_) + j);              \
            const float* rowp = xbc + (size_t)tt * CONVD + DIN;                 \
            rB[k] = ((const float4*)rowp)[idx & 31];                            \
            rC[k] = ((const float4*)(rowp + NS))[idx & 31];                     \
        }                                                                       \
        if (tid < 2 * TC) {                                                     \
            int j = tid >> 1; if (j > lim) j = lim;                             \
            int tt = dir ? (2048 - ((s0_) + j)) : (4 + (s0_) + j);              \
            rx = ((const float4*)(xbc + (size_t)tt * CONVD + h * HD + pq * 8))[tid & 1]; \
        }                                                                       \
        if (tid < TC) {                                                         \
            int j = (tid > lim) ? lim : tid;                                    \
            int tt = dir ? (2048 - ((s0_) + j)) : (4 + (s0_) + j);              \
            rdt = dtr[(tt - 1) * NH + h];                                       \
            rdA = dAr[(tt - 1) * NH + h];                                       \
        }                                                                       \
    }
#define SCAN_STORE(bb_)                                                         \
    {                                                                           \
        _Pragma("unroll")                                                       \
        for (int k = 0; k < 4; k++) {                                           \
            int idx = tid + k * 128;                                            \
            *(float4*)&sB[bb_][idx >> 5][(idx & 31) * 4] = rB[k];               \
            *(float4*)&sC[bb_][idx >> 5][(idx & 31) * 4] = rC[k];               \
        }                                                                       \
        if (tid < 2 * TC) *(float4*)&sx[bb_][tid >> 1][(tid & 1) * 4] = rx;     \
        if (tid < TC) { sdt[bb_][tid] = rdt; sdA[bb_][tid] = rdA; }             \
    }

    SCAN_LOAD(0);
    SCAN_STORE(0);
    __syncthreads();

    for (int c = 0; c < nch; c++) {
        int s0 = c * TC;
        int cnt = (S - s0 < TC) ? (S - s0) : TC;
        bool more = (c + 1) < nch;
        if (more) SCAN_LOAD(s0 + TC);
        int bb = c & 1;
        for (int j = 0; j < cnt; j++) {
            float xv = sx[bb][j][p8];
            unsigned long long coef2 = pack2(sdt[bb][j] * xv);
            unsigned long long dA2 = pack2(sdA[bb][j]);
            const ulonglong2* B4 = (const ulonglong2*)&sB[bb][j][nsix * 8];
            const ulonglong2* C4 = (const ulonglong2*)&sC[bb][j][nsix * 8];
            ulonglong2 bv0 = B4[0], cv0 = C4[0];
            ulonglong2 bv1 = B4[1], cv1 = C4[1];
            unsigned long long a0 = 0ull, a1 = 0ull, tm;
            MUL2(tm, coef2, bv0.x);
            FMA2(hs2[0], dA2, hs2[0], tm);
            FMA2(a0, hs2[0], cv0.x, a0);
            MUL2(tm, coef2, bv0.y);
            FMA2(hs2[1], dA2, hs2[1], tm);
            FMA2(a1, hs2[1], cv0.y, a1);
            MUL2(tm, coef2, bv1.x);
            FMA2(hs2[2], dA2, hs2[2], tm);
            FMA2(a0, hs2[2], cv1.x, a0);
            MUL2(tm, coef2, bv1.y);
            FMA2(hs2[3], dA2, hs2[3], tm);
            FMA2(a1, hs2[3], cv1.y, a1);
            ADD2(a0, a0, a1);
            sy[j][tid] = sum2(a0);
        }
        if (more) SCAN_STORE(bb ^ 1);
        __syncthreads();
        {
            int jo = tid >> 3;
            int po = tid & 7;
            if (jo < cnt) {
                const float* sp = &sy[jo][po];
                float s = 0.f;
#pragma unroll
                for (int k = 0; k < 16; k++) s += sp[k * 8];
                s = fmaf(Dh, sx[bb][jo][po], s);
                int tt = dir ? (2048 - (s0 + jo)) : (4 + s0 + jo);
                ysum[(size_t)tt * 1024 + h * 64 + pq * 8 + po] = s;
            }
        }
        __syncthreads();
    }
#undef SCAN_LOAD
#undef SCAN_STORE
}

// ------------------------- 7. gate + RMSnorm + fused head (per-t, all b) -----
__global__ __launch_bounds__(256) void final_kernel(const float* __restrict__ head_b,
                                                    float* __restrict__ out) {
    int t = blockIdx.x + 1;     // 1..2048
    int tid = threadIdx.x;      // 256
    __shared__ float cco[8][64];
    __shared__ float sh[8][18];

    if (t >= 4) {
        for (int i = tid; i < 512; i += 256) {
            int b = i >> 6;
            int r = i & 63;             // h*4+tau
            int hh = r >> 2, tau = r & 3;
            cco[b][r] = d_decayf[hh * TCOR + (t - 4)] *
                        d_W4[(b * 16 + hh) * 4 + tau] *
                        d_dotCB[t * 32 + b * 4 + tau];
        }
    }
    __syncthreads();

    int j0 = tid * 4;
    int h = tid >> 4;
    float4 ysf4 = *(const float4*)&d_ysum[0][(size_t)t * DIN + j0];
    float4 ysb4 = *(const float4*)&d_ysum[1][(size_t)t * DIN + j0];
    float4 pf4 = *(const float4*)&d_P[0][(size_t)(t - 1) * DIN + j0];
    float4 pb4 = *(const float4*)&d_P[1][(size_t)(t - 1) * DIN + j0];
    float4 w04 = *(const float4*)&d_wcomb[0][j0];
    float4 w14 = *(const float4*)&d_wcomb[1][j0];

    float ssqb = 0.f, sdotb = 0.f;
    {
        float g;
        g = ysb4.x * pb4.x; ssqb = fmaf(g, g, ssqb); sdotb = fmaf(g, w14.x, sdotb);
        g = ysb4.y * pb4.y; ssqb = fmaf(g, g, ssqb); sdotb = fmaf(g, w14.y, sdotb);
        g = ysb4.z * pb4.z; ssqb = fmaf(g, g, ssqb); sdotb = fmaf(g, w14.z, sdotb);
        g = ysb4.w * pb4.w; ssqb = fmaf(g, g, ssqb); sdotb = fmaf(g, w14.w, sdotb);
    }

    float ssqf[8], sdotf[8];
    if (t >= 4) {
#pragma unroll
        for (int b = 0; b < 8; b++) {
            const float* xbb = d_xBC0 + (size_t)b * 4 * CONVD + j0;
            float4 x0 = *(const float4*)&xbb[0];
            float4 x1 = *(const float4*)&xbb[CONVD];
            float4 x2 = *(const float4*)&xbb[2 * CONVD];
            float4 x3 = *(const float4*)&xbb[3 * CONVD];
            float cc0 = cco[b][h * 4 + 0], cc1 = cco[b][h * 4 + 1];
            float cc2 = cco[b][h * 4 + 2], cc3 = cco[b][h * 4 + 3];
            float sq = 0.f, sd = 0.f, yf, g;
            yf = ysf4.x + cc0 * x0.x + cc1 * x1.x + cc2 * x2.x + cc3 * x3.x;
            g = yf * pf4.x; sq = fmaf(g, g, sq); sd = fmaf(g, w04.x, sd);
            yf = ysf4.y + cc0 * x0.y + cc1 * x1.y + cc2 * x2.y + cc3 * x3.y;
            g = yf * pf4.y; sq = fmaf(g, g, sq); sd = fmaf(g, w04.y, sd);
            yf = ysf4.z + cc0 * x0.z + cc1 * x1.z + cc2 * x2.z + cc3 * x3.z;
            g = yf * pf4.z; sq = fmaf(g, g, sq); sd = fmaf(g, w04.z, sd);
            yf = ysf4.w + cc0 * x0.w + cc1 * x1.w + cc2 * x2.w + cc3 * x3.w;
            g = yf * pf4.w; sq = fmaf(g, g, sq); sd = fmaf(g, w04.w, sd);
            ssqf[b] = sq; sdotf[b] = sd;
        }
    } else {
        int p0 = j0 & 63;
#pragma unroll
        for (int b = 0; b < 8; b++) {
            const float* yp = d_ypre + ((size_t)(b * 3 + (t - 1)) * 16 + h) * 128;
            float sq = 0.f, sd = 0.f;
            float pf[4] = {pf4.x, pf4.y, pf4.z, pf4.w};
            float w0[4] = {w04.x, w04.y, w04.z, w04.w};
#pragma unroll
            for (int k = 0; k < 4; k++) {
                float yf = yp[p0 + k] + yp[64 + p0 + k];
                float g = yf * pf[k];
                sq = fmaf(g, g, sq); sd = fmaf(g, w0[k], sd);
            }
            ssqf[b] = sq; sdotf[b] = sd;
        }
    }

#pragma unroll
    for (int off = 16; off; off >>= 1) {
        ssqb += __shfl_xor_sync(0xffffffffu, ssqb, off);
        sdotb += __shfl_xor_sync(0xffffffffu, sdotb, off);
#pragma unroll
        for (int b = 0; b < 8; b++) {
            ssqf[b] += __shfl_xor_sync(0xffffffffu, ssqf[b], off);
            sdotf[b] += __shfl_xor_sync(0xffffffffu, sdotf[b], off);
        }
    }
    int w = tid >> 5, l = tid & 31;
    if (l == 0) {
        sh[w][0] = ssqb; sh[w][1] = sdotb;
#pragma unroll
        for (int b = 0; b < 8; b++) { sh[w][2 + b] = ssqf[b]; sh[w][10 + b] = sdotf[b]; }
    }
    __syncthreads();
    if (tid < 8) {
        float qb = 0.f, db = 0.f, a = 0.f, d = 0.f;
        for (int i = 0; i < 8; i++) {
            qb += sh[i][0]; db += sh[i][1];
            a += sh[i][2 + tid]; d += sh[i][10 + tid];
        }
        float resb = rsqrtf(qb * (1.f / 1024.f) + 1e-5f) * db;
        float resf = rsqrtf(a * (1.f / 1024.f) + 1e-5f) * d;
        out[tid * 2048 + (t - 1)] = resf + resb + head_b[0];
    }
}

// ------------------------- launch --------------------------------------------
extern "C" void kernel_launch(void* const* d_in, const int* in_sizes, int n_in,
                              void* d_out, int out_size) {
    const int* pidx            = (const int*)d_in[0];
    const int* chridx          = (const int*)d_in[1];
    const float* locus_fourier = (const float*)d_in[2];
    const float* pathway       = (const float*)d_in[3];
    const float* pert_emb      = (const float*)d_in[4];
    const float* gene_id       = (const float*)d_in[5];
    const float* chr_emb       = (const float*)d_in[6];
    const float* locus_w       = (const float*)d_in[7];
    const float* locus_b       = (const float*)d_in[8];
    const float* cond_w        = (const float*)d_in[9];
    const float* cond_b        = (const float*)d_in[10];
    const float* in_w          = (const float*)d_in[11];
    const float* in_b          = (const float*)d_in[12];
    const float* head_w        = (const float*)d_in[13];
    const float* head_b        = (const float*)d_in[14];
    const float* f_in_w        = (const float*)d_in[15];
    const float* f_conv_w      = (const float*)d_in[16];
    const float* f_conv_b      = (const float*)d_in[17];
    const float* f_dt_bias     = (const float*)d_in[18];
    const float* f_A_log       = (const float*)d_in[19];
    const float* f_D           = (const float*)d_in[20];
    const float* f_norm_w      = (const float*)d_in[21];
    const float* f_out_w       = (const float*)d_in[22];
    const float* b_in_w        = (const float*)d_in[23];
    const float* b_conv_w      = (const float*)d_in[24];
    const float* b_conv_b      = (const float*)d_in[25];
    const float* b_dt_bias     = (const float*)d_in[26];
    const float* b_A_log       = (const float*)d_in[27];
    const float* b_D           = (const float*)d_in[28];
    const float* b_norm_w      = (const float*)d_in[29];
    const float* b_out_w       = (const float*)d_in[30];
    float* out = (float*)d_out;

    feat_kernel<<<NROWS, 128>>>(pidx, chridx, locus_fourier, pathway, pert_emb,
                                gene_id, chr_emb, locus_w, locus_b, cond_w, cond_b);
    cvt_weights<<<(DPROJ * DMODEL + 255) / 256, 256>>>(f_in_w, b_in_w, in_w);

    // X = feat @ in_w^T + in_b (64x128 tiles)
    hgemm<0><<<dim3(4, 33), 256>>>(in_b);
    // Z_dir = X @ W^T (128x128 tiles, both dirs in one launch)
    hgemm<1><<<dim3(19, 17, 2), 256>>>(nullptr);

    conv_kernel<<<dim3(L_SEQ + 32, 2), 256>>>(f_conv_w, f_conv_b, b_conv_w, b_conv_b);

    dtda_kernel<<<(2 * NROWS * NH + 255) / 256, 256>>>(f_dt_bias, f_A_log, b_dt_bias, b_A_log);
    decay_kernel<<<1, 512>>>();
    w4_kernel<<<1, 512>>>();
    dotcb_kernel<<<TCOR, 256>>>();

    wcomb_kernel<<<(2 * DIN + 255) / 256, 256>>>(head_w, f_out_w, b_out_w, f_norm_w, b_norm_w);
    siluz_kernel<<<dim3(2048, 2), 256>>>();

    prefix_kernel<<<128, 128>>>(f_D);

    scan_shared<<<256, 128>>>(f_D, b_D);

    final_kernel<<<2048, 256>>>(head_b, out);
}

// round 14
// speedup vs baseline: 4.2532x; 1.0057x over previous
#include <cuda_runtime.h>
#include <cuda_bf16.h>
#include <math.h>

#define L_SEQ 2049
#define BATCH 8
#define NH 16
#define HD 64
#define NS 128
#define DIN 1024
#define CONVD 1280
#define DPROJ 2320
#define NROWS 2056
#define GENEF 384
#define DMODEL 512
#define TCOR 2045   // corrected timesteps t=4..2048
#define TC 16       // scan chunk length
#define SST 24      // hgemm shared stride, bf16 elems (48B rows)

// ------------------------- scratch (static device globals) -------------------
__device__ float d_Z[2][NROWS * DPROJ];
__device__ float d_xBCs[2][(size_t)L_SEQ * CONVD];   // batch-shared conv out
__device__ float d_xBC0[BATCH * 4 * CONVD];          // fwd per-batch conv out, t=0..3
__device__ float d_dtr[2][NROWS * NH];
__device__ float d_dAr[2][NROWS * NH];
__device__ float d_ysum[2][(size_t)L_SEQ * NH * 64]; // scan y (each elem written once)
__device__ float d_ypre[BATCH * 3 * NH * 128];       // fwd per-batch y (t=1..3), halves
__device__ float d_decayf[NH * TCOR];                // cumprod dA fwd, t=4..2048
__device__ float d_dotCB[L_SEQ * 32];                // C_t . B_tau  [t][b][tau]
__device__ float d_W4[BATCH * NH * 4];               // dt_tau * prod dA  [b][h][tau]
__device__ float d_P[2][(size_t)2048 * DIN];         // silu(z) per gene row
__device__ float d_wcomb[2][DIN];
// split-bf16 operands for tensor-core GEMMs
__device__ __nv_bfloat16 d_Fhi[NROWS * GENEF];
__device__ __nv_bfloat16 d_Flo[NROWS * GENEF];
__device__ __nv_bfloat16 d_IWhi[DMODEL * GENEF];
__device__ __nv_bfloat16 d_IWlo[DMODEL * GENEF];
__device__ __nv_bfloat16 d_Xhi[NROWS * DMODEL];
__device__ __nv_bfloat16 d_Xlo[NROWS * DMODEL];
__device__ __nv_bfloat16 d_Whi[2][DPROJ * DMODEL];
__device__ __nv_bfloat16 d_Wlo[2][DPROJ * DMODEL];

__device__ __forceinline__ int seq_row(int b, int t) {
    return (t == 0) ? (2048 + b) : (t - 1);
}
__device__ __forceinline__ const float* xbc_fwd_ptr(int b, int t) {
    return (t >= 4) ? (d_xBCs[0] + (size_t)t * CONVD)
                    : (d_xBC0 + (size_t)(b * 4 + t) * CONVD);
}
// silu via hw tanh: silu(x) = 0.5x(1+tanh(x/2)) — 1 MUFU
__device__ __forceinline__ float fast_silu(float x) {
    float t;
    asm("tanh.approx.f32 %0, %1;" : "=f"(t) : "f"(x * 0.5f));
    return fmaf(0.5f * x, t, 0.5f * x);
}
__device__ __forceinline__ void store_split(__nv_bfloat16* hi, __nv_bfloat16* lo,
                                            size_t i, float v) {
    __nv_bfloat16 h = __float2bfloat16(v);
    hi[i] = h;
    lo[i] = __float2bfloat16(v - __bfloat162float(h));
}

// f32x2 packed math (sm_100+)
#define MUL2(d, a, b) asm("mul.rn.f32x2 %0,%1,%2;" : "=l"(d) : "l"(a), "l"(b))
#define FMA2(d, a, b, c) asm("fma.rn.f32x2 %0,%1,%2,%3;" : "=l"(d) : "l"(a), "l"(b), "l"(c))
#define ADD2(d, a, b) asm("add.rn.f32x2 %0,%1,%2;" : "=l"(d) : "l"(a), "l"(b))
__device__ __forceinline__ unsigned long long pack2(float x) {
    unsigned long long r;
    asm("mov.b64 %0,{%1,%1};" : "=l"(r) : "r"(__float_as_uint(x)));
    return r;
}
__device__ __forceinline__ float sum2(unsigned long long v) {
    unsigned int lo, hi;
    asm("mov.b64 {%0,%1},%2;" : "=r"(lo), "=r"(hi) : "l"(v));
    return __uint_as_float(lo) + __uint_as_float(hi);
}

// bf16 mma: D += A(m16k16) * B(n8k16)^T, f32 accum
#define MMA_BF16(cc, aa, bb) \
    asm volatile("mma.sync.aligned.m16n8k16.row.col.f32.bf16.bf16.f32 " \
        "{%0,%1,%2,%3}, {%4,%5,%6,%7}, {%8,%9}, {%0,%1,%2,%3};" \
        : "+f"((cc)[0]), "+f"((cc)[1]), "+f"((cc)[2]), "+f"((cc)[3]) \
        : "r"((aa)[0]), "r"((aa)[1]), "r"((aa)[2]), "r"((aa)[3]), \
          "r"((bb)[0]), "r"((bb)[1]))

#define LDSM_X4(r0, r1, r2, r3, addr) \
    asm volatile("ldmatrix.sync.aligned.m8n8.x4.shared.b16 {%0,%1,%2,%3}, [%4];" \
        : "=r"(r0), "=r"(r1), "=r"(r2), "=r"(r3) : "r"(addr))

__device__ __forceinline__ unsigned smem_u32(const void* p) {
    return (unsigned)__cvta_generic_to_shared(p);
}

#define CPA16(saddr, gptr) \
    asm volatile("cp.async.ca.shared.global [%0], [%1], 16;" :: "r"(saddr), "l"(gptr))
#define CP_COMMIT() asm volatile("cp.async.commit_group;")
#define CP_WAIT0() asm volatile("cp.async.wait_group 0;")
#define CP_WAIT1() asm volatile("cp.async.wait_group 1;")

// ------------------------- 1. feature rows (split-bf16 output) ---------------
__global__ void feat_kernel(const int* __restrict__ pidx,
                            const int* __restrict__ chridx,
                            const float* __restrict__ locus_fourier,
                            const float* __restrict__ pathway,
                            const float* __restrict__ pert_emb,
                            const float* __restrict__ gene_id,
                            const float* __restrict__ chr_emb,
                            const float* __restrict__ locus_w,
                            const float* __restrict__ locus_b,
                            const float* __restrict__ cond_w,
                            const float* __restrict__ cond_b) {
    int g = blockIdx.x;
    int tid = threadIdx.x;  // 128
    if (g < 2048) {
        store_split(d_Fhi, d_Flo, (size_t)g * GENEF + tid, gene_id[g * 128 + tid]);
        store_split(d_Fhi, d_Flo, (size_t)g * GENEF + 128 + tid, pathway[g * 128 + tid]);
        if (tid < 64) {
            int ci = chridx[g];
            store_split(d_Fhi, d_Flo, (size_t)g * GENEF + 256 + tid, chr_emb[ci * 64 + tid]);
        } else {
            int j = tid - 64;
            float acc = locus_b[j];
            const float* lf = locus_fourier + g * 64;
            const float* lw = locus_w + j * 64;
            for (int k = 0; k < 64; k++) acc = fmaf(lf[k], lw[k], acc);
            float ge = 0.5f * acc * (1.f + erff(acc * 0.70710678118654752f));
            store_split(d_Fhi, d_Flo, (size_t)g * GENEF + 320 + j, ge);
        }
    } else {
        int b = g - 2048;
        const float* pe = pert_emb + (size_t)pidx[b] * 128;
        for (int j = tid; j < GENEF; j += 128) {
            float acc = cond_b[j];
            const float* cw = cond_w + (size_t)j * 128;
            for (int k = 0; k < 128; k++) acc = fmaf(pe[k], cw[k], acc);
            store_split(d_Fhi, d_Flo, (size_t)g * GENEF + j, acc);
        }
    }
}

// ------------------------- 2a. weight conversions (merged) -------------------
__global__ void cvt_weights(const float* __restrict__ fw, const float* __restrict__ bw,
                            const float* __restrict__ iw) {
    int i = blockIdx.x * 256 + threadIdx.x;
    if (i < DPROJ * DMODEL) {
        store_split(d_Whi[0], d_Wlo[0], i, fw[i]);
        store_split(d_Whi[1], d_Wlo[1], i, bw[i]);
    }
    if (i < DMODEL * GENEF)
        store_split(d_IWhi, d_IWlo, i, iw[i]);
}

// ------------------------- 2b. tensor-core GEMM (cp.async + ldmatrix) --------
// CFG 0: X-GEMM — BM=64, tile 64x128, grid (4, 33).
// CFG 1: Z-GEMM — BM=128, tile 128x128, grid (19, 17, 2); dir = blockIdx.z.
//        Fused epilogue: cc<DIN -> d_P (silu, gene rows only), else d_Z.
template <int CFG>
__global__ __launch_bounds__(256) void hgemm(const float* __restrict__ bias) {
    constexpr int BM = (CFG == 0) ? 64 : 128;
    constexpr int MT = 2;
    constexpr int NT = (CFG == 0) ? 4 : 8;
    constexpr int NWC = (CFG == 0) ? 32 : 64;   // cols per n-warp

    const __nv_bfloat16 *Ah, *Al, *Bh, *Bl;
    float* Cf = nullptr;
    float* Pf = nullptr;
    __nv_bfloat16 *Chi = nullptr, *Clo = nullptr;
    int M, N, K;
    if (CFG == 0) {
        Ah = d_Fhi; Al = d_Flo; Bh = d_IWhi; Bl = d_IWlo;
        Chi = d_Xhi; Clo = d_Xlo;
        M = NROWS; N = DMODEL; K = GENEF;
    } else {
        int dir = blockIdx.z;
        Ah = d_Xhi; Al = d_Xlo; Bh = d_Whi[dir]; Bl = d_Wlo[dir];
        Cf = d_Z[dir];
        Pf = d_P[dir];
        M = NROWS; N = DPROJ; K = DMODEL;
    }

    __shared__ __align__(16) __nv_bfloat16 sA[2][2][128 * SST];
    __shared__ __align__(16) __nv_bfloat16 sB[2][2][128 * SST];

    int tid = threadIdx.x;
    int row0 = blockIdx.y * BM;
    int col0 = blockIdx.x * 128;
    int lrow = tid >> 1;
    int seg = tid & 1;
    int lrowA = lrow & (BM - 1);

    int arow = row0 + lrowA;
    int brow = col0 + lrow;
    // clamp OOB rows to valid addresses; garbage values are discarded at epilogue
    int arc = (arow < M) ? arow : (M - 1);
    int brc = (brow < N) ? brow : (N - 1);

    const __nv_bfloat16* pAh = Ah + (size_t)arc * K + seg * 8;
    const __nv_bfloat16* pAl = Al + (size_t)arc * K + seg * 8;
    const __nv_bfloat16* pBh = Bh + (size_t)brc * K + seg * 8;
    const __nv_bfloat16* pBl = Bl + (size_t)brc * K + seg * 8;

    unsigned dA0 = smem_u32(&sA[0][0][lrow * SST + seg * 8]);
    unsigned dA1 = smem_u32(&sA[0][1][lrow * SST + seg * 8]);
    unsigned dB0 = smem_u32(&sB[0][0][lrow * SST + seg * 8]);
    unsigned dB1 = smem_u32(&sB[0][1][lrow * SST + seg * 8]);
    const unsigned bufoff = (unsigned)(2 * 128 * SST * sizeof(__nv_bfloat16));

#define HG_STAGE(kc_, bb_)                                                     \
    {                                                                          \
        size_t o = (size_t)(kc_) * 16;                                         \
        unsigned bo = (bb_) ? bufoff : 0u;                                     \
        CPA16(dA0 + bo, pAh + o);                                              \
        CPA16(dA1 + bo, pAl + o);                                              \
        CPA16(dB0 + bo, pBh + o);                                              \
        CPA16(dB1 + bo, pBl + o);                                              \
    }

    HG_STAGE(0, 0);
    CP_COMMIT();

    int w = tid >> 5, l = tid & 31;
    int mw = (CFG == 0) ? (w >> 2) : (w >> 1);
    int nw = (CFG == 0) ? (w & 3) : (w & 1);
    int g = l >> 2, q = l & 3;

    int aoff = (mw * 32 + (l & 15)) * SST + (l >> 4) * 8;
    int boff = (nw * NWC + (l & 7) + (l >> 4) * 8) * SST + ((l >> 3) & 1) * 8;

    float c[MT][NT][4];
#pragma unroll
    for (int mt = 0; mt < MT; mt++)
#pragma unroll
        for (int nt = 0; nt < NT; nt++)
#pragma unroll
            for (int i = 0; i < 4; i++) c[mt][nt][i] = 0.f;

    const int NCH = K >> 4;
    for (int kc = 0; kc < NCH; kc++) {
        int buf = kc & 1;
        bool more = (kc + 1) < NCH;
        if (more) {
            HG_STAGE(kc + 1, buf ^ 1);
            CP_COMMIT();
            CP_WAIT1();
        } else {
            CP_WAIT0();
        }
        __syncthreads();

        unsigned a[MT][2][4], b[NT][2][2];
#pragma unroll
        for (int v = 0; v < 2; v++) {
#pragma unroll
            for (int mt = 0; mt < MT; mt++) {
                unsigned ad = smem_u32(&sA[buf][v][aoff + mt * 16 * SST]);
                LDSM_X4(a[mt][v][0], a[mt][v][1], a[mt][v][2], a[mt][v][3], ad);
            }
#pragma unroll
            for (int jp = 0; jp < NT / 2; jp++) {
                unsigned bd = smem_u32(&sB[buf][v][boff + jp * 16 * SST]);
                LDSM_X4(b[2 * jp][v][0], b[2 * jp][v][1],
                        b[2 * jp + 1][v][0], b[2 * jp + 1][v][1], bd);
            }
        }
#pragma unroll
        for (int mt = 0; mt < MT; mt++)
#pragma unroll
            for (int nt = 0; nt < NT; nt++) {
                MMA_BF16(c[mt][nt], a[mt][0], b[nt][0]);
                MMA_BF16(c[mt][nt], a[mt][0], b[nt][1]);
                MMA_BF16(c[mt][nt], a[mt][1], b[nt][0]);
            }
        __syncthreads();
    }
#undef HG_STAGE

#pragma unroll
    for (int mt = 0; mt < MT; mt++) {
        int r0 = row0 + mw * 32 + mt * 16 + g;
#pragma unroll
        for (int nt = 0; nt < NT; nt++) {
            int cc = col0 + nw * NWC + nt * 8 + q * 2;
            if (cc >= N) continue;
            float b0 = bias ? bias[cc] : 0.f;
            float b1 = bias ? bias[cc + 1] : 0.f;
#pragma unroll
            for (int half = 0; half < 2; half++) {
                int r = r0 + half * 8;
                if (r >= M) continue;
                float v0 = c[mt][nt][half * 2 + 0] + b0;
                float v1 = c[mt][nt][half * 2 + 1] + b1;
                if (CFG != 0) {
                    if (cc < DIN) {
                        // z-columns: only consumed as silu(z) for gene rows
                        if (r < 2048) {
                            Pf[(size_t)r * DIN + cc] = fast_silu(v0);
                            Pf[(size_t)r * DIN + cc + 1] = fast_silu(v1);
                        }
                    } else {
                        *(float2*)&Cf[(size_t)r * N + cc] = make_float2(v0, v1);
                    }
                } else {
                    store_split(Chi, Clo, (size_t)r * N + cc, v0);
                    store_split(Chi, Clo, (size_t)r * N + cc + 1, v1);
                }
            }
        }
    }
}

// ------------------------- 3. causal depthwise conv + silu -------------------
__global__ void conv_kernel(const float* __restrict__ cw_f, const float* __restrict__ cb_f,
                            const float* __restrict__ cw_b, const float* __restrict__ cb_b) {
    int bx = blockIdx.x;
    int dir = blockIdx.y;
    const float* cw = dir ? cw_b : cw_f;
    const float* cb = dir ? cb_b : cb_f;
    const float* Z = d_Z[dir];

    const float* rows[4];
    float* dst;
    if (bx < L_SEQ) {
        int t = bx;
        if ((dir == 0 && t < 4) || (dir == 1 && t < 1)) return;
        dst = d_xBCs[dir] + (size_t)t * CONVD;
#pragma unroll
        for (int k = 0; k < 4; k++) {
            int tau = dir ? (t + 3 - k) : (t - 3 + k);
            rows[k] = (tau <= L_SEQ - 1) ? (Z + (size_t)(tau - 1) * DPROJ + DIN) : nullptr;
        }
    } else {
        if (dir == 1) return;
        int idx = bx - L_SEQ;
        int b = idx >> 2;
        int t = idx & 3;
        dst = d_xBC0 + (size_t)(b * 4 + t) * CONVD;
#pragma unroll
        for (int k = 0; k < 4; k++) {
            int tau = t - 3 + k;
            rows[k] = (tau >= 0) ? (Z + (size_t)seq_row(b, tau) * DPROJ + DIN) : nullptr;
        }
    }
    for (int c = threadIdx.x; c < CONVD; c += blockDim.x) {
        float acc = cb[c];
#pragma unroll
        for (int k = 0; k < 4; k++)
            if (rows[k]) acc = fmaf(rows[k][c], cw[c * 4 + k], acc);
        dst[c] = fast_silu(acc);
    }
}

// ------------------------- 4. dt / dA per row --------------------------------
__global__ void dtda_kernel(const float* __restrict__ fdtb, const float* __restrict__ fAl,
                            const float* __restrict__ bdtb, const float* __restrict__ bAl) {
    int idx = blockIdx.x * blockDim.x + threadIdx.x;
    const int per = NROWS * NH;
    if (idx >= 2 * per) return;
    int dir = idx / per;
    int r = idx % per;
    int row = r >> 4;
    int h = r & 15;
    float raw = d_Z[dir][(size_t)row * DPROJ + (DIN + CONVD) + h] + (dir ? bdtb : fdtb)[h];
    float dtv = (raw > 20.f) ? raw : log1pf(expf(raw));
    float Al = (dir ? bAl : fAl)[h];
    d_dtr[dir][row * NH + h] = dtv;
    d_dAr[dir][row * NH + h] = expf(-expf(Al) * dtv);
}

// ------------------------- 4b. fwd decay cumprod (parallel) ------------------
__global__ void decay_kernel() {
    int tid = threadIdx.x;    // 512
    int h = tid >> 5;
    int lane = tid & 31;
    int s0 = lane * 64;
    int len = (s0 < TCOR) ? ((TCOR - s0 < 64) ? (TCOR - s0) : 64) : 0;
    float prod = 1.f;
    for (int i = 0; i < len; i++) prod *= d_dAr[0][(size_t)(3 + s0 + i) * NH + h];
    float inc = prod;
#pragma unroll
    for (int off = 1; off < 32; off <<= 1) {
        float v = __shfl_up_sync(0xffffffffu, inc, off);
        if (lane >= off) inc *= v;
    }
    float excl = __shfl_up_sync(0xffffffffu, inc, 1);
    if (lane == 0) excl = 1.f;
    float run = excl;
    for (int i = 0; i < len; i++) {
        run *= d_dAr[0][(size_t)(3 + s0 + i) * NH + h];
        d_decayf[h * TCOR + s0 + i] = run;
    }
}

// ------------------------- 4c. W4 --------------------------------------------
__global__ void w4_kernel() {
    int idx = threadIdx.x;   // 512
    if (idx >= BATCH * NH * 4) return;
    int b = idx >> 6, h = (idx >> 2) & 15, tau = idx & 3;
    int row_tau = (tau == 0) ? (2048 + b) : (tau - 1);
    float w = d_dtr[0][row_tau * NH + h];
    for (int s = tau + 1; s < 4; s++)
        w *= d_dAr[0][(s - 1) * NH + h];
    d_W4[idx] = w;
}

// ------------------------- 4d. dotCB -----------------------------------------
__global__ void dotcb_kernel() {
    int t = blockIdx.x + 4;       // 4..2048
    __shared__ float sC[128];
    int tid = threadIdx.x;        // 256 = 8 warps
    if (tid < 128) sC[tid] = d_xBCs[0][(size_t)t * CONVD + DIN + NS + tid];
    __syncthreads();
    int w = tid >> 5, l = tid & 31;
    for (int c = w; c < 32; c += 8) {
        const float* B0 = d_xBC0 + (size_t)c * CONVD + DIN;
        float acc = 0.f;
#pragma unroll
        for (int i = 0; i < 4; i++) acc = fmaf(B0[i * 32 + l], sC[i * 32 + l], acc);
#pragma unroll
        for (int off = 16; off; off >>= 1)
            acc += __shfl_xor_sync(0xffffffffu, acc, off);
        if (l == 0) d_dotCB[t * 32 + c] = acc;
    }
}

// ------------------------- 5. combined output vector -------------------------
__global__ void wcomb_kernel(const float* __restrict__ head_w,
                             const float* __restrict__ fow, const float* __restrict__ bow,
                             const float* __restrict__ fnw, const float* __restrict__ bnw) {
    int idx = blockIdx.x * blockDim.x + threadIdx.x;
    if (idx >= 2 * DIN) return;
    int dir = idx >> 10;
    int j = idx & 1023;
    const float* ow = dir ? bow : fow;
    float acc = 0.f;
    for (int i = 0; i < DMODEL; i++) acc = fmaf(ow[(size_t)i * DIN + j], head_w[i], acc);
    d_wcomb[dir][j] = acc * (dir ? bnw : fnw)[j];
}

// ------------------------- 6a. fwd per-batch prefix scan (t=0..3) ------------
__global__ __launch_bounds__(128) void prefix_kernel(const float* __restrict__ fD) {
    int blk = blockIdx.x;
    int b = blk >> 4;
    int h = blk & 15;
    int tid = threadIdx.x;
    int p = tid & 63;
    int nh = tid >> 6;
    float Dh = fD[h];

    __shared__ __align__(16) float sB[128], sC[128], sx[64];

    unsigned long long hs2[32];
#pragma unroll
    for (int i = 0; i < 32; i++) hs2[i] = 0ull;

    for (int t = 0; t < 4; t++) {
        const float* pp = xbc_fwd_ptr(b, t);
        sB[tid] = pp[DIN + tid];
        sC[tid] = pp[DIN + NS + tid];
        if (tid < 64) sx[tid] = pp[h * HD + tid];
        __syncthreads();
        int row = (t == 0) ? (2048 + b) : (t - 1);
        float dtv = d_dtr[0][row * NH + h];
        float dAv = d_dAr[0][row * NH + h];
        float xv = sx[p];
        unsigned long long coef2 = pack2(dtv * xv);
        unsigned long long dA2 = pack2(dAv);
        const ulonglong2* B4 = (const ulonglong2*)(sB + nh * 64);
        const ulonglong2* C4 = (const ulonglong2*)(sC + nh * 64);
        unsigned long long a0 = 0ull, a1 = 0ull;
#pragma unroll
        for (int i = 0; i < 16; i++) {
            ulonglong2 bv = B4[i], cv = C4[i];
            unsigned long long tm;
            MUL2(tm, coef2, bv.x);
            FMA2(hs2[2 * i + 0], dA2, hs2[2 * i + 0], tm);
            FMA2(a0, hs2[2 * i + 0], cv.x, a0);
            MUL2(tm, coef2, bv.y);
            FMA2(hs2[2 * i + 1], dA2, hs2[2 * i + 1], tm);
            FMA2(a1, hs2[2 * i + 1], cv.y, a1);
        }
        ADD2(a0, a0, a1);
        float part = sum2(a0);
        if (nh == 0) part = fmaf(Dh, xv, part);
        if (t >= 1)
            d_ypre[((size_t)(b * 3 + (t - 1)) * 16 + h) * 128 + tid] = part;
        __syncthreads();
    }
}

// ------------------------- 6b. shared scans — p-split, no atomics ------------
__global__ __launch_bounds__(128) void scan_shared(const float* __restrict__ fD,
                                                   const float* __restrict__ bD) {
    int blk = blockIdx.x;          // 0..255
    int dir = blk >> 7;
    int rest = blk & 127;
    int h = rest >> 3;
    int pq = rest & 7;
    int tid = threadIdx.x;
    int p8 = tid & 7;
    int nsix = tid >> 3;
    float Dh = (dir ? bD : fD)[h];
    const float* xbc = d_xBCs[dir];
    const float* dtr = d_dtr[dir];
    const float* dAr = d_dAr[dir];
    float* ysum = d_ysum[dir];

    int S = dir ? 2048 : TCOR;
    int nch = (S + TC - 1) / TC;

    __shared__ __align__(16) float sB[2][TC][128];
    __shared__ __align__(16) float sC[2][TC][128];
    __shared__ __align__(16) float sx[2][TC][8];
    __shared__ float sdt[2][TC], sdA[2][TC];
    __shared__ __align__(16) float sy[TC][128];

    unsigned long long hs2[4] = {0ull, 0ull, 0ull, 0ull};

    float4 rB[4], rC[4], rx;
    float rdt = 0.f, rdA = 0.f;

#define SCAN_LOAD(s0_)                                                          \
    {                                                                           \
        int lim = S - 1 - (s0_);                                                \
        _Pragma("unroll")                                                       \
        for (int k = 0; k < 4; k++) {                                           \
            int idx = tid + k * 128;                                            \
            int j = idx >> 5; if (j > lim) j = lim;                             \
            int tt = dir ? (2048 - ((s0_) + j)) : (4 + (s0_) + j);              \
            const float* rowp = xbc + (size_t)tt * CONVD + DIN;                 \
            rB[k] = ((const float4*)rowp)[idx & 31];                            \
            rC[k] = ((const float4*)(rowp + NS))[idx & 31];                     \
        }                                                                       \
        if (tid < 2 * TC) {                                                     \
            int j = tid >> 1; if (j > lim) j = lim;                             \
            int tt = dir ? (2048 - ((s0_) + j)) : (4 + (s0_) + j);              \
            rx = ((const float4*)(xbc + (size_t)tt * CONVD + h * HD + pq * 8))[tid & 1]; \
        }                                                                       \
        if (tid < TC) {                                                         \
            int j = (tid > lim) ? lim : tid;                                    \
            int tt = dir ? (2048 - ((s0_) + j)) : (4 + (s0_) + j);              \
            rdt = dtr[(tt - 1) * NH + h];                                       \
            rdA = dAr[(tt - 1) * NH + h];                                       \
        }                                                                       \
    }
#define SCAN_STORE(bb_)                                                         \
    {                                                                           \
        _Pragma("unroll")                                                       \
        for (int k = 0; k < 4; k++) {                                           \
            int idx = tid + k * 128;                                            \
            *(float4*)&sB[bb_][idx >> 5][(idx & 31) * 4] = rB[k];               \
            *(float4*)&sC[bb_][idx >> 5][(idx & 31) * 4] = rC[k];               \
        }                                                                       \
        if (tid < 2 * TC) *(float4*)&sx[bb_][tid >> 1][(tid & 1) * 4] = rx;     \
        if (tid < TC) { sdt[bb_][tid] = rdt; sdA[bb_][tid] = rdA; }             \
    }

    SCAN_LOAD(0);
    SCAN_STORE(0);
    __syncthreads();

    for (int c = 0; c < nch; c++) {
        int s0 = c * TC;
        int cnt = (S - s0 < TC) ? (S - s0) : TC;
        bool more = (c + 1) < nch;
        if (more) SCAN_LOAD(s0 + TC);
        int bb = c & 1;
        for (int j = 0; j < cnt; j++) {
            float xv = sx[bb][j][p8];
            unsigned long long coef2 = pack2(sdt[bb][j] * xv);
            unsigned long long dA2 = pack2(sdA[bb][j]);
            const ulonglong2* B4 = (const ulonglong2*)&sB[bb][j][nsix * 8];
            const ulonglong2* C4 = (const ulonglong2*)&sC[bb][j][nsix * 8];
            ulonglong2 bv0 = B4[0], cv0 = C4[0];
            ulonglong2 bv1 = B4[1], cv1 = C4[1];
            unsigned long long a0 = 0ull, a1 = 0ull, tm;
            MUL2(tm, coef2, bv0.x);
            FMA2(hs2[0], dA2, hs2[0], tm);
            FMA2(a0, hs2[0], cv0.x, a0);
            MUL2(tm, coef2, bv0.y);
            FMA2(hs2[1], dA2, hs2[1], tm);
            FMA2(a1, hs2[1], cv0.y, a1);
            MUL2(tm, coef2, bv1.x);
            FMA2(hs2[2], dA2, hs2[2], tm);
            FMA2(a0, hs2[2], cv1.x, a0);
            MUL2(tm, coef2, bv1.y);
            FMA2(hs2[3], dA2, hs2[3], tm);
            FMA2(a1, hs2[3], cv1.y, a1);
            ADD2(a0, a0, a1);
            sy[j][tid] = sum2(a0);
        }
        if (more) SCAN_STORE(bb ^ 1);
        __syncthreads();
        {
            int jo = tid >> 3;
            int po = tid & 7;
            if (jo < cnt) {
                const float* sp = &sy[jo][po];
                float s = 0.f;
#pragma unroll
                for (int k = 0; k < 16; k++) s += sp[k * 8];
                s = fmaf(Dh, sx[bb][jo][po], s);
                int tt = dir ? (2048 - (s0 + jo)) : (4 + s0 + jo);
                ysum[(size_t)tt * 1024 + h * 64 + pq * 8 + po] = s;
            }
        }
        __syncthreads();
    }
#undef SCAN_LOAD
#undef SCAN_STORE
}

// ------------------------- 7. gate + RMSnorm + fused head (per-t, all b) -----
__global__ __launch_bounds__(256) void final_kernel(const float* __restrict__ head_b,
                                                    float* __restrict__ out) {
    int t = blockIdx.x + 1;     // 1..2048
    int tid = threadIdx.x;      // 256
    __shared__ float cco[8][64];
    __shared__ float sh[8][18];

    if (t >= 4) {
        for (int i = tid; i < 512; i += 256) {
            int b = i >> 6;
            int r = i & 63;             // h*4+tau
            int hh = r >> 2, tau = r & 3;
            cco[b][r] = d_decayf[hh * TCOR + (t - 4)] *
                        d_W4[(b * 16 + hh) * 4 + tau] *
                        d_dotCB[t * 32 + b * 4 + tau];
        }
    }
    __syncthreads();

    int j0 = tid * 4;
    int h = tid >> 4;
    float4 ysf4 = *(const float4*)&d_ysum[0][(size_t)t * DIN + j0];
    float4 ysb4 = *(const float4*)&d_ysum[1][(size_t)t * DIN + j0];
    float4 pf4 = *(const float4*)&d_P[0][(size_t)(t - 1) * DIN + j0];
    float4 pb4 = *(const float4*)&d_P[1][(size_t)(t - 1) * DIN + j0];
    float4 w04 = *(const float4*)&d_wcomb[0][j0];
    float4 w14 = *(const float4*)&d_wcomb[1][j0];

    float ssqb = 0.f, sdotb = 0.f;
    {
        float g;
        g = ysb4.x * pb4.x; ssqb = fmaf(g, g, ssqb); sdotb = fmaf(g, w14.x, sdotb);
        g = ysb4.y * pb4.y; ssqb = fmaf(g, g, ssqb); sdotb = fmaf(g, w14.y, sdotb);
        g = ysb4.z * pb4.z; ssqb = fmaf(g, g, ssqb); sdotb = fmaf(g, w14.z, sdotb);
        g = ysb4.w * pb4.w; ssqb = fmaf(g, g, ssqb); sdotb = fmaf(g, w14.w, sdotb);
    }

    float ssqf[8], sdotf[8];
    if (t >= 4) {
#pragma unroll
        for (int b = 0; b < 8; b++) {
            const float* xbb = d_xBC0 + (size_t)b * 4 * CONVD + j0;
            float4 x0 = *(const float4*)&xbb[0];
            float4 x1 = *(const float4*)&xbb[CONVD];
            float4 x2 = *(const float4*)&xbb[2 * CONVD];
            float4 x3 = *(const float4*)&xbb[3 * CONVD];
            float cc0 = cco[b][h * 4 + 0], cc1 = cco[b][h * 4 + 1];
            float cc2 = cco[b][h * 4 + 2], cc3 = cco[b][h * 4 + 3];
            float sq = 0.f, sd = 0.f, yf, g;
            yf = ysf4.x + cc0 * x0.x + cc1 * x1.x + cc2 * x2.x + cc3 * x3.x;
            g = yf * pf4.x; sq = fmaf(g, g, sq); sd = fmaf(g, w04.x, sd);
            yf = ysf4.y + cc0 * x0.y + cc1 * x1.y + cc2 * x2.y + cc3 * x3.y;
            g = yf * pf4.y; sq = fmaf(g, g, sq); sd = fmaf(g, w04.y, sd);
            yf = ysf4.z + cc0 * x0.z + cc1 * x1.z + cc2 * x2.z + cc3 * x3.z;
            g = yf * pf4.z; sq = fmaf(g, g, sq); sd = fmaf(g, w04.z, sd);
            yf = ysf4.w + cc0 * x0.w + cc1 * x1.w + cc2 * x2.w + cc3 * x3.w;
            g = yf * pf4.w; sq = fmaf(g, g, sq); sd = fmaf(g, w04.w, sd);
            ssqf[b] = sq; sdotf[b] = sd;
        }
    } else {
        int p0 = j0 & 63;
#pragma unroll
        for (int b = 0; b < 8; b++) {
            const float* yp = d_ypre + ((size_t)(b * 3 + (t - 1)) * 16 + h) * 128;
            float sq = 0.f, sd = 0.f;
            float pf[4] = {pf4.x, pf4.y, pf4.z, pf4.w};
            float w0[4] = {w04.x, w04.y, w04.z, w04.w};
#pragma unroll
            for (int k = 0; k < 4; k++) {
                float yf = yp[p0 + k] + yp[64 + p0 + k];
                float g = yf * pf[k];
                sq = fmaf(g, g, sq); sd = fmaf(g, w0[k], sd);
            }
            ssqf[b] = sq; sdotf[b] = sd;
        }
    }

#pragma unroll
    for (int off = 16; off; off >>= 1) {
        ssqb += __shfl_xor_sync(0xffffffffu, ssqb, off);
        sdotb += __shfl_xor_sync(0xffffffffu, sdotb, off);
#pragma unroll
        for (int b = 0; b < 8; b++) {
            ssqf[b] += __shfl_xor_sync(0xffffffffu, ssqf[b], off);
            sdotf[b] += __shfl_xor_sync(0xffffffffu, sdotf[b], off);
        }
    }
    int w = tid >> 5, l = tid & 31;
    if (l == 0) {
        sh[w][0] = ssqb; sh[w][1] = sdotb;
#pragma unroll
        for (int b = 0; b < 8; b++) { sh[w][2 + b] = ssqf[b]; sh[w][10 + b] = sdotf[b]; }
    }
    __syncthreads();
    if (tid < 8) {
        float qb = 0.f, db = 0.f, a = 0.f, d = 0.f;
        for (int i = 0; i < 8; i++) {
            qb += sh[i][0]; db += sh[i][1];
            a += sh[i][2 + tid]; d += sh[i][10 + tid];
        }
        float resb = rsqrtf(qb * (1.f / 1024.f) + 1e-5f) * db;
        float resf = rsqrtf(a * (1.f / 1024.f) + 1e-5f) * d;
        out[tid * 2048 + (t - 1)] = resf + resb + head_b[0];
    }
}

// ------------------------- launch --------------------------------------------
extern "C" void kernel_launch(void* const* d_in, const int* in_sizes, int n_in,
                              void* d_out, int out_size) {
    const int* pidx            = (const int*)d_in[0];
    const int* chridx          = (const int*)d_in[1];
    const float* locus_fourier = (const float*)d_in[2];
    const float* pathway       = (const float*)d_in[3];
    const float* pert_emb      = (const float*)d_in[4];
    const float* gene_id       = (const float*)d_in[5];
    const float* chr_emb       = (const float*)d_in[6];
    const float* locus_w       = (const float*)d_in[7];
    const float* locus_b       = (const float*)d_in[8];
    const float* cond_w        = (const float*)d_in[9];
    const float* cond_b        = (const float*)d_in[10];
    const float* in_w          = (const float*)d_in[11];
    const float* in_b          = (const float*)d_in[12];
    const float* head_w        = (const float*)d_in[13];
    const float* head_b        = (const float*)d_in[14];
    const float* f_in_w        = (const float*)d_in[15];
    const float* f_conv_w      = (const float*)d_in[16];
    const float* f_conv_b      = (const float*)d_in[17];
    const float* f_dt_bias     = (const float*)d_in[18];
    const float* f_A_log       = (const float*)d_in[19];
    const float* f_D           = (const float*)d_in[20];
    const float* f_norm_w      = (const float*)d_in[21];
    const float* f_out_w       = (const float*)d_in[22];
    const float* b_in_w        = (const float*)d_in[23];
    const float* b_conv_w      = (const float*)d_in[24];
    const float* b_conv_b      = (const float*)d_in[25];
    const float* b_dt_bias     = (const float*)d_in[26];
    const float* b_A_log       = (const float*)d_in[27];
    const float* b_D           = (const float*)d_in[28];
    const float* b_norm_w      = (const float*)d_in[29];
    const float* b_out_w       = (const float*)d_in[30];
    float* out = (float*)d_out;

    feat_kernel<<<NROWS, 128>>>(pidx, chridx, locus_fourier, pathway, pert_emb,
                                gene_id, chr_emb, locus_w, locus_b, cond_w, cond_b);
    cvt_weights<<<(DPROJ * DMODEL + 255) / 256, 256>>>(f_in_w, b_in_w, in_w);

    // X = feat @ in_w^T + in_b (64x128 tiles, cp.async staging)
    hgemm<0><<<dim3(4, 33), 256>>>(in_b);
    // Z_dir = X @ W^T (128x128 tiles, both dirs; z-cols -> silu -> d_P fused)
    hgemm<1><<<dim3(19, 17, 2), 256>>>(nullptr);

    conv_kernel<<<dim3(L_SEQ + 32, 2), 256>>>(f_conv_w, f_conv_b, b_conv_w, b_conv_b);

    dtda_kernel<<<(2 * NROWS * NH + 255) / 256, 256>>>(f_dt_bias, f_A_log, b_dt_bias, b_A_log);
    decay_kernel<<<1, 512>>>();
    w4_kernel<<<1, 512>>>();
    dotcb_kernel<<<TCOR, 256>>>();

    wcomb_kernel<<<(2 * DIN + 255) / 256, 256>>>(head_w, f_out_w, b_out_w, f_norm_w, b_norm_w);

    prefix_kernel<<<128, 128>>>(f_D);

    scan_shared<<<256, 128>>>(f_D, b_D);

    final_kernel<<<2048, 256>>>(head_b, out);
}

// round 15
// speedup vs baseline: 4.4099x; 1.0368x over previous
#include <cuda_runtime.h>
#include <cuda_bf16.h>
#include <math.h>

#define L_SEQ 2049
#define BATCH 8
#define NH 16
#define HD 64
#define NS 128
#define DIN 1024
#define CONVD 1280
#define DPROJ 2320
#define NROWS 2056
#define GENEF 384
#define DMODEL 512
#define TCOR 2045   // corrected timesteps t=4..2048
#define TC 16       // scan chunk length
#define SST 24      // hgemm shared stride, bf16 elems (48B rows)

// ------------------------- scratch (static device globals) -------------------
__device__ float d_Z[2][NROWS * DPROJ];
__device__ float d_xBCs[2][(size_t)L_SEQ * CONVD];   // batch-shared conv out
__device__ float d_xBC0[BATCH * 4 * CONVD];          // fwd per-batch conv out, t=0..3
__device__ float d_dtr[2][NROWS * NH];
__device__ float d_dAr[2][NROWS * NH];
__device__ float d_ysum[2][(size_t)L_SEQ * NH * 64]; // scan y (each elem written once)
__device__ float d_ypre[BATCH * 3 * NH * 128];       // fwd per-batch y (t=1..3), halves
__device__ float d_decayf[NH * TCOR];                // cumprod dA fwd, t=4..2048
__device__ float d_dotCB[L_SEQ * 32];                // C_t . B_tau  [t][b][tau]
__device__ float d_W4[BATCH * NH * 4];               // dt_tau * prod dA  [b][h][tau]
__device__ float d_P[2][(size_t)2048 * DIN];         // silu(z) per gene row
__device__ float d_wcomb[2][DIN];
// split-bf16 operands for tensor-core GEMMs
__device__ __nv_bfloat16 d_Fhi[NROWS * GENEF];
__device__ __nv_bfloat16 d_Flo[NROWS * GENEF];
__device__ __nv_bfloat16 d_IWhi[DMODEL * GENEF];
__device__ __nv_bfloat16 d_IWlo[DMODEL * GENEF];
__device__ __nv_bfloat16 d_Xhi[NROWS * DMODEL];
__device__ __nv_bfloat16 d_Xlo[NROWS * DMODEL];
__device__ __nv_bfloat16 d_Whi[2][DPROJ * DMODEL];
__device__ __nv_bfloat16 d_Wlo[2][DPROJ * DMODEL];

__device__ __forceinline__ int seq_row(int b, int t) {
    return (t == 0) ? (2048 + b) : (t - 1);
}
__device__ __forceinline__ const float* xbc_fwd_ptr(int b, int t) {
    return (t >= 4) ? (d_xBCs[0] + (size_t)t * CONVD)
                    : (d_xBC0 + (size_t)(b * 4 + t) * CONVD);
}
// silu via hw tanh: silu(x) = 0.5x(1+tanh(x/2)) — 1 MUFU
__device__ __forceinline__ float fast_silu(float x) {
    float t;
    asm("tanh.approx.f32 %0, %1;" : "=f"(t) : "f"(x * 0.5f));
    return fmaf(0.5f * x, t, 0.5f * x);
}
__device__ __forceinline__ void store_split(__nv_bfloat16* hi, __nv_bfloat16* lo,
                                            size_t i, float v) {
    __nv_bfloat16 h = __float2bfloat16(v);
    hi[i] = h;
    lo[i] = __float2bfloat16(v - __bfloat162float(h));
}

// f32x2 packed math (sm_100+)
#define MUL2(d, a, b) asm("mul.rn.f32x2 %0,%1,%2;" : "=l"(d) : "l"(a), "l"(b))
#define FMA2(d, a, b, c) asm("fma.rn.f32x2 %0,%1,%2,%3;" : "=l"(d) : "l"(a), "l"(b), "l"(c))
#define ADD2(d, a, b) asm("add.rn.f32x2 %0,%1,%2;" : "=l"(d) : "l"(a), "l"(b))
__device__ __forceinline__ unsigned long long pack2(float x) {
    unsigned long long r;
    asm("mov.b64 %0,{%1,%1};" : "=l"(r) : "r"(__float_as_uint(x)));
    return r;
}
__device__ __forceinline__ float sum2(unsigned long long v) {
    unsigned int lo, hi;
    asm("mov.b64 {%0,%1},%2;" : "=r"(lo), "=r"(hi) : "l"(v));
    return __uint_as_float(lo) + __uint_as_float(hi);
}

// bf16 mma: D += A(m16k16) * B(n8k16)^T, f32 accum
#define MMA_BF16(cc, aa, bb) \
    asm volatile("mma.sync.aligned.m16n8k16.row.col.f32.bf16.bf16.f32 " \
        "{%0,%1,%2,%3}, {%4,%5,%6,%7}, {%8,%9}, {%0,%1,%2,%3};" \
        : "+f"((cc)[0]), "+f"((cc)[1]), "+f"((cc)[2]), "+f"((cc)[3]) \
        : "r"((aa)[0]), "r"((aa)[1]), "r"((aa)[2]), "r"((aa)[3]), \
          "r"((bb)[0]), "r"((bb)[1]))

#define LDSM_X4(r0, r1, r2, r3, addr) \
    asm volatile("ldmatrix.sync.aligned.m8n8.x4.shared.b16 {%0,%1,%2,%3}, [%4];" \
        : "=r"(r0), "=r"(r1), "=r"(r2), "=r"(r3) : "r"(addr))

__device__ __forceinline__ unsigned smem_u32(const void* p) {
    return (unsigned)__cvta_generic_to_shared(p);
}

#define CPA16(saddr, gptr) \
    asm volatile("cp.async.ca.shared.global [%0], [%1], 16;" :: "r"(saddr), "l"(gptr))
#define CP_COMMIT() asm volatile("cp.async.commit_group;")
#define CP_WAIT0() asm volatile("cp.async.wait_group 0;")

// ------------------------- 1. feature rows (split-bf16 output) ---------------
__global__ void feat_kernel(const int* __restrict__ pidx,
                            const int* __restrict__ chridx,
                            const float* __restrict__ locus_fourier,
                            const float* __restrict__ pathway,
                            const float* __restrict__ pert_emb,
                            const float* __restrict__ gene_id,
                            const float* __restrict__ chr_emb,
                            const float* __restrict__ locus_w,
                            const float* __restrict__ locus_b,
                            const float* __restrict__ cond_w,
                            const float* __restrict__ cond_b) {
    int g = blockIdx.x;
    int tid = threadIdx.x;  // 128
    if (g < 2048) {
        store_split(d_Fhi, d_Flo, (size_t)g * GENEF + tid, gene_id[g * 128 + tid]);
        store_split(d_Fhi, d_Flo, (size_t)g * GENEF + 128 + tid, pathway[g * 128 + tid]);
        if (tid < 64) {
            int ci = chridx[g];
            store_split(d_Fhi, d_Flo, (size_t)g * GENEF + 256 + tid, chr_emb[ci * 64 + tid]);
        } else {
            int j = tid - 64;
            float acc = locus_b[j];
            const float* lf = locus_fourier + g * 64;
            const float* lw = locus_w + j * 64;
            for (int k = 0; k < 64; k++) acc = fmaf(lf[k], lw[k], acc);
            float ge = 0.5f * acc * (1.f + erff(acc * 0.70710678118654752f));
            store_split(d_Fhi, d_Flo, (size_t)g * GENEF + 320 + j, ge);
        }
    } else {
        int b = g - 2048;
        const float* pe = pert_emb + (size_t)pidx[b] * 128;
        for (int j = tid; j < GENEF; j += 128) {
            float acc = cond_b[j];
            const float* cw = cond_w + (size_t)j * 128;
            for (int k = 0; k < 128; k++) acc = fmaf(pe[k], cw[k], acc);
            store_split(d_Fhi, d_Flo, (size_t)g * GENEF + j, acc);
        }
    }
}

// ------------------------- 2a. weight conversions (merged) -------------------
__global__ void cvt_weights(const float* __restrict__ fw, const float* __restrict__ bw,
                            const float* __restrict__ iw) {
    int i = blockIdx.x * 256 + threadIdx.x;
    if (i < DPROJ * DMODEL) {
        store_split(d_Whi[0], d_Wlo[0], i, fw[i]);
        store_split(d_Whi[1], d_Wlo[1], i, bw[i]);
    }
    if (i < DMODEL * GENEF)
        store_split(d_IWhi, d_IWlo, i, iw[i]);
}

// ------------------------- 2b. tensor-core GEMM (cp.async, 1 barrier/chunk) --
// CFG 0: X-GEMM — BM=64, tile 64x128, grid (4, 33).
// CFG 1: Z-GEMM — BM=128, tile 128x128, grid (19, 17, 2); dir = blockIdx.z.
//        Fused epilogue: cc<DIN -> d_P (silu, gene rows only), else d_Z.
template <int CFG>
__global__ __launch_bounds__(256) void hgemm(const float* __restrict__ bias) {
    constexpr int BM = (CFG == 0) ? 64 : 128;
    constexpr int MT = 2;
    constexpr int NT = (CFG == 0) ? 4 : 8;
    constexpr int NWC = (CFG == 0) ? 32 : 64;   // cols per n-warp

    const __nv_bfloat16 *Ah, *Al, *Bh, *Bl;
    float* Cf = nullptr;
    float* Pf = nullptr;
    __nv_bfloat16 *Chi = nullptr, *Clo = nullptr;
    int M, N, K;
    if (CFG == 0) {
        Ah = d_Fhi; Al = d_Flo; Bh = d_IWhi; Bl = d_IWlo;
        Chi = d_Xhi; Clo = d_Xlo;
        M = NROWS; N = DMODEL; K = GENEF;
    } else {
        int dir = blockIdx.z;
        Ah = d_Xhi; Al = d_Xlo; Bh = d_Whi[dir]; Bl = d_Wlo[dir];
        Cf = d_Z[dir];
        Pf = d_P[dir];
        M = NROWS; N = DPROJ; K = DMODEL;
    }

    __shared__ __align__(16) __nv_bfloat16 sA[2][2][128 * SST];
    __shared__ __align__(16) __nv_bfloat16 sB[2][2][128 * SST];

    int tid = threadIdx.x;
    int row0 = blockIdx.y * BM;
    int col0 = blockIdx.x * 128;
    int lrow = tid >> 1;
    int seg = tid & 1;
    int lrowA = lrow & (BM - 1);

    int arow = row0 + lrowA;
    int brow = col0 + lrow;
    // clamp OOB rows; garbage values are discarded at epilogue guards
    int arc = (arow < M) ? arow : (M - 1);
    int brc = (brow < N) ? brow : (N - 1);

    const __nv_bfloat16* pAh = Ah + (size_t)arc * K + seg * 8;
    const __nv_bfloat16* pAl = Al + (size_t)arc * K + seg * 8;
    const __nv_bfloat16* pBh = Bh + (size_t)brc * K + seg * 8;
    const __nv_bfloat16* pBl = Bl + (size_t)brc * K + seg * 8;

    unsigned dA0 = smem_u32(&sA[0][0][lrow * SST + seg * 8]);
    unsigned dA1 = smem_u32(&sA[0][1][lrow * SST + seg * 8]);
    unsigned dB0 = smem_u32(&sB[0][0][lrow * SST + seg * 8]);
    unsigned dB1 = smem_u32(&sB[0][1][lrow * SST + seg * 8]);
    const unsigned bufoff = (unsigned)(2 * 128 * SST * sizeof(__nv_bfloat16));

#define HG_STAGE(kc_, bb_)                                                     \
    {                                                                          \
        size_t o = (size_t)(kc_) * 16;                                         \
        unsigned bo = (bb_) ? bufoff : 0u;                                     \
        CPA16(dA0 + bo, pAh + o);                                              \
        CPA16(dA1 + bo, pAl + o);                                              \
        CPA16(dB0 + bo, pBh + o);                                              \
        CPA16(dB1 + bo, pBl + o);                                              \
    }

    HG_STAGE(0, 0);
    CP_COMMIT();

    int w = tid >> 5, l = tid & 31;
    int mw = (CFG == 0) ? (w >> 2) : (w >> 1);
    int nw = (CFG == 0) ? (w & 3) : (w & 1);
    int g = l >> 2, q = l & 3;

    int aoff = (mw * 32 + (l & 15)) * SST + (l >> 4) * 8;
    int boff = (nw * NWC + (l & 7) + (l >> 4) * 8) * SST + ((l >> 3) & 1) * 8;

    float c[MT][NT][4];
#pragma unroll
    for (int mt = 0; mt < MT; mt++)
#pragma unroll
        for (int nt = 0; nt < NT; nt++)
#pragma unroll
            for (int i = 0; i < 4; i++) c[mt][nt][i] = 0.f;

    const int NCH = K >> 4;
    for (int kc = 0; kc < NCH; kc++) {
        int buf = kc & 1;
        bool more = (kc + 1) < NCH;
        // wait for this chunk's copies; single barrier covers both the copy
        // visibility and the reuse hazard for the buffer we prefetch into.
        CP_WAIT0();
        __syncthreads();
        if (more) {
            HG_STAGE(kc + 1, buf ^ 1);
            CP_COMMIT();
        }

        unsigned a[MT][2][4], b[NT][2][2];
#pragma unroll
        for (int v = 0; v < 2; v++) {
#pragma unroll
            for (int mt = 0; mt < MT; mt++) {
                unsigned ad = smem_u32(&sA[buf][v][aoff + mt * 16 * SST]);
                LDSM_X4(a[mt][v][0], a[mt][v][1], a[mt][v][2], a[mt][v][3], ad);
            }
#pragma unroll
            for (int jp = 0; jp < NT / 2; jp++) {
                unsigned bd = smem_u32(&sB[buf][v][boff + jp * 16 * SST]);
                LDSM_X4(b[2 * jp][v][0], b[2 * jp][v][1],
                        b[2 * jp + 1][v][0], b[2 * jp + 1][v][1], bd);
            }
        }
#pragma unroll
        for (int mt = 0; mt < MT; mt++)
#pragma unroll
            for (int nt = 0; nt < NT; nt++) {
                MMA_BF16(c[mt][nt], a[mt][0], b[nt][0]);
                MMA_BF16(c[mt][nt], a[mt][0], b[nt][1]);
                MMA_BF16(c[mt][nt], a[mt][1], b[nt][0]);
            }
    }
#undef HG_STAGE

#pragma unroll
    for (int mt = 0; mt < MT; mt++) {
        int r0 = row0 + mw * 32 + mt * 16 + g;
#pragma unroll
        for (int nt = 0; nt < NT; nt++) {
            int cc = col0 + nw * NWC + nt * 8 + q * 2;
            if (cc >= N) continue;
            float b0 = bias ? bias[cc] : 0.f;
            float b1 = bias ? bias[cc + 1] : 0.f;
#pragma unroll
            for (int half = 0; half < 2; half++) {
                int r = r0 + half * 8;
                if (r >= M) continue;
                float v0 = c[mt][nt][half * 2 + 0] + b0;
                float v1 = c[mt][nt][half * 2 + 1] + b1;
                if (CFG != 0) {
                    if (cc < DIN) {
                        if (r < 2048) {
                            Pf[(size_t)r * DIN + cc] = fast_silu(v0);
                            Pf[(size_t)r * DIN + cc + 1] = fast_silu(v1);
                        }
                    } else {
                        *(float2*)&Cf[(size_t)r * N + cc] = make_float2(v0, v1);
                    }
                } else {
                    store_split(Chi, Clo, (size_t)r * N + cc, v0);
                    store_split(Chi, Clo, (size_t)r * N + cc + 1, v1);
                }
            }
        }
    }
}

// ------------------------- 3. causal depthwise conv + silu -------------------
__global__ void conv_kernel(const float* __restrict__ cw_f, const float* __restrict__ cb_f,
                            const float* __restrict__ cw_b, const float* __restrict__ cb_b) {
    int bx = blockIdx.x;
    int dir = blockIdx.y;
    const float* cw = dir ? cw_b : cw_f;
    const float* cb = dir ? cb_b : cb_f;
    const float* Z = d_Z[dir];

    const float* rows[4];
    float* dst;
    if (bx < L_SEQ) {
        int t = bx;
        if ((dir == 0 && t < 4) || (dir == 1 && t < 1)) return;
        dst = d_xBCs[dir] + (size_t)t * CONVD;
#pragma unroll
        for (int k = 0; k < 4; k++) {
            int tau = dir ? (t + 3 - k) : (t - 3 + k);
            rows[k] = (tau <= L_SEQ - 1) ? (Z + (size_t)(tau - 1) * DPROJ + DIN) : nullptr;
        }
    } else {
        if (dir == 1) return;
        int idx = bx - L_SEQ;
        int b = idx >> 2;
        int t = idx & 3;
        dst = d_xBC0 + (size_t)(b * 4 + t) * CONVD;
#pragma unroll
        for (int k = 0; k < 4; k++) {
            int tau = t - 3 + k;
            rows[k] = (tau >= 0) ? (Z + (size_t)seq_row(b, tau) * DPROJ + DIN) : nullptr;
        }
    }
    for (int c = threadIdx.x; c < CONVD; c += blockDim.x) {
        float acc = cb[c];
#pragma unroll
        for (int k = 0; k < 4; k++)
            if (rows[k]) acc = fmaf(rows[k][c], cw[c * 4 + k], acc);
        dst[c] = fast_silu(acc);
    }
}

// ------------------------- 4. dt / dA per row --------------------------------
__global__ void dtda_kernel(const float* __restrict__ fdtb, const float* __restrict__ fAl,
                            const float* __restrict__ bdtb, const float* __restrict__ bAl) {
    int idx = blockIdx.x * blockDim.x + threadIdx.x;
    const int per = NROWS * NH;
    if (idx >= 2 * per) return;
    int dir = idx / per;
    int r = idx % per;
    int row = r >> 4;
    int h = r & 15;
    float raw = d_Z[dir][(size_t)row * DPROJ + (DIN + CONVD) + h] + (dir ? bdtb : fdtb)[h];
    float dtv = (raw > 20.f) ? raw : log1pf(expf(raw));
    float Al = (dir ? bAl : fAl)[h];
    d_dtr[dir][row * NH + h] = dtv;
    d_dAr[dir][row * NH + h] = expf(-expf(Al) * dtv);
}

// ------------------------- 4b. fwd decay cumprod (parallel) ------------------
__global__ void decay_kernel() {
    int tid = threadIdx.x;    // 512
    int h = tid >> 5;
    int lane = tid & 31;
    int s0 = lane * 64;
    int len = (s0 < TCOR) ? ((TCOR - s0 < 64) ? (TCOR - s0) : 64) : 0;
    float prod = 1.f;
    for (int i = 0; i < len; i++) prod *= d_dAr[0][(size_t)(3 + s0 + i) * NH + h];
    float inc = prod;
#pragma unroll
    for (int off = 1; off < 32; off <<= 1) {
        float v = __shfl_up_sync(0xffffffffu, inc, off);
        if (lane >= off) inc *= v;
    }
    float excl = __shfl_up_sync(0xffffffffu, inc, 1);
    if (lane == 0) excl = 1.f;
    float run = excl;
    for (int i = 0; i < len; i++) {
        run *= d_dAr[0][(size_t)(3 + s0 + i) * NH + h];
        d_decayf[h * TCOR + s0 + i] = run;
    }
}

// ------------------------- 4c. W4 --------------------------------------------
__global__ void w4_kernel() {
    int idx = threadIdx.x;   // 512
    if (idx >= BATCH * NH * 4) return;
    int b = idx >> 6, h = (idx >> 2) & 15, tau = idx & 3;
    int row_tau = (tau == 0) ? (2048 + b) : (tau - 1);
    float w = d_dtr[0][row_tau * NH + h];
    for (int s = tau + 1; s < 4; s++)
        w *= d_dAr[0][(s - 1) * NH + h];
    d_W4[idx] = w;
}

// ------------------------- 4d. dotCB -----------------------------------------
__global__ void dotcb_kernel() {
    int t = blockIdx.x + 4;       // 4..2048
    __shared__ float sC[128];
    int tid = threadIdx.x;        // 256 = 8 warps
    if (tid < 128) sC[tid] = d_xBCs[0][(size_t)t * CONVD + DIN + NS + tid];
    __syncthreads();
    int w = tid >> 5, l = tid & 31;
    for (int c = w; c < 32; c += 8) {
        const float* B0 = d_xBC0 + (size_t)c * CONVD + DIN;
        float acc = 0.f;
#pragma unroll
        for (int i = 0; i < 4; i++) acc = fmaf(B0[i * 32 + l], sC[i * 32 + l], acc);
#pragma unroll
        for (int off = 16; off; off >>= 1)
            acc += __shfl_xor_sync(0xffffffffu, acc, off);
        if (l == 0) d_dotCB[t * 32 + c] = acc;
    }
}

// ------------------------- 5. combined output vector -------------------------
__global__ void wcomb_kernel(const float* __restrict__ head_w,
                             const float* __restrict__ fow, const float* __restrict__ bow,
                             const float* __restrict__ fnw, const float* __restrict__ bnw) {
    int idx = blockIdx.x * blockDim.x + threadIdx.x;
    if (idx >= 2 * DIN) return;
    int dir = idx >> 10;
    int j = idx & 1023;
    const float* ow = dir ? bow : fow;
    float acc = 0.f;
    for (int i = 0; i < DMODEL; i++) acc = fmaf(ow[(size_t)i * DIN + j], head_w[i], acc);
    d_wcomb[dir][j] = acc * (dir ? bnw : fnw)[j];
}

// ------------------------- 6a. fwd per-batch prefix scan (t=0..3) ------------
__global__ __launch_bounds__(128) void prefix_kernel(const float* __restrict__ fD) {
    int blk = blockIdx.x;
    int b = blk >> 4;
    int h = blk & 15;
    int tid = threadIdx.x;
    int p = tid & 63;
    int nh = tid >> 6;
    float Dh = fD[h];

    __shared__ __align__(16) float sB[128], sC[128], sx[64];

    unsigned long long hs2[32];
#pragma unroll
    for (int i = 0; i < 32; i++) hs2[i] = 0ull;

    for (int t = 0; t < 4; t++) {
        const float* pp = xbc_fwd_ptr(b, t);
        sB[tid] = pp[DIN + tid];
        sC[tid] = pp[DIN + NS + tid];
        if (tid < 64) sx[tid] = pp[h * HD + tid];
        __syncthreads();
        int row = (t == 0) ? (2048 + b) : (t - 1);
        float dtv = d_dtr[0][row * NH + h];
        float dAv = d_dAr[0][row * NH + h];
        float xv = sx[p];
        unsigned long long coef2 = pack2(dtv * xv);
        unsigned long long dA2 = pack2(dAv);
        const ulonglong2* B4 = (const ulonglong2*)(sB + nh * 64);
        const ulonglong2* C4 = (const ulonglong2*)(sC + nh * 64);
        unsigned long long a0 = 0ull, a1 = 0ull;
#pragma unroll
        for (int i = 0; i < 16; i++) {
            ulonglong2 bv = B4[i], cv = C4[i];
            unsigned long long tm;
            MUL2(tm, coef2, bv.x);
            FMA2(hs2[2 * i + 0], dA2, hs2[2 * i + 0], tm);
            FMA2(a0, hs2[2 * i + 0], cv.x, a0);
            MUL2(tm, coef2, bv.y);
            FMA2(hs2[2 * i + 1], dA2, hs2[2 * i + 1], tm);
            FMA2(a1, hs2[2 * i + 1], cv.y, a1);
        }
        ADD2(a0, a0, a1);
        float part = sum2(a0);
        if (nh == 0) part = fmaf(Dh, xv, part);
        if (t >= 1)
            d_ypre[((size_t)(b * 3 + (t - 1)) * 16 + h) * 128 + tid] = part;
        __syncthreads();
    }
}

// ------------------------- 6b. shared scans — p-split, no atomics ------------
__global__ __launch_bounds__(128) void scan_shared(const float* __restrict__ fD,
                                                   const float* __restrict__ bD) {
    int blk = blockIdx.x;          // 0..255
    int dir = blk >> 7;
    int rest = blk & 127;
    int h = rest >> 3;
    int pq = rest & 7;
    int tid = threadIdx.x;
    int p8 = tid & 7;
    int nsix = tid >> 3;
    float Dh = (dir ? bD : fD)[h];
    const float* xbc = d_xBCs[dir];
    const float* dtr = d_dtr[dir];
    const float* dAr = d_dAr[dir];
    float* ysum = d_ysum[dir];

    int S = dir ? 2048 : TCOR;
    int nch = (S + TC - 1) / TC;

    __shared__ __align__(16) float sB[2][TC][128];
    __shared__ __align__(16) float sC[2][TC][128];
    __shared__ __align__(16) float sx[2][TC][8];
    __shared__ float sdt[2][TC], sdA[2][TC];
    __shared__ __align__(16) float sy[TC][128];

    unsigned long long hs2[4] = {0ull, 0ull, 0ull, 0ull};

    float4 rB[4], rC[4], rx;
    float rdt = 0.f, rdA = 0.f;

#define SCAN_LOAD(s0_)                                                          \
    {                                                                           \
        int lim = S - 1 - (s0_);                                                \
        _Pragma("unroll")                                                       \
        for (int k = 0; k < 4; k++) {                                           \
            int idx = tid + k * 128;                                            \
            int j = idx >> 5; if (j > lim) j = lim;                             \
            int tt = dir ? (2048 - ((s0_) + j)) : (4 + (s0_) + j);              \
            const float* rowp = xbc + (size_t)tt * CONVD + DIN;                 \
            rB[k] = ((const float4*)rowp)[idx & 31];                            \
            rC[k] = ((const float4*)(rowp + NS))[idx & 31];                     \
        }                                                                       \
        if (tid < 2 * TC) {                                                     \
            int j = tid >> 1; if (j > lim) j = lim;                             \
            int tt = dir ? (2048 - ((s0_) + j)) : (4 + (s0_) + j);              \
            rx = ((const float4*)(xbc + (size_t)tt * CONVD + h * HD + pq * 8))[tid & 1]; \
        }                                                                       \
        if (tid < TC) {                                                         \
            int j = (tid > lim) ? lim : tid;                                    \
            int tt = dir ? (2048 - ((s0_) + j)) : (4 + (s0_) + j);              \
            rdt = dtr[(tt - 1) * NH + h];                                       \
            rdA = dAr[(tt - 1) * NH + h];                                       \
        }                                                                       \
    }
#define SCAN_STORE(bb_)                                                         \
    {                                                                           \
        _Pragma("unroll")                                                       \
        for (int k = 0; k < 4; k++) {                                           \
            int idx = tid + k * 128;                                            \
            *(float4*)&sB[bb_][idx >> 5][(idx & 31) * 4] = rB[k];               \
            *(float4*)&sC[bb_][idx >> 5][(idx & 31) * 4] = rC[k];               \
        }                                                                       \
        if (tid < 2 * TC) *(float4*)&sx[bb_][tid >> 1][(tid & 1) * 4] = rx;     \
        if (tid < TC) { sdt[bb_][tid] = rdt; sdA[bb_][tid] = rdA; }             \
    }

    SCAN_LOAD(0);
    SCAN_STORE(0);
    __syncthreads();

    for (int c = 0; c < nch; c++) {
        int s0 = c * TC;
        int cnt = (S - s0 < TC) ? (S - s0) : TC;
        bool more = (c + 1) < nch;
        if (more) SCAN_LOAD(s0 + TC);
        int bb = c & 1;
        for (int j = 0; j < cnt; j++) {
            float xv = sx[bb][j][p8];
            unsigned long long coef2 = pack2(sdt[bb][j] * xv);
            unsigned long long dA2 = pack2(sdA[bb][j]);
            const ulonglong2* B4 = (const ulonglong2*)&sB[bb][j][nsix * 8];
            const ulonglong2* C4 = (const ulonglong2*)&sC[bb][j][nsix * 8];
            ulonglong2 bv0 = B4[0], cv0 = C4[0];
            ulonglong2 bv1 = B4[1], cv1 = C4[1];
            unsigned long long a0 = 0ull, a1 = 0ull, tm;
            MUL2(tm, coef2, bv0.x);
            FMA2(hs2[0], dA2, hs2[0], tm);
            FMA2(a0, hs2[0], cv0.x, a0);
            MUL2(tm, coef2, bv0.y);
            FMA2(hs2[1], dA2, hs2[1], tm);
            FMA2(a1, hs2[1], cv0.y, a1);
            MUL2(tm, coef2, bv1.x);
            FMA2(hs2[2], dA2, hs2[2], tm);
            FMA2(a0, hs2[2], cv1.x, a0);
            MUL2(tm, coef2, bv1.y);
            FMA2(hs2[3], dA2, hs2[3], tm);
            FMA2(a1, hs2[3], cv1.y, a1);
            ADD2(a0, a0, a1);
            sy[j][tid] = sum2(a0);
        }
        if (more) SCAN_STORE(bb ^ 1);
        __syncthreads();
        {
            int jo = tid >> 3;
            int po = tid & 7;
            if (jo < cnt) {
                const float* sp = &sy[jo][po];
                float s = 0.f;
#pragma unroll
                for (int k = 0; k < 16; k++) s += sp[k * 8];
                s = fmaf(Dh, sx[bb][jo][po], s);
                int tt = dir ? (2048 - (s0 + jo)) : (4 + s0 + jo);
                ysum[(size_t)tt * 1024 + h * 64 + pq * 8 + po] = s;
            }
        }
        __syncthreads();
    }
#undef SCAN_LOAD
#undef SCAN_STORE
}

// ------------------------- 7. gate + RMSnorm + fused head (per-t, all b) -----
__global__ __launch_bounds__(256) void final_kernel(const float* __restrict__ head_b,
                                                    float* __restrict__ out) {
    int t = blockIdx.x + 1;     // 1..2048
    int tid = threadIdx.x;      // 256
    __shared__ float cco[8][64];
    __shared__ float sh[8][18];

    if (t >= 4) {
        for (int i = tid; i < 512; i += 256) {
            int b = i >> 6;
            int r = i & 63;             // h*4+tau
            int hh = r >> 2, tau = r & 3;
            cco[b][r] = d_decayf[hh * TCOR + (t - 4)] *
                        d_W4[(b * 16 + hh) * 4 + tau] *
                        d_dotCB[t * 32 + b * 4 + tau];
        }
    }
    __syncthreads();

    int j0 = tid * 4;
    int h = tid >> 4;
    float4 ysf4 = *(const float4*)&d_ysum[0][(size_t)t * DIN + j0];
    float4 ysb4 = *(const float4*)&d_ysum[1][(size_t)t * DIN + j0];
    float4 pf4 = *(const float4*)&d_P[0][(size_t)(t - 1) * DIN + j0];
    float4 pb4 = *(const float4*)&d_P[1][(size_t)(t - 1) * DIN + j0];
    float4 w04 = *(const float4*)&d_wcomb[0][j0];
    float4 w14 = *(const float4*)&d_wcomb[1][j0];

    float ssqb = 0.f, sdotb = 0.f;
    {
        float g;
        g = ysb4.x * pb4.x; ssqb = fmaf(g, g, ssqb); sdotb = fmaf(g, w14.x, sdotb);
        g = ysb4.y * pb4.y; ssqb = fmaf(g, g, ssqb); sdotb = fmaf(g, w14.y, sdotb);
        g = ysb4.z * pb4.z; ssqb = fmaf(g, g, ssqb); sdotb = fmaf(g, w14.z, sdotb);
        g = ysb4.w * pb4.w; ssqb = fmaf(g, g, ssqb); sdotb = fmaf(g, w14.w, sdotb);
    }

    float ssqf[8], sdotf[8];
    if (t >= 4) {
#pragma unroll
        for (int b = 0; b < 8; b++) {
            const float* xbb = d_xBC0 + (size_t)b * 4 * CONVD + j0;
            float4 x0 = *(const float4*)&xbb[0];
            float4 x1 = *(const float4*)&xbb[CONVD];
            float4 x2 = *(const float4*)&xbb[2 * CONVD];
            float4 x3 = *(const float4*)&xbb[3 * CONVD];
            float cc0 = cco[b][h * 4 + 0], cc1 = cco[b][h * 4 + 1];
            float cc2 = cco[b][h * 4 + 2], cc3 = cco[b][h * 4 + 3];
            float sq = 0.f, sd = 0.f, yf, g;
            yf = ysf4.x + cc0 * x0.x + cc1 * x1.x + cc2 * x2.x + cc3 * x3.x;
            g = yf * pf4.x; sq = fmaf(g, g, sq); sd = fmaf(g, w04.x, sd);
            yf = ysf4.y + cc0 * x0.y + cc1 * x1.y + cc2 * x2.y + cc3 * x3.y;
            g = yf * pf4.y; sq = fmaf(g, g, sq); sd = fmaf(g, w04.y, sd);
            yf = ysf4.z + cc0 * x0.z + cc1 * x1.z + cc2 * x2.z + cc3 * x3.z;
            g = yf * pf4.z; sq = fmaf(g, g, sq); sd = fmaf(g, w04.z, sd);
            yf = ysf4.w + cc0 * x0.w + cc1 * x1.w + cc2 * x2.w + cc3 * x3.w;
            g = yf * pf4.w; sq = fmaf(g, g, sq); sd = fmaf(g, w04.w, sd);
            ssqf[b] = sq; sdotf[b] = sd;
        }
    } else {
        int p0 = j0 & 63;
#pragma unroll
        for (int b = 0; b < 8; b++) {
            const float* yp = d_ypre + ((size_t)(b * 3 + (t - 1)) * 16 + h) * 128;
            float sq = 0.f, sd = 0.f;
            float pf[4] = {pf4.x, pf4.y, pf4.z, pf4.w};
            float w0[4] = {w04.x, w04.y, w04.z, w04.w};
#pragma unroll
            for (int k = 0; k < 4; k++) {
                float yf = yp[p0 + k] + yp[64 + p0 + k];
                float g = yf * pf[k];
                sq = fmaf(g, g, sq); sd = fmaf(g, w0[k], sd);
            }
            ssqf[b] = sq; sdotf[b] = sd;
        }
    }

#pragma unroll
    for (int off = 16; off; off >>= 1) {
        ssqb += __shfl_xor_sync(0xffffffffu, ssqb, off);
        sdotb += __shfl_xor_sync(0xffffffffu, sdotb, off);
#pragma unroll
        for (int b = 0; b < 8; b++) {
            ssqf[b] += __shfl_xor_sync(0xffffffffu, ssqf[b], off);
            sdotf[b] += __shfl_xor_sync(0xffffffffu, sdotf[b], off);
        }
    }
    int w = tid >> 5, l = tid & 31;
    if (l == 0) {
        sh[w][0] = ssqb; sh[w][1] = sdotb;
#pragma unroll
        for (int b = 0; b < 8; b++) { sh[w][2 + b] = ssqf[b]; sh[w][10 + b] = sdotf[b]; }
    }
    __syncthreads();
    if (tid < 8) {
        float qb = 0.f, db = 0.f, a = 0.f, d = 0.f;
        for (int i = 0; i < 8; i++) {
            qb += sh[i][0]; db += sh[i][1];
            a += sh[i][2 + tid]; d += sh[i][10 + tid];
        }
        float resb = rsqrtf(qb * (1.f / 1024.f) + 1e-5f) * db;
        float resf = rsqrtf(a * (1.f / 1024.f) + 1e-5f) * d;
        out[tid * 2048 + (t - 1)] = resf + resb + head_b[0];
    }
}

// ------------------------- launch --------------------------------------------
extern "C" void kernel_launch(void* const* d_in, const int* in_sizes, int n_in,
                              void* d_out, int out_size) {
    const int* pidx            = (const int*)d_in[0];
    const int* chridx          = (const int*)d_in[1];
    const float* locus_fourier = (const float*)d_in[2];
    const float* pathway       = (const float*)d_in[3];
    const float* pert_emb      = (const float*)d_in[4];
    const float* gene_id       = (const float*)d_in[5];
    const float* chr_emb       = (const float*)d_in[6];
    const float* locus_w       = (const float*)d_in[7];
    const float* locus_b       = (const float*)d_in[8];
    const float* cond_w        = (const float*)d_in[9];
    const float* cond_b        = (const float*)d_in[10];
    const float* in_w          = (const float*)d_in[11];
    const float* in_b          = (const float*)d_in[12];
    const float* head_w        = (const float*)d_in[13];
    const float* head_b        = (const float*)d_in[14];
    const float* f_in_w        = (const float*)d_in[15];
    const float* f_conv_w      = (const float*)d_in[16];
    const float* f_conv_b      = (const float*)d_in[17];
    const float* f_dt_bias     = (const float*)d_in[18];
    const float* f_A_log       = (const float*)d_in[19];
    const float* f_D           = (const float*)d_in[20];
    const float* f_norm_w      = (const float*)d_in[21];
    const float* f_out_w       = (const float*)d_in[22];
    const float* b_in_w        = (const float*)d_in[23];
    const float* b_conv_w      = (const float*)d_in[24];
    const float* b_conv_b      = (const float*)d_in[25];
    const float* b_dt_bias     = (const float*)d_in[26];
    const float* b_A_log       = (const float*)d_in[27];
    const float* b_D           = (const float*)d_in[28];
    const float* b_norm_w      = (const float*)d_in[29];
    const float* b_out_w       = (const float*)d_in[30];
    float* out = (float*)d_out;

    feat_kernel<<<NROWS, 128>>>(pidx, chridx, locus_fourier, pathway, pert_emb,
                                gene_id, chr_emb, locus_w, locus_b, cond_w, cond_b);
    cvt_weights<<<(DPROJ * DMODEL + 255) / 256, 256>>>(f_in_w, b_in_w, in_w);

    // X = feat @ in_w^T + in_b (64x128 tiles, cp.async staging)
    hgemm<0><<<dim3(4, 33), 256>>>(in_b);
    // Z_dir = X @ W^T (128x128 tiles, both dirs; z-cols -> silu -> d_P fused)
    hgemm<1><<<dim3(19, 17, 2), 256>>>(nullptr);

    conv_kernel<<<dim3(L_SEQ + 32, 2), 256>>>(f_conv_w, f_conv_b, b_conv_w, b_conv_b);

    dtda_kernel<<<(2 * NROWS * NH + 255) / 256, 256>>>(f_dt_bias, f_A_log, b_dt_bias, b_A_log);
    decay_kernel<<<1, 512>>>();
    w4_kernel<<<1, 512>>>();
    dotcb_kernel<<<TCOR, 256>>>();

    wcomb_kernel<<<(2 * DIN + 255) / 256, 256>>>(head_w, f_out_w, b_out_w, f_norm_w, b_norm_w);

    prefix_kernel<<<128, 128>>>(f_D);

    scan_shared<<<256, 128>>>(f_D, b_D);

    final_kernel<<<2048, 256>>>(head_b, out);
}